// round 6
// baseline (speedup 1.0000x reference)
#include <cuda_runtime.h>
#include <cuda_bf16.h>
#include <math.h>
#include <stdint.h>

#define T_LEN   2048
#define B_SZ    4
#define DMODEL  1024
#define DINNER  2048
#define DSTATE  16
#define DTRANK  64
#define NXP     96
#define M_ROWS  (B_SZ*T_LEN)   // 8192
#define DPROJ   (2*DINNER)     // 4096

// ---------------- scratch (device globals; EXACTLY the round-1 set, 323MB) ----------
__device__ __align__(16) float g_P[(size_t)M_ROWS * DPROJ];     // in_proj output (u | res)
__device__ __align__(16) float g_uc[(size_t)M_ROWS * DINNER];   // conv+silu output
__device__ __align__(16) float g_xdbl[(size_t)M_ROWS * NXP];    // x_proj output (dt|B|C)
__device__ __align__(16) float g_delta[(size_t)M_ROWS * DINNER];// softplus(dt_proj)
__device__ __align__(16) float g_y[(size_t)M_ROWS * DINNER];    // gated ssm output

// ---- bf16 hi/lo operands ALIASED into scratch (lifetimes verified disjoint) ----
// A1 (split of x):    lives in g_delta until dtproj writes it   (33.6MB <= 64MB)
// W1 (split W_in^T):  lives in g_uc    until conv writes it     (16.8MB <= 64MB)
// A2 (split of y):    g_delta (hi) + g_uc (lo), after scan      (33.6MB each)
// W2 (split W_out^T): lives in g_P after scan consumed res      ( 8.4MB <= 128MB)
__device__ __forceinline__ __nv_bfloat16* A1H() { return (__nv_bfloat16*)g_delta; }
__device__ __forceinline__ __nv_bfloat16* A1L() { return (__nv_bfloat16*)g_delta + (size_t)M_ROWS * DMODEL; }
__device__ __forceinline__ __nv_bfloat16* W1H() { return (__nv_bfloat16*)g_uc; }
__device__ __forceinline__ __nv_bfloat16* W1L() { return (__nv_bfloat16*)g_uc + (size_t)DPROJ * DMODEL; }
__device__ __forceinline__ __nv_bfloat16* A2H() { return (__nv_bfloat16*)g_delta; }
__device__ __forceinline__ __nv_bfloat16* A2L() { return (__nv_bfloat16*)g_uc; }
__device__ __forceinline__ __nv_bfloat16* W2H() { return (__nv_bfloat16*)g_P; }
__device__ __forceinline__ __nv_bfloat16* W2L() { return (__nv_bfloat16*)g_P + (size_t)DMODEL * DINNER; }

// ---------------- helpers ----------------
__device__ __forceinline__ void mma16816(float* c, const uint32_t* a, const uint32_t* b) {
    asm volatile("mma.sync.aligned.m16n8k16.row.col.f32.bf16.bf16.f32 "
        "{%0,%1,%2,%3}, {%4,%5,%6,%7}, {%8,%9}, {%0,%1,%2,%3};"
        : "+f"(c[0]), "+f"(c[1]), "+f"(c[2]), "+f"(c[3])
        : "r"(a[0]), "r"(a[1]), "r"(a[2]), "r"(a[3]), "r"(b[0]), "r"(b[1]));
}

__device__ __forceinline__ size_t map_tbc(int m, int col) {
    return (size_t)(m & (T_LEN - 1)) * (B_SZ * DMODEL) + (size_t)(m >> 11) * DMODEL + col;
}

// =================================================================================
// ROUND-1 PROVEN fp32 GEMM (verbatim): C[M,N] = A[M,K] @ B[K,N]
// MODE 0: A = x with (t,b,c) row mapping, C = g_P
// MODE 1: A = g_y, C = param written with (t,b,c) mapping
// =================================================================================
template<int MODE>
__global__ __launch_bounds__(256, 2)
void gemm_f32(const float* __restrict__ Aparam, const float* __restrict__ Bw,
              float* __restrict__ Cparam, int M, int N, int K)
{
    __shared__ float As[2][16][128];
    __shared__ float Bs[2][16][128];

    const float* A = (MODE == 1) ? g_y : Aparam;
    float*       C = (MODE == 1) ? Cparam : g_P;

    const int tid = threadIdx.x;
    const int bm = blockIdx.y * 128;
    const int bn = blockIdx.x * 128;

    const int ar = tid >> 2;
    const int ac = (tid & 3) << 2;
    const int br = tid >> 5;
    const int bc = (tid & 31) << 2;
    const int tx = tid & 15;
    const int ty = tid >> 4;

    float acc[8][8];
    #pragma unroll
    for (int i = 0; i < 8; i++)
        #pragma unroll
        for (int j = 0; j < 8; j++) acc[i][j] = 0.f;

    float4 pa0, pa1, pb0, pb1;

    {
        size_t o0 = (MODE == 0) ? map_tbc(bm + ar, ac)      : (size_t)(bm + ar) * K + ac;
        size_t o1 = (MODE == 0) ? map_tbc(bm + ar + 64, ac) : (size_t)(bm + ar + 64) * K + ac;
        pa0 = *(const float4*)(A + o0);
        pa1 = *(const float4*)(A + o1);
        pb0 = *(const float4*)(Bw + (size_t)br * N + bn + bc);
        pb1 = *(const float4*)(Bw + (size_t)(br + 8) * N + bn + bc);
    }
    As[0][ac + 0][ar] = pa0.x; As[0][ac + 1][ar] = pa0.y;
    As[0][ac + 2][ar] = pa0.z; As[0][ac + 3][ar] = pa0.w;
    As[0][ac + 0][ar + 64] = pa1.x; As[0][ac + 1][ar + 64] = pa1.y;
    As[0][ac + 2][ar + 64] = pa1.z; As[0][ac + 3][ar + 64] = pa1.w;
    *(float4*)&Bs[0][br][bc]     = pb0;
    *(float4*)&Bs[0][br + 8][bc] = pb1;
    __syncthreads();

    const int KT = K >> 4;
    for (int kt = 0; kt < KT; kt++) {
        const int s = kt & 1;
        if (kt + 1 < KT) {
            const int k0 = (kt + 1) << 4;
            size_t o0 = (MODE == 0) ? map_tbc(bm + ar, k0 + ac)      : (size_t)(bm + ar) * K + k0 + ac;
            size_t o1 = (MODE == 0) ? map_tbc(bm + ar + 64, k0 + ac) : (size_t)(bm + ar + 64) * K + k0 + ac;
            pa0 = *(const float4*)(A + o0);
            pa1 = *(const float4*)(A + o1);
            pb0 = *(const float4*)(Bw + (size_t)(k0 + br) * N + bn + bc);
            pb1 = *(const float4*)(Bw + (size_t)(k0 + br + 8) * N + bn + bc);
        }
        #pragma unroll
        for (int k = 0; k < 16; k++) {
            float a[8], bf[8];
            *(float4*)&a[0]  = *(const float4*)&As[s][k][ty * 8];
            *(float4*)&a[4]  = *(const float4*)&As[s][k][ty * 8 + 4];
            *(float4*)&bf[0] = *(const float4*)&Bs[s][k][tx * 8];
            *(float4*)&bf[4] = *(const float4*)&Bs[s][k][tx * 8 + 4];
            #pragma unroll
            for (int i = 0; i < 8; i++)
                #pragma unroll
                for (int j = 0; j < 8; j++)
                    acc[i][j] = fmaf(a[i], bf[j], acc[i][j]);
        }
        if (kt + 1 < KT) {
            const int ss = s ^ 1;
            As[ss][ac + 0][ar] = pa0.x; As[ss][ac + 1][ar] = pa0.y;
            As[ss][ac + 2][ar] = pa0.z; As[ss][ac + 3][ar] = pa0.w;
            As[ss][ac + 0][ar + 64] = pa1.x; As[ss][ac + 1][ar + 64] = pa1.y;
            As[ss][ac + 2][ar + 64] = pa1.z; As[ss][ac + 3][ar + 64] = pa1.w;
            *(float4*)&Bs[ss][br][bc]     = pb0;
            *(float4*)&Bs[ss][br + 8][bc] = pb1;
        }
        __syncthreads();
    }

    #pragma unroll
    for (int i = 0; i < 8; i++) {
        const int row = bm + ty * 8 + i;
        const int col = bn + tx * 8;
        size_t off = (MODE == 1) ? map_tbc(row, col) : (size_t)row * N + col;
        *(float4*)(C + off)     = make_float4(acc[i][0], acc[i][1], acc[i][2], acc[i][3]);
        *(float4*)(C + off + 4) = make_float4(acc[i][4], acc[i][5], acc[i][6], acc[i][7]);
    }
}

// =================================================================================
// Split kernels: fp32 -> bf16 hi/lo (targets are the aliased scratch regions)
// =================================================================================
__device__ __forceinline__ void split_store4(float4 v, __nv_bfloat16* hp, __nv_bfloat16* lp) {
    __nv_bfloat16 h0 = __float2bfloat16_rn(v.x), h1 = __float2bfloat16_rn(v.y);
    __nv_bfloat16 h2 = __float2bfloat16_rn(v.z), h3 = __float2bfloat16_rn(v.w);
    __nv_bfloat16 l0 = __float2bfloat16_rn(v.x - __bfloat162float(h0));
    __nv_bfloat16 l1 = __float2bfloat16_rn(v.y - __bfloat162float(h1));
    __nv_bfloat16 l2 = __float2bfloat16_rn(v.z - __bfloat162float(h2));
    __nv_bfloat16 l3 = __float2bfloat16_rn(v.w - __bfloat162float(h3));
    *(ushort4*)hp = make_ushort4(__bfloat16_as_ushort(h0), __bfloat16_as_ushort(h1),
                                 __bfloat16_as_ushort(h2), __bfloat16_as_ushort(h3));
    *(ushort4*)lp = make_ushort4(__bfloat16_as_ushort(l0), __bfloat16_as_ushort(l1),
                                 __bfloat16_as_ushort(l2), __bfloat16_as_ushort(l3));
}

__global__ __launch_bounds__(256)
void split_x_kernel(const float* __restrict__ x)
{
    const int q = blockIdx.x * 256 + threadIdx.x;
    const int c = (q & 255) * 4;
    const int m = q >> 8;
    const int t = m & (T_LEN - 1), b = m >> 11;
    float4 v = *(const float4*)(x + (size_t)t * (B_SZ * DMODEL) + b * DMODEL + c);
    const size_t o = (size_t)m * DMODEL + c;
    split_store4(v, A1H() + o, A1L() + o);
}

__global__ __launch_bounds__(256)
void split_y_kernel()
{
    const int q = blockIdx.x * 256 + threadIdx.x;
    const size_t o = (size_t)q * 4;
    float4 v = *(const float4*)(g_y + o);
    split_store4(v, A2H() + o, A2L() + o);
}

// W [K,N] row-major -> W^T [N,K] hi/lo.  WHICH=0 -> W1, WHICH=1 -> W2.
template<int WHICH>
__global__ __launch_bounds__(256)
void splitT_kernel(const float* __restrict__ W)
{
    constexpr int K = WHICH ? DINNER : DMODEL;
    constexpr int N = WHICH ? DMODEL : DPROJ;
    __shared__ float tile[32][33];
    const int n0 = blockIdx.x * 32, k0 = blockIdx.y * 32;
    const int tid = threadIdx.x;
    #pragma unroll
    for (int p = 0; p < 4; p++) {
        const int idx = tid + p * 256;
        const int kr = idx >> 5, nc = idx & 31;
        tile[kr][nc] = W[(size_t)(k0 + kr) * N + n0 + nc];
    }
    __syncthreads();
    const int nr = tid >> 3;
    const int kq = (tid & 7) * 4;
    float4 v = make_float4(tile[kq + 0][nr], tile[kq + 1][nr], tile[kq + 2][nr], tile[kq + 3][nr]);
    const size_t o = (size_t)(n0 + nr) * K + (k0 + kq);
    __nv_bfloat16* Th = WHICH ? W2H() : W1H();
    __nv_bfloat16* Tl = WHICH ? W2L() : W1L();
    split_store4(v, Th + o, Tl + o);
}

// =================================================================================
// bf16 hi/lo split GEMM via mma.sync (under test; overwrites the fp32 result).
// CTA 128x128, K-chunk 16, static 32KB smem, register double buffer, 8 warps.
// =================================================================================
template<int MODE>
__global__ __launch_bounds__(256)
void gemm_hmma(float* __restrict__ Cparam)
{
    constexpr int N  = MODE ? DMODEL : DPROJ;
    constexpr int K  = MODE ? DINNER : DMODEL;
    constexpr int CH = K / 16;

    __shared__ unsigned short sm[2][4][128][16];   // 32KB static

    const int tid  = threadIdx.x;
    const int lane = tid & 31, wid = tid >> 5;
    const int wm = wid & 1;
    const int wn = wid >> 1;
    const int bm = blockIdx.y * 128;
    const int bn = blockIdx.x * 128;

    const __nv_bfloat16* srcAh = (MODE ? A2H() : A1H()) + (size_t)bm * K;
    const __nv_bfloat16* srcAl = (MODE ? A2L() : A1L()) + (size_t)bm * K;
    const __nv_bfloat16* srcBh = (MODE ? W2H() : W1H()) + (size_t)bn * K;
    const __nv_bfloat16* srcBl = (MODE ? W2L() : W1L()) + (size_t)bn * K;
    float* C = MODE ? Cparam : g_P;

    float acc[4][4][4];
    #pragma unroll
    for (int mi = 0; mi < 4; mi++)
        #pragma unroll
        for (int nj = 0; nj < 4; nj++)
            #pragma unroll
            for (int e = 0; e < 4; e++) acc[mi][nj][e] = 0.f;

    const int crow = tid >> 2;
    const int cck  = tid & 3;

    ushort4 rb[8];
    #define LOAD_REGS(CHK) do {                                                       \
        _Pragma("unroll")                                                             \
        for (int j = 0; j < 8; j++) {                                                 \
            const __nv_bfloat16* sp = (j < 2) ? srcAh : (j < 4) ? srcAl               \
                                    : (j < 6) ? srcBh : srcBl;                        \
            const int r = ((j & 1) << 6) + crow;                                      \
            rb[j] = *(const ushort4*)(sp + (size_t)r * K + (CHK) * 16 + cck * 4);     \
        }                                                                             \
    } while (0)

    #define STORE_SMEM(S) do {                                                        \
        _Pragma("unroll")                                                             \
        for (int j = 0; j < 8; j++) {                                                 \
            const int r = ((j & 1) << 6) + crow;                                      \
            *(ushort4*)&sm[S][j >> 1][r][cck * 4] = rb[j];                            \
        }                                                                             \
    } while (0)

    LOAD_REGS(0);
    STORE_SMEM(0);
    __syncthreads();

    const int tg2 = (lane & 3) * 2;
    const int gq  = lane >> 2;

    for (int i = 0; i < CH; i++) {
        const int s = i & 1;
        if (i + 1 < CH) LOAD_REGS(i + 1);

        uint32_t ah[4][4], al[4][4], bh[4][2], bl[4][2];
        #pragma unroll
        for (int mi = 0; mi < 4; mi++) {
            const int ra = wm * 64 + mi * 16 + gq;
            ah[mi][0] = *(const uint32_t*)&sm[s][0][ra][tg2];
            ah[mi][1] = *(const uint32_t*)&sm[s][0][ra + 8][tg2];
            ah[mi][2] = *(const uint32_t*)&sm[s][0][ra][tg2 + 8];
            ah[mi][3] = *(const uint32_t*)&sm[s][0][ra + 8][tg2 + 8];
            al[mi][0] = *(const uint32_t*)&sm[s][1][ra][tg2];
            al[mi][1] = *(const uint32_t*)&sm[s][1][ra + 8][tg2];
            al[mi][2] = *(const uint32_t*)&sm[s][1][ra][tg2 + 8];
            al[mi][3] = *(const uint32_t*)&sm[s][1][ra + 8][tg2 + 8];
        }
        #pragma unroll
        for (int nj = 0; nj < 4; nj++) {
            const int rbn = wn * 32 + nj * 8 + gq;
            bh[nj][0] = *(const uint32_t*)&sm[s][2][rbn][tg2];
            bh[nj][1] = *(const uint32_t*)&sm[s][2][rbn][tg2 + 8];
            bl[nj][0] = *(const uint32_t*)&sm[s][3][rbn][tg2];
            bl[nj][1] = *(const uint32_t*)&sm[s][3][rbn][tg2 + 8];
        }
        #pragma unroll
        for (int mi = 0; mi < 4; mi++)
            #pragma unroll
            for (int nj = 0; nj < 4; nj++) {
                mma16816(acc[mi][nj], ah[mi], bh[nj]);
                mma16816(acc[mi][nj], ah[mi], bl[nj]);
                mma16816(acc[mi][nj], al[mi], bh[nj]);
            }

        if (i + 1 < CH) STORE_SMEM(s ^ 1);
        __syncthreads();
    }

    #pragma unroll
    for (int mi = 0; mi < 4; mi++) {
        const int row0 = bm + wm * 64 + mi * 16 + gq;
        #pragma unroll
        for (int nj = 0; nj < 4; nj++) {
            const int col = bn + wn * 32 + nj * 8 + tg2;
            const size_t o0 = MODE ? map_tbc(row0, col)     : (size_t)row0 * N + col;
            const size_t o1 = MODE ? map_tbc(row0 + 8, col) : (size_t)(row0 + 8) * N + col;
            *(float2*)(C + o0) = make_float2(acc[mi][nj][0], acc[mi][nj][1]);
            *(float2*)(C + o1) = make_float2(acc[mi][nj][2], acc[mi][nj][3]);
        }
    }
}

// =================================================================================
// Depthwise causal conv (k=4) + bias + silu.
// =================================================================================
__global__ __launch_bounds__(256)
void conv_silu_kernel(const float* __restrict__ cw, const float* __restrict__ cb)
{
    const int idx = blockIdx.x * 256 + threadIdx.x;
    const int d = idx & (DINNER - 1);
    const int m = idx >> 11;
    const int t = m & (T_LEN - 1);
    const int b = m >> 11;

    const float4 w = *(const float4*)(cw + d * 4);
    float acc = cb[d];
    const size_t rowbase = (size_t)(b * T_LEN) * DPROJ + d;
    if (t >= 3) acc = fmaf(g_P[rowbase + (size_t)(t - 3) * DPROJ], w.x, acc);
    if (t >= 2) acc = fmaf(g_P[rowbase + (size_t)(t - 2) * DPROJ], w.y, acc);
    if (t >= 1) acc = fmaf(g_P[rowbase + (size_t)(t - 1) * DPROJ], w.z, acc);
    acc = fmaf(g_P[rowbase + (size_t)t * DPROJ], w.w, acc);
    acc = acc * (1.f / (1.f + __expf(-acc)));
    g_uc[idx] = acc;
}

// =================================================================================
// x_proj
// =================================================================================
__global__ __launch_bounds__(128)
void xproj_kernel(const float* __restrict__ W_x)
{
    __shared__ float swl[64 * 96];
    __shared__ float su[16][64];
    const int m0 = blockIdx.x * 16;
    const int tid = threadIdx.x;

    float acc[16];
    #pragma unroll
    for (int mi = 0; mi < 16; mi++) acc[mi] = 0.f;

    for (int kb = 0; kb < DINNER; kb += 64) {
        __syncthreads();
        #pragma unroll 4
        for (int i = tid; i < 64 * 96; i += 128) swl[i] = W_x[kb * 96 + i];
        #pragma unroll
        for (int i = tid; i < 16 * 64; i += 128) {
            const int mi = i >> 6, c = i & 63;
            su[mi][c] = g_uc[(size_t)(m0 + mi) * DINNER + kb + c];
        }
        __syncthreads();
        if (tid < 96) {
            #pragma unroll 2
            for (int r = 0; r < 64; r++) {
                const float w = swl[r * 96 + tid];
                #pragma unroll
                for (int mi = 0; mi < 16; mi++)
                    acc[mi] = fmaf(su[mi][r], w, acc[mi]);
            }
        }
    }
    if (tid < 96) {
        #pragma unroll
        for (int mi = 0; mi < 16; mi++)
            g_xdbl[(size_t)(m0 + mi) * NXP + tid] = acc[mi];
    }
}

// =================================================================================
// dt_proj + softplus
// =================================================================================
__global__ __launch_bounds__(128)
void dtproj_kernel(const float* __restrict__ W_dt, const float* __restrict__ b_dt)
{
    __shared__ float sw[64][128];
    __shared__ float sx[16][64];
    const int d0 = blockIdx.x * 128;
    const int m0 = blockIdx.y * 16;
    const int tid = threadIdx.x;

    #pragma unroll 4
    for (int i = tid; i < 64 * 128; i += 128) {
        const int r = i >> 7, dd = i & 127;
        sw[r][dd] = W_dt[(size_t)r * DINNER + d0 + dd];
    }
    #pragma unroll
    for (int i = tid; i < 16 * 64; i += 128) {
        const int mi = i >> 6, r = i & 63;
        sx[mi][r] = g_xdbl[(size_t)(m0 + mi) * NXP + r];
    }
    __syncthreads();

    float acc[16];
    const float bb = b_dt[d0 + tid];
    #pragma unroll
    for (int mi = 0; mi < 16; mi++) acc[mi] = bb;

    #pragma unroll 2
    for (int r = 0; r < 64; r++) {
        const float w = sw[r][tid];
        #pragma unroll
        for (int mi = 0; mi < 16; mi++)
            acc[mi] = fmaf(sx[mi][r], w, acc[mi]);
    }
    #pragma unroll
    for (int mi = 0; mi < 16; mi++) {
        const float z = acc[mi];
        const float sp = (z > 15.f) ? z : log1pf(__expf(z));
        g_delta[(size_t)(m0 + mi) * DINNER + d0 + tid] = sp;
    }
}

// =================================================================================
// Selective scan + skip + gate.
// =================================================================================
__global__ __launch_bounds__(128)
void scan_kernel(const float* __restrict__ A_log, const float* __restrict__ Dv)
{
    const int b = blockIdx.y;
    const int d0 = blockIdx.x * 32;
    const int tid = threadIdx.x;
    const int w = tid >> 5, lane = tid & 31;
    const int g = lane >> 2, q = lane & 3;
    const int d = d0 + w * 8 + g;
    const int nb = q * 4;

    const float A0 = -__expf(A_log[d * DSTATE + nb + 0]);
    const float A1 = -__expf(A_log[d * DSTATE + nb + 1]);
    const float A2 = -__expf(A_log[d * DSTATE + nb + 2]);
    const float A3 = -__expf(A_log[d * DSTATE + nb + 3]);
    const float Dd = Dv[d];

    float h0 = 0.f, h1 = 0.f, h2 = 0.f, h3 = 0.f;
    size_t base  = (size_t)b * T_LEN * DINNER + d;
    size_t rbase = (size_t)b * T_LEN * DPROJ + DINNER + d;
    size_t xb    = (size_t)b * T_LEN * NXP;

    #pragma unroll 2
    for (int t = 0; t < T_LEN; t++) {
        const float dl = g_delta[base];
        const float uu = g_uc[base];
        const float4 Bv = *(const float4*)&g_xdbl[xb + DTRANK + nb];
        const float4 Cv = *(const float4*)&g_xdbl[xb + DTRANK + DSTATE + nb];

        const float du = dl * uu;
        h0 = fmaf(__expf(dl * A0), h0, du * Bv.x);
        h1 = fmaf(__expf(dl * A1), h1, du * Bv.y);
        h2 = fmaf(__expf(dl * A2), h2, du * Bv.z);
        h3 = fmaf(__expf(dl * A3), h3, du * Bv.w);

        float p = fmaf(h0, Cv.x, fmaf(h1, Cv.y, fmaf(h2, Cv.z, h3 * Cv.w)));
        p += __shfl_xor_sync(0xffffffffu, p, 1);
        p += __shfl_xor_sync(0xffffffffu, p, 2);

        if (q == 0) {
            const float resv = g_P[rbase];
            const float gate = resv * (1.f / (1.f + __expf(-resv)));
            g_y[base] = (p + uu * Dd) * gate;
        }
        base += DINNER;
        rbase += DPROJ;
        xb += NXP;
    }
}

// =================================================================================
// launch — fp32 path guarantees correctness; HMMA path overwrites (under test)
// =================================================================================
extern "C" void kernel_launch(void* const* d_in, const int* in_sizes, int n_in,
                              void* d_out, int out_size)
{
    const float* x      = (const float*)d_in[0];
    const float* W_in   = (const float*)d_in[1];
    const float* conv_w = (const float*)d_in[2];
    const float* conv_b = (const float*)d_in[3];
    const float* W_x    = (const float*)d_in[4];
    const float* W_dt   = (const float*)d_in[5];
    const float* b_dt   = (const float*)d_in[6];
    const float* A_log  = (const float*)d_in[7];
    const float* Dv     = (const float*)d_in[8];
    const float* W_out  = (const float*)d_in[9];
    float* out = (float*)d_out;

    // --- in_proj: splits, fp32 reference, HMMA overwrite ---
    split_x_kernel<<<(M_ROWS * DMODEL / 4) / 256, 256>>>(x);
    splitT_kernel<0><<<dim3(DPROJ / 32, DMODEL / 32), 256>>>(W_in);
    gemm_f32<0><<<dim3(DPROJ / 128, M_ROWS / 128), 256>>>(x, W_in, nullptr, M_ROWS, DPROJ, DMODEL);
    gemm_hmma<0><<<dim3(DPROJ / 128, M_ROWS / 128), 256>>>(nullptr);

    // --- mid pipeline (consumes g_P; frees the W1/A1 alias regions) ---
    conv_silu_kernel<<<(M_ROWS * DINNER) / 256, 256>>>(conv_w, conv_b);
    xproj_kernel<<<M_ROWS / 16, 128>>>(W_x);
    dtproj_kernel<<<dim3(DINNER / 128, M_ROWS / 16), 128>>>(W_dt, b_dt);
    scan_kernel<<<dim3(DINNER / 32, B_SZ), 128>>>(A_log, Dv);

    // --- out_proj: splits (into now-free scratch), fp32 reference, HMMA overwrite ---
    split_y_kernel<<<(M_ROWS * DINNER / 4) / 256, 256>>>();
    splitT_kernel<1><<<dim3(DMODEL / 32, DINNER / 32), 256>>>(W_out);
    gemm_f32<1><<<dim3(DMODEL / 128, M_ROWS / 128), 256>>>(nullptr, W_out, out, M_ROWS, DMODEL, DINNER);
    gemm_hmma<1><<<dim3(DMODEL / 128, M_ROWS / 128), 256>>>(out);
}

// round 7
// speedup vs baseline: 1.5407x; 1.5407x over previous
#include <cuda_runtime.h>
#include <cuda_bf16.h>
#include <math.h>
#include <stdint.h>

#define T_LEN   2048
#define B_SZ    4
#define DMODEL  1024
#define DINNER  2048
#define DSTATE  16
#define DTRANK  64
#define NXP     96
#define M_ROWS  (B_SZ*T_LEN)   // 8192
#define DPROJ   (2*DINNER)     // 4096

// ---------------- scratch (device globals; EXACTLY the round-1 set, 323MB) ----------
__device__ __align__(16) float g_P[(size_t)M_ROWS * DPROJ];     // in_proj output (u | res)
__device__ __align__(16) float g_uc[(size_t)M_ROWS * DINNER];   // conv+silu output
__device__ __align__(16) float g_xdbl[(size_t)M_ROWS * NXP];    // x_proj output (dt|B|C)
__device__ __align__(16) float g_delta[(size_t)M_ROWS * DINNER];// softplus(dt_proj)
__device__ __align__(16) float g_y[(size_t)M_ROWS * DINNER];    // gated ssm output

// ---- bf16 hi/lo operands ALIASED into scratch (lifetimes verified disjoint) ----
// A1 (split of x):    lives in g_delta until dtproj writes it   (33.6MB <= 64MB)
// W1 (split W_in^T):  lives in g_uc    until conv writes it     (16.8MB <= 64MB)
// A2 (split of y):    g_delta (hi) + g_uc (lo), after scan
// W2 (split W_out^T): lives in g_P after scan consumed res      ( 8.4MB <= 128MB)
__device__ __forceinline__ __nv_bfloat16* A1H() { return (__nv_bfloat16*)g_delta; }
__device__ __forceinline__ __nv_bfloat16* A1L() { return (__nv_bfloat16*)g_delta + (size_t)M_ROWS * DMODEL; }
__device__ __forceinline__ __nv_bfloat16* W1H() { return (__nv_bfloat16*)g_uc; }
__device__ __forceinline__ __nv_bfloat16* W1L() { return (__nv_bfloat16*)g_uc + (size_t)DPROJ * DMODEL; }
__device__ __forceinline__ __nv_bfloat16* A2H() { return (__nv_bfloat16*)g_delta; }
__device__ __forceinline__ __nv_bfloat16* A2L() { return (__nv_bfloat16*)g_uc; }
__device__ __forceinline__ __nv_bfloat16* W2H() { return (__nv_bfloat16*)g_P; }
__device__ __forceinline__ __nv_bfloat16* W2L() { return (__nv_bfloat16*)g_P + (size_t)DMODEL * DINNER; }

// ---------------- helpers ----------------
__device__ __forceinline__ void mma16816(float* c, const uint32_t* a, const uint32_t* b) {
    asm volatile("mma.sync.aligned.m16n8k16.row.col.f32.bf16.bf16.f32 "
        "{%0,%1,%2,%3}, {%4,%5,%6,%7}, {%8,%9}, {%0,%1,%2,%3};"
        : "+f"(c[0]), "+f"(c[1]), "+f"(c[2]), "+f"(c[3])
        : "r"(a[0]), "r"(a[1]), "r"(a[2]), "r"(a[3]), "r"(b[0]), "r"(b[1]));
}

__device__ __forceinline__ size_t map_tbc(int m, int col) {
    return (size_t)(m & (T_LEN - 1)) * (B_SZ * DMODEL) + (size_t)(m >> 11) * DMODEL + col;
}

// =================================================================================
// Split kernels: fp32 -> bf16 hi/lo (targets are the aliased scratch regions)
// =================================================================================
__device__ __forceinline__ void split_store4(float4 v, __nv_bfloat16* hp, __nv_bfloat16* lp) {
    __nv_bfloat16 h0 = __float2bfloat16_rn(v.x), h1 = __float2bfloat16_rn(v.y);
    __nv_bfloat16 h2 = __float2bfloat16_rn(v.z), h3 = __float2bfloat16_rn(v.w);
    __nv_bfloat16 l0 = __float2bfloat16_rn(v.x - __bfloat162float(h0));
    __nv_bfloat16 l1 = __float2bfloat16_rn(v.y - __bfloat162float(h1));
    __nv_bfloat16 l2 = __float2bfloat16_rn(v.z - __bfloat162float(h2));
    __nv_bfloat16 l3 = __float2bfloat16_rn(v.w - __bfloat162float(h3));
    *(ushort4*)hp = make_ushort4(__bfloat16_as_ushort(h0), __bfloat16_as_ushort(h1),
                                 __bfloat16_as_ushort(h2), __bfloat16_as_ushort(h3));
    *(ushort4*)lp = make_ushort4(__bfloat16_as_ushort(l0), __bfloat16_as_ushort(l1),
                                 __bfloat16_as_ushort(l2), __bfloat16_as_ushort(l3));
}

__global__ __launch_bounds__(256)
void split_x_kernel(const float* __restrict__ x)
{
    const int q = blockIdx.x * 256 + threadIdx.x;
    const int c = (q & 255) * 4;
    const int m = q >> 8;
    const int t = m & (T_LEN - 1), b = m >> 11;
    float4 v = *(const float4*)(x + (size_t)t * (B_SZ * DMODEL) + b * DMODEL + c);
    const size_t o = (size_t)m * DMODEL + c;
    split_store4(v, A1H() + o, A1L() + o);
}

__global__ __launch_bounds__(256)
void split_y_kernel()
{
    const int q = blockIdx.x * 256 + threadIdx.x;
    const size_t o = (size_t)q * 4;
    float4 v = *(const float4*)(g_y + o);
    split_store4(v, A2H() + o, A2L() + o);
}

// W [K,N] row-major -> W^T [N,K] hi/lo.  WHICH=0 -> W1, WHICH=1 -> W2.
template<int WHICH>
__global__ __launch_bounds__(256)
void splitT_kernel(const float* __restrict__ W)
{
    constexpr int K = WHICH ? DINNER : DMODEL;
    constexpr int N = WHICH ? DMODEL : DPROJ;
    __shared__ float tile[32][33];
    const int n0 = blockIdx.x * 32, k0 = blockIdx.y * 32;
    const int tid = threadIdx.x;
    #pragma unroll
    for (int p = 0; p < 4; p++) {
        const int idx = tid + p * 256;
        const int kr = idx >> 5, nc = idx & 31;
        tile[kr][nc] = W[(size_t)(k0 + kr) * N + n0 + nc];
    }
    __syncthreads();
    const int nr = tid >> 3;
    const int kq = (tid & 7) * 4;
    float4 v = make_float4(tile[kq + 0][nr], tile[kq + 1][nr], tile[kq + 2][nr], tile[kq + 3][nr]);
    const size_t o = (size_t)(n0 + nr) * K + (k0 + kq);
    __nv_bfloat16* Th = WHICH ? W2H() : W1H();
    __nv_bfloat16* Tl = WHICH ? W2L() : W1L();
    split_store4(v, Th + o, Tl + o);
}

// =================================================================================
// bf16 hi/lo split GEMM via mma.sync (PROVEN in round 6).
// CTA 128x128, K-chunk 16, static 32KB smem, register double buffer, 8 warps.
// MODE 0: g_P = A1 @ W1  (N=4096, K=1024)
// MODE 1: out = A2 @ W2  (N=1024, K=2048), output through map_tbc
// =================================================================================
template<int MODE>
__global__ __launch_bounds__(256)
void gemm_hmma(float* __restrict__ Cparam)
{
    constexpr int N  = MODE ? DMODEL : DPROJ;
    constexpr int K  = MODE ? DINNER : DMODEL;
    constexpr int CH = K / 16;

    __shared__ unsigned short sm[2][4][128][16];   // 32KB static

    const int tid  = threadIdx.x;
    const int lane = tid & 31, wid = tid >> 5;
    const int wm = wid & 1;
    const int wn = wid >> 1;
    const int bm = blockIdx.y * 128;
    const int bn = blockIdx.x * 128;

    const __nv_bfloat16* srcAh = (MODE ? A2H() : A1H()) + (size_t)bm * K;
    const __nv_bfloat16* srcAl = (MODE ? A2L() : A1L()) + (size_t)bm * K;
    const __nv_bfloat16* srcBh = (MODE ? W2H() : W1H()) + (size_t)bn * K;
    const __nv_bfloat16* srcBl = (MODE ? W2L() : W1L()) + (size_t)bn * K;
    float* C = MODE ? Cparam : g_P;

    float acc[4][4][4];
    #pragma unroll
    for (int mi = 0; mi < 4; mi++)
        #pragma unroll
        for (int nj = 0; nj < 4; nj++)
            #pragma unroll
            for (int e = 0; e < 4; e++) acc[mi][nj][e] = 0.f;

    const int crow = tid >> 2;
    const int cck  = tid & 3;

    ushort4 rb[8];
    #define LOAD_REGS(CHK) do {                                                       \
        _Pragma("unroll")                                                             \
        for (int j = 0; j < 8; j++) {                                                 \
            const __nv_bfloat16* sp = (j < 2) ? srcAh : (j < 4) ? srcAl               \
                                    : (j < 6) ? srcBh : srcBl;                        \
            const int r = ((j & 1) << 6) + crow;                                      \
            rb[j] = *(const ushort4*)(sp + (size_t)r * K + (CHK) * 16 + cck * 4);     \
        }                                                                             \
    } while (0)

    #define STORE_SMEM(S) do {                                                        \
        _Pragma("unroll")                                                             \
        for (int j = 0; j < 8; j++) {                                                 \
            const int r = ((j & 1) << 6) + crow;                                      \
            *(ushort4*)&sm[S][j >> 1][r][cck * 4] = rb[j];                            \
        }                                                                             \
    } while (0)

    LOAD_REGS(0);
    STORE_SMEM(0);
    __syncthreads();

    const int tg2 = (lane & 3) * 2;
    const int gq  = lane >> 2;

    for (int i = 0; i < CH; i++) {
        const int s = i & 1;
        if (i + 1 < CH) LOAD_REGS(i + 1);

        uint32_t ah[4][4], al[4][4], bh[4][2], bl[4][2];
        #pragma unroll
        for (int mi = 0; mi < 4; mi++) {
            const int ra = wm * 64 + mi * 16 + gq;
            ah[mi][0] = *(const uint32_t*)&sm[s][0][ra][tg2];
            ah[mi][1] = *(const uint32_t*)&sm[s][0][ra + 8][tg2];
            ah[mi][2] = *(const uint32_t*)&sm[s][0][ra][tg2 + 8];
            ah[mi][3] = *(const uint32_t*)&sm[s][0][ra + 8][tg2 + 8];
            al[mi][0] = *(const uint32_t*)&sm[s][1][ra][tg2];
            al[mi][1] = *(const uint32_t*)&sm[s][1][ra + 8][tg2];
            al[mi][2] = *(const uint32_t*)&sm[s][1][ra][tg2 + 8];
            al[mi][3] = *(const uint32_t*)&sm[s][1][ra + 8][tg2 + 8];
        }
        #pragma unroll
        for (int nj = 0; nj < 4; nj++) {
            const int rbn = wn * 32 + nj * 8 + gq;
            bh[nj][0] = *(const uint32_t*)&sm[s][2][rbn][tg2];
            bh[nj][1] = *(const uint32_t*)&sm[s][2][rbn][tg2 + 8];
            bl[nj][0] = *(const uint32_t*)&sm[s][3][rbn][tg2];
            bl[nj][1] = *(const uint32_t*)&sm[s][3][rbn][tg2 + 8];
        }
        #pragma unroll
        for (int mi = 0; mi < 4; mi++)
            #pragma unroll
            for (int nj = 0; nj < 4; nj++) {
                mma16816(acc[mi][nj], ah[mi], bh[nj]);
                mma16816(acc[mi][nj], ah[mi], bl[nj]);
                mma16816(acc[mi][nj], al[mi], bh[nj]);
            }

        if (i + 1 < CH) STORE_SMEM(s ^ 1);
        __syncthreads();
    }

    #pragma unroll
    for (int mi = 0; mi < 4; mi++) {
        const int row0 = bm + wm * 64 + mi * 16 + gq;
        #pragma unroll
        for (int nj = 0; nj < 4; nj++) {
            const int col = bn + wn * 32 + nj * 8 + tg2;
            const size_t o0 = MODE ? map_tbc(row0, col)     : (size_t)row0 * N + col;
            const size_t o1 = MODE ? map_tbc(row0 + 8, col) : (size_t)(row0 + 8) * N + col;
            *(float2*)(C + o0) = make_float2(acc[mi][nj][0], acc[mi][nj][1]);
            *(float2*)(C + o1) = make_float2(acc[mi][nj][2], acc[mi][nj][3]);
        }
    }
}

// =================================================================================
// Depthwise causal conv (k=4) + bias + silu.
// =================================================================================
__global__ __launch_bounds__(256)
void conv_silu_kernel(const float* __restrict__ cw, const float* __restrict__ cb)
{
    const int idx = blockIdx.x * 256 + threadIdx.x;
    const int d = idx & (DINNER - 1);
    const int m = idx >> 11;
    const int t = m & (T_LEN - 1);
    const int b = m >> 11;

    const float4 w = *(const float4*)(cw + d * 4);
    float acc = cb[d];
    const size_t rowbase = (size_t)(b * T_LEN) * DPROJ + d;
    if (t >= 3) acc = fmaf(g_P[rowbase + (size_t)(t - 3) * DPROJ], w.x, acc);
    if (t >= 2) acc = fmaf(g_P[rowbase + (size_t)(t - 2) * DPROJ], w.y, acc);
    if (t >= 1) acc = fmaf(g_P[rowbase + (size_t)(t - 1) * DPROJ], w.z, acc);
    acc = fmaf(g_P[rowbase + (size_t)t * DPROJ], w.w, acc);
    acc = acc * (1.f / (1.f + __expf(-acc)));
    g_uc[idx] = acc;
}

// =================================================================================
// x_proj
// =================================================================================
__global__ __launch_bounds__(128)
void xproj_kernel(const float* __restrict__ W_x)
{
    __shared__ float swl[64 * 96];
    __shared__ float su[16][64];
    const int m0 = blockIdx.x * 16;
    const int tid = threadIdx.x;

    float acc[16];
    #pragma unroll
    for (int mi = 0; mi < 16; mi++) acc[mi] = 0.f;

    for (int kb = 0; kb < DINNER; kb += 64) {
        __syncthreads();
        #pragma unroll 4
        for (int i = tid; i < 64 * 96; i += 128) swl[i] = W_x[kb * 96 + i];
        #pragma unroll
        for (int i = tid; i < 16 * 64; i += 128) {
            const int mi = i >> 6, c = i & 63;
            su[mi][c] = g_uc[(size_t)(m0 + mi) * DINNER + kb + c];
        }
        __syncthreads();
        if (tid < 96) {
            #pragma unroll 2
            for (int r = 0; r < 64; r++) {
                const float w = swl[r * 96 + tid];
                #pragma unroll
                for (int mi = 0; mi < 16; mi++)
                    acc[mi] = fmaf(su[mi][r], w, acc[mi]);
            }
        }
    }
    if (tid < 96) {
        #pragma unroll
        for (int mi = 0; mi < 16; mi++)
            g_xdbl[(size_t)(m0 + mi) * NXP + tid] = acc[mi];
    }
}

// =================================================================================
// dt_proj + softplus
// =================================================================================
__global__ __launch_bounds__(128)
void dtproj_kernel(const float* __restrict__ W_dt, const float* __restrict__ b_dt)
{
    __shared__ float sw[64][128];
    __shared__ float sx[16][64];
    const int d0 = blockIdx.x * 128;
    const int m0 = blockIdx.y * 16;
    const int tid = threadIdx.x;

    #pragma unroll 4
    for (int i = tid; i < 64 * 128; i += 128) {
        const int r = i >> 7, dd = i & 127;
        sw[r][dd] = W_dt[(size_t)r * DINNER + d0 + dd];
    }
    #pragma unroll
    for (int i = tid; i < 16 * 64; i += 128) {
        const int mi = i >> 6, r = i & 63;
        sx[mi][r] = g_xdbl[(size_t)(m0 + mi) * NXP + r];
    }
    __syncthreads();

    float acc[16];
    const float bb = b_dt[d0 + tid];
    #pragma unroll
    for (int mi = 0; mi < 16; mi++) acc[mi] = bb;

    #pragma unroll 2
    for (int r = 0; r < 64; r++) {
        const float w = sw[r][tid];
        #pragma unroll
        for (int mi = 0; mi < 16; mi++)
            acc[mi] = fmaf(sx[mi][r], w, acc[mi]);
    }
    #pragma unroll
    for (int mi = 0; mi < 16; mi++) {
        const float z = acc[mi];
        const float sp = (z > 15.f) ? z : log1pf(__expf(z));
        g_delta[(size_t)(m0 + mi) * DINNER + d0 + tid] = sp;
    }
}

// =================================================================================
// Selective scan + skip + gate.
// =================================================================================
__global__ __launch_bounds__(128)
void scan_kernel(const float* __restrict__ A_log, const float* __restrict__ Dv)
{
    const int b = blockIdx.y;
    const int d0 = blockIdx.x * 32;
    const int tid = threadIdx.x;
    const int w = tid >> 5, lane = tid & 31;
    const int g = lane >> 2, q = lane & 3;
    const int d = d0 + w * 8 + g;
    const int nb = q * 4;

    const float A0 = -__expf(A_log[d * DSTATE + nb + 0]);
    const float A1 = -__expf(A_log[d * DSTATE + nb + 1]);
    const float A2 = -__expf(A_log[d * DSTATE + nb + 2]);
    const float A3 = -__expf(A_log[d * DSTATE + nb + 3]);
    const float Dd = Dv[d];

    float h0 = 0.f, h1 = 0.f, h2 = 0.f, h3 = 0.f;
    size_t base  = (size_t)b * T_LEN * DINNER + d;
    size_t rbase = (size_t)b * T_LEN * DPROJ + DINNER + d;
    size_t xb    = (size_t)b * T_LEN * NXP;

    #pragma unroll 2
    for (int t = 0; t < T_LEN; t++) {
        const float dl = g_delta[base];
        const float uu = g_uc[base];
        const float4 Bv = *(const float4*)&g_xdbl[xb + DTRANK + nb];
        const float4 Cv = *(const float4*)&g_xdbl[xb + DTRANK + DSTATE + nb];

        const float du = dl * uu;
        h0 = fmaf(__expf(dl * A0), h0, du * Bv.x);
        h1 = fmaf(__expf(dl * A1), h1, du * Bv.y);
        h2 = fmaf(__expf(dl * A2), h2, du * Bv.z);
        h3 = fmaf(__expf(dl * A3), h3, du * Bv.w);

        float p = fmaf(h0, Cv.x, fmaf(h1, Cv.y, fmaf(h2, Cv.z, h3 * Cv.w)));
        p += __shfl_xor_sync(0xffffffffu, p, 1);
        p += __shfl_xor_sync(0xffffffffu, p, 2);

        if (q == 0) {
            const float resv = g_P[rbase];
            const float gate = resv * (1.f / (1.f + __expf(-resv)));
            g_y[base] = (p + uu * Dd) * gate;
        }
        base += DINNER;
        rbase += DPROJ;
        xb += NXP;
    }
}

// =================================================================================
// launch — HMMA GEMMs only (fp32 reference path removed)
// =================================================================================
extern "C" void kernel_launch(void* const* d_in, const int* in_sizes, int n_in,
                              void* d_out, int out_size)
{
    const float* x      = (const float*)d_in[0];
    const float* W_in   = (const float*)d_in[1];
    const float* conv_w = (const float*)d_in[2];
    const float* conv_b = (const float*)d_in[3];
    const float* W_x    = (const float*)d_in[4];
    const float* W_dt   = (const float*)d_in[5];
    const float* b_dt   = (const float*)d_in[6];
    const float* A_log  = (const float*)d_in[7];
    const float* Dv     = (const float*)d_in[8];
    const float* W_out  = (const float*)d_in[9];
    float* out = (float*)d_out;

    // --- in_proj ---
    split_x_kernel<<<(M_ROWS * DMODEL / 4) / 256, 256>>>(x);
    splitT_kernel<0><<<dim3(DPROJ / 32, DMODEL / 32), 256>>>(W_in);
    gemm_hmma<0><<<dim3(DPROJ / 128, M_ROWS / 128), 256>>>(nullptr);

    // --- mid pipeline ---
    conv_silu_kernel<<<(M_ROWS * DINNER) / 256, 256>>>(conv_w, conv_b);
    xproj_kernel<<<M_ROWS / 16, 128>>>(W_x);
    dtproj_kernel<<<dim3(DINNER / 128, M_ROWS / 16), 128>>>(W_dt, b_dt);
    scan_kernel<<<dim3(DINNER / 32, B_SZ), 128>>>(A_log, Dv);

    // --- out_proj ---
    split_y_kernel<<<(M_ROWS * DINNER / 4) / 256, 256>>>();
    splitT_kernel<1><<<dim3(DMODEL / 32, DINNER / 32), 256>>>(W_out);
    gemm_hmma<1><<<dim3(DMODEL / 128, M_ROWS / 128), 256>>>(out);
}

// round 8
// speedup vs baseline: 3.0844x; 2.0019x over previous
#include <cuda_runtime.h>
#include <cuda_bf16.h>
#include <math.h>
#include <stdint.h>

#define T_LEN   2048
#define B_SZ    4
#define DMODEL  1024
#define DINNER  2048
#define DSTATE  16
#define DTRANK  64
#define NXP     96
#define M_ROWS  (B_SZ*T_LEN)   // 8192
#define DPROJ   (2*DINNER)     // 4096

// ---------------- scratch (device globals; proven 323MB set) ----------
__device__ __align__(16) float g_P[(size_t)M_ROWS * DPROJ];     // in_proj output (u | res)
__device__ __align__(16) float g_uc[(size_t)M_ROWS * DINNER];   // conv+silu output
__device__ __align__(16) float g_xdbl[(size_t)M_ROWS * NXP];    // x_proj output (dt|B|C)
__device__ __align__(16) float g_delta[(size_t)M_ROWS * DINNER];// softplus(dt_proj)
__device__ __align__(16) float g_y[(size_t)M_ROWS * DINNER];    // gated ssm output

// ---- bf16 hi/lo operands ALIASED into scratch (lifetimes verified disjoint) ----
__device__ __forceinline__ __nv_bfloat16* A1H() { return (__nv_bfloat16*)g_delta; }
__device__ __forceinline__ __nv_bfloat16* A1L() { return (__nv_bfloat16*)g_delta + (size_t)M_ROWS * DMODEL; }
__device__ __forceinline__ __nv_bfloat16* W1H() { return (__nv_bfloat16*)g_uc; }
__device__ __forceinline__ __nv_bfloat16* W1L() { return (__nv_bfloat16*)g_uc + (size_t)DPROJ * DMODEL; }
__device__ __forceinline__ __nv_bfloat16* A2H() { return (__nv_bfloat16*)g_delta; }
__device__ __forceinline__ __nv_bfloat16* A2L() { return (__nv_bfloat16*)g_uc; }
__device__ __forceinline__ __nv_bfloat16* W2H() { return (__nv_bfloat16*)g_P; }
__device__ __forceinline__ __nv_bfloat16* W2L() { return (__nv_bfloat16*)g_P + (size_t)DMODEL * DINNER; }

// ---------------- helpers ----------------
__device__ __forceinline__ uint32_t smem_u32(const void* p) {
    uint32_t a;
    asm("{ .reg .u64 t; cvta.to.shared.u64 t, %1; cvt.u32.u64 %0, t; }" : "=r"(a) : "l"(p));
    return a;
}
__device__ __forceinline__ void cp16(uint32_t d, const void* s) {
    asm volatile("cp.async.cg.shared.global [%0], [%1], 16;" :: "r"(d), "l"(s));
}
#define CP_COMMIT() asm volatile("cp.async.commit_group;" ::: "memory")
#define CP_WAIT3()  asm volatile("cp.async.wait_group 3;"  ::: "memory")

__device__ __forceinline__ void mma16816(float* c, const uint32_t* a, const uint32_t* b) {
    asm volatile("mma.sync.aligned.m16n8k16.row.col.f32.bf16.bf16.f32 "
        "{%0,%1,%2,%3}, {%4,%5,%6,%7}, {%8,%9}, {%0,%1,%2,%3};"
        : "+f"(c[0]), "+f"(c[1]), "+f"(c[2]), "+f"(c[3])
        : "r"(a[0]), "r"(a[1]), "r"(a[2]), "r"(a[3]), "r"(b[0]), "r"(b[1]));
}

__device__ __forceinline__ size_t map_tbc(int m, int col) {
    return (size_t)(m & (T_LEN - 1)) * (B_SZ * DMODEL) + (size_t)(m >> 11) * DMODEL + col;
}

// =================================================================================
// Split kernels: fp32 -> bf16 hi/lo (targets are the aliased scratch regions)
// =================================================================================
__device__ __forceinline__ void split_store4(float4 v, __nv_bfloat16* hp, __nv_bfloat16* lp) {
    __nv_bfloat16 h0 = __float2bfloat16_rn(v.x), h1 = __float2bfloat16_rn(v.y);
    __nv_bfloat16 h2 = __float2bfloat16_rn(v.z), h3 = __float2bfloat16_rn(v.w);
    __nv_bfloat16 l0 = __float2bfloat16_rn(v.x - __bfloat162float(h0));
    __nv_bfloat16 l1 = __float2bfloat16_rn(v.y - __bfloat162float(h1));
    __nv_bfloat16 l2 = __float2bfloat16_rn(v.z - __bfloat162float(h2));
    __nv_bfloat16 l3 = __float2bfloat16_rn(v.w - __bfloat162float(h3));
    *(ushort4*)hp = make_ushort4(__bfloat16_as_ushort(h0), __bfloat16_as_ushort(h1),
                                 __bfloat16_as_ushort(h2), __bfloat16_as_ushort(h3));
    *(ushort4*)lp = make_ushort4(__bfloat16_as_ushort(l0), __bfloat16_as_ushort(l1),
                                 __bfloat16_as_ushort(l2), __bfloat16_as_ushort(l3));
}

__global__ __launch_bounds__(256)
void split_x_kernel(const float* __restrict__ x)
{
    const int q = blockIdx.x * 256 + threadIdx.x;
    const int c = (q & 255) * 4;
    const int m = q >> 8;
    const int t = m & (T_LEN - 1), b = m >> 11;
    float4 v = *(const float4*)(x + (size_t)t * (B_SZ * DMODEL) + b * DMODEL + c);
    const size_t o = (size_t)m * DMODEL + c;
    split_store4(v, A1H() + o, A1L() + o);
}

__global__ __launch_bounds__(256)
void split_y_kernel()
{
    const int q = blockIdx.x * 256 + threadIdx.x;
    const size_t o = (size_t)q * 4;
    float4 v = *(const float4*)(g_y + o);
    split_store4(v, A2H() + o, A2L() + o);
}

template<int WHICH>
__global__ __launch_bounds__(256)
void splitT_kernel(const float* __restrict__ W)
{
    constexpr int K = WHICH ? DINNER : DMODEL;
    constexpr int N = WHICH ? DMODEL : DPROJ;
    __shared__ float tile[32][33];
    const int n0 = blockIdx.x * 32, k0 = blockIdx.y * 32;
    const int tid = threadIdx.x;
    #pragma unroll
    for (int p = 0; p < 4; p++) {
        const int idx = tid + p * 256;
        const int kr = idx >> 5, nc = idx & 31;
        tile[kr][nc] = W[(size_t)(k0 + kr) * N + n0 + nc];
    }
    __syncthreads();
    const int nr = tid >> 3;
    const int kq = (tid & 7) * 4;
    float4 v = make_float4(tile[kq + 0][nr], tile[kq + 1][nr], tile[kq + 2][nr], tile[kq + 3][nr]);
    const size_t o = (size_t)(n0 + nr) * K + (k0 + kq);
    __nv_bfloat16* Th = WHICH ? W2H() : W1H();
    __nv_bfloat16* Tl = WHICH ? W2L() : W1L();
    split_store4(v, Th + o, Tl + o);
}

// =================================================================================
// bf16 hi/lo split GEMM via mma.sync (PROVEN in rounds 6/7) — unchanged.
// =================================================================================
template<int MODE>
__global__ __launch_bounds__(256)
void gemm_hmma(float* __restrict__ Cparam)
{
    constexpr int N  = MODE ? DMODEL : DPROJ;
    constexpr int K  = MODE ? DINNER : DMODEL;
    constexpr int CH = K / 16;

    __shared__ unsigned short sm[2][4][128][16];   // 32KB static

    const int tid  = threadIdx.x;
    const int lane = tid & 31, wid = tid >> 5;
    const int wm = wid & 1;
    const int wn = wid >> 1;
    const int bm = blockIdx.y * 128;
    const int bn = blockIdx.x * 128;

    const __nv_bfloat16* srcAh = (MODE ? A2H() : A1H()) + (size_t)bm * K;
    const __nv_bfloat16* srcAl = (MODE ? A2L() : A1L()) + (size_t)bm * K;
    const __nv_bfloat16* srcBh = (MODE ? W2H() : W1H()) + (size_t)bn * K;
    const __nv_bfloat16* srcBl = (MODE ? W2L() : W1L()) + (size_t)bn * K;
    float* C = MODE ? Cparam : g_P;

    float acc[4][4][4];
    #pragma unroll
    for (int mi = 0; mi < 4; mi++)
        #pragma unroll
        for (int nj = 0; nj < 4; nj++)
            #pragma unroll
            for (int e = 0; e < 4; e++) acc[mi][nj][e] = 0.f;

    const int crow = tid >> 2;
    const int cck  = tid & 3;

    ushort4 rb[8];
    #define LOAD_REGS(CHK) do {                                                       \
        _Pragma("unroll")                                                             \
        for (int j = 0; j < 8; j++) {                                                 \
            const __nv_bfloat16* sp = (j < 2) ? srcAh : (j < 4) ? srcAl               \
                                    : (j < 6) ? srcBh : srcBl;                        \
            const int r = ((j & 1) << 6) + crow;                                      \
            rb[j] = *(const ushort4*)(sp + (size_t)r * K + (CHK) * 16 + cck * 4);     \
        }                                                                             \
    } while (0)

    #define STORE_SMEM(S) do {                                                        \
        _Pragma("unroll")                                                             \
        for (int j = 0; j < 8; j++) {                                                 \
            const int r = ((j & 1) << 6) + crow;                                      \
            *(ushort4*)&sm[S][j >> 1][r][cck * 4] = rb[j];                            \
        }                                                                             \
    } while (0)

    LOAD_REGS(0);
    STORE_SMEM(0);
    __syncthreads();

    const int tg2 = (lane & 3) * 2;
    const int gq  = lane >> 2;

    for (int i = 0; i < CH; i++) {
        const int s = i & 1;
        if (i + 1 < CH) LOAD_REGS(i + 1);

        uint32_t ah[4][4], al[4][4], bh[4][2], bl[4][2];
        #pragma unroll
        for (int mi = 0; mi < 4; mi++) {
            const int ra = wm * 64 + mi * 16 + gq;
            ah[mi][0] = *(const uint32_t*)&sm[s][0][ra][tg2];
            ah[mi][1] = *(const uint32_t*)&sm[s][0][ra + 8][tg2];
            ah[mi][2] = *(const uint32_t*)&sm[s][0][ra][tg2 + 8];
            ah[mi][3] = *(const uint32_t*)&sm[s][0][ra + 8][tg2 + 8];
            al[mi][0] = *(const uint32_t*)&sm[s][1][ra][tg2];
            al[mi][1] = *(const uint32_t*)&sm[s][1][ra + 8][tg2];
            al[mi][2] = *(const uint32_t*)&sm[s][1][ra][tg2 + 8];
            al[mi][3] = *(const uint32_t*)&sm[s][1][ra + 8][tg2 + 8];
        }
        #pragma unroll
        for (int nj = 0; nj < 4; nj++) {
            const int rbn = wn * 32 + nj * 8 + gq;
            bh[nj][0] = *(const uint32_t*)&sm[s][2][rbn][tg2];
            bh[nj][1] = *(const uint32_t*)&sm[s][2][rbn][tg2 + 8];
            bl[nj][0] = *(const uint32_t*)&sm[s][3][rbn][tg2];
            bl[nj][1] = *(const uint32_t*)&sm[s][3][rbn][tg2 + 8];
        }
        #pragma unroll
        for (int mi = 0; mi < 4; mi++)
            #pragma unroll
            for (int nj = 0; nj < 4; nj++) {
                mma16816(acc[mi][nj], ah[mi], bh[nj]);
                mma16816(acc[mi][nj], ah[mi], bl[nj]);
                mma16816(acc[mi][nj], al[mi], bh[nj]);
            }

        if (i + 1 < CH) STORE_SMEM(s ^ 1);
        __syncthreads();
    }

    #pragma unroll
    for (int mi = 0; mi < 4; mi++) {
        const int row0 = bm + wm * 64 + mi * 16 + gq;
        #pragma unroll
        for (int nj = 0; nj < 4; nj++) {
            const int col = bn + wn * 32 + nj * 8 + tg2;
            const size_t o0 = MODE ? map_tbc(row0, col)     : (size_t)row0 * N + col;
            const size_t o1 = MODE ? map_tbc(row0 + 8, col) : (size_t)(row0 + 8) * N + col;
            *(float2*)(C + o0) = make_float2(acc[mi][nj][0], acc[mi][nj][1]);
            *(float2*)(C + o1) = make_float2(acc[mi][nj][2], acc[mi][nj][3]);
        }
    }
}

// =================================================================================
// Depthwise causal conv (k=4) + bias + silu. (unchanged)
// =================================================================================
__global__ __launch_bounds__(256)
void conv_silu_kernel(const float* __restrict__ cw, const float* __restrict__ cb)
{
    const int idx = blockIdx.x * 256 + threadIdx.x;
    const int d = idx & (DINNER - 1);
    const int m = idx >> 11;
    const int t = m & (T_LEN - 1);
    const int b = m >> 11;

    const float4 w = *(const float4*)(cw + d * 4);
    float acc = cb[d];
    const size_t rowbase = (size_t)(b * T_LEN) * DPROJ + d;
    if (t >= 3) acc = fmaf(g_P[rowbase + (size_t)(t - 3) * DPROJ], w.x, acc);
    if (t >= 2) acc = fmaf(g_P[rowbase + (size_t)(t - 2) * DPROJ], w.y, acc);
    if (t >= 1) acc = fmaf(g_P[rowbase + (size_t)(t - 1) * DPROJ], w.z, acc);
    acc = fmaf(g_P[rowbase + (size_t)t * DPROJ], w.w, acc);
    acc = acc * (1.f / (1.f + __expf(-acc)));
    g_uc[idx] = acc;
}

// =================================================================================
// x_proj (unchanged)
// =================================================================================
__global__ __launch_bounds__(128)
void xproj_kernel(const float* __restrict__ W_x)
{
    __shared__ float swl[64 * 96];
    __shared__ float su[16][64];
    const int m0 = blockIdx.x * 16;
    const int tid = threadIdx.x;

    float acc[16];
    #pragma unroll
    for (int mi = 0; mi < 16; mi++) acc[mi] = 0.f;

    for (int kb = 0; kb < DINNER; kb += 64) {
        __syncthreads();
        #pragma unroll 4
        for (int i = tid; i < 64 * 96; i += 128) swl[i] = W_x[kb * 96 + i];
        #pragma unroll
        for (int i = tid; i < 16 * 64; i += 128) {
            const int mi = i >> 6, c = i & 63;
            su[mi][c] = g_uc[(size_t)(m0 + mi) * DINNER + kb + c];
        }
        __syncthreads();
        if (tid < 96) {
            #pragma unroll 2
            for (int r = 0; r < 64; r++) {
                const float w = swl[r * 96 + tid];
                #pragma unroll
                for (int mi = 0; mi < 16; mi++)
                    acc[mi] = fmaf(su[mi][r], w, acc[mi]);
            }
        }
    }
    if (tid < 96) {
        #pragma unroll
        for (int mi = 0; mi < 16; mi++)
            g_xdbl[(size_t)(m0 + mi) * NXP + tid] = acc[mi];
    }
}

// =================================================================================
// dt_proj + softplus (unchanged)
// =================================================================================
__global__ __launch_bounds__(128)
void dtproj_kernel(const float* __restrict__ W_dt, const float* __restrict__ b_dt)
{
    __shared__ float sw[64][128];
    __shared__ float sx[16][64];
    const int d0 = blockIdx.x * 128;
    const int m0 = blockIdx.y * 16;
    const int tid = threadIdx.x;

    #pragma unroll 4
    for (int i = tid; i < 64 * 128; i += 128) {
        const int r = i >> 7, dd = i & 127;
        sw[r][dd] = W_dt[(size_t)r * DINNER + d0 + dd];
    }
    #pragma unroll
    for (int i = tid; i < 16 * 64; i += 128) {
        const int mi = i >> 6, r = i & 63;
        sx[mi][r] = g_xdbl[(size_t)(m0 + mi) * NXP + r];
    }
    __syncthreads();

    float acc[16];
    const float bb = b_dt[d0 + tid];
    #pragma unroll
    for (int mi = 0; mi < 16; mi++) acc[mi] = bb;

    #pragma unroll 2
    for (int r = 0; r < 64; r++) {
        const float w = sw[r][tid];
        #pragma unroll
        for (int mi = 0; mi < 16; mi++)
            acc[mi] = fmaf(sx[mi][r], w, acc[mi]);
    }
    #pragma unroll
    for (int mi = 0; mi < 16; mi++) {
        const float z = acc[mi];
        const float sp = (z > 15.f) ? z : log1pf(__expf(z));
        g_delta[(size_t)(m0 + mi) * DINNER + d0 + tid] = sp;
    }
}

// =================================================================================
// Selective scan v2: 4-stage cp.async pipeline, 16 timesteps/stage.
// Block = 128 threads = 32 d-channels (4 lanes/d x 4 states). Grid (64, B).
// SMEM/stage: delta/uc/res [16][32] + BC [16][32]  -> 8KB; 4 stages = 32KB.
// =================================================================================
#define TB   16
#define NSTG 4

__global__ __launch_bounds__(128)
void scan_kernel(const float* __restrict__ A_log, const float* __restrict__ Dv)
{
    __shared__ __align__(16) float sdl[NSTG][TB][32];
    __shared__ __align__(16) float suu[NSTG][TB][32];
    __shared__ __align__(16) float srs[NSTG][TB][32];
    __shared__ __align__(16) float sbc[NSTG][TB][32];

    const int b = blockIdx.y;
    const int d0 = blockIdx.x * 32;
    const int tid = threadIdx.x;
    const int w = tid >> 5, lane = tid & 31;
    const int g = lane >> 2, q = lane & 3;
    const int dloc = w * 8 + g;
    const int d = d0 + dloc;
    const int nb = q * 4;

    const float A0 = -__expf(A_log[d * DSTATE + nb + 0]);
    const float A1 = -__expf(A_log[d * DSTATE + nb + 1]);
    const float A2 = -__expf(A_log[d * DSTATE + nb + 2]);
    const float A3 = -__expf(A_log[d * DSTATE + nb + 3]);
    const float Dd = Dv[d];

    // copy duty: thread -> (timestep within stage, 16B segment)
    const int t_ld = tid >> 3;        // 0..15
    const int seg  = (tid & 7) * 4;   // float offset 0,4,...,28

    const size_t mb = (size_t)b * T_LEN;   // global row base

    const uint32_t a_dl = smem_u32(&sdl[0][t_ld][seg]);
    const uint32_t a_uu = smem_u32(&suu[0][t_ld][seg]);
    const uint32_t a_rs = smem_u32(&srs[0][t_ld][seg]);
    const uint32_t a_bc = smem_u32(&sbc[0][t_ld][seg]);
    const uint32_t stg_bytes = TB * 32 * 4;   // 2048

    #define SCAN_ISSUE(S, Cc) do {                                                     \
        const size_t _m = mb + (size_t)(Cc) * TB + t_ld;                               \
        cp16(a_dl + (S) * stg_bytes, g_delta + _m * DINNER + d0 + seg);                \
        cp16(a_uu + (S) * stg_bytes, g_uc    + _m * DINNER + d0 + seg);                \
        cp16(a_rs + (S) * stg_bytes, g_P     + _m * DPROJ + DINNER + d0 + seg);        \
        cp16(a_bc + (S) * stg_bytes, g_xdbl  + _m * NXP + DTRANK + seg);               \
        CP_COMMIT();                                                                   \
    } while (0)

    #pragma unroll
    for (int p = 0; p < NSTG; p++) SCAN_ISSUE(p, p);

    float h0 = 0.f, h1 = 0.f, h2 = 0.f, h3 = 0.f;
    size_t ybase = mb * DINNER + d;
    constexpr int NCH = T_LEN / TB;   // 128

    for (int c = 0; c < NCH; c++) {
        const int S = c & (NSTG - 1);
        CP_WAIT3();
        __syncthreads();

        #pragma unroll
        for (int tt = 0; tt < TB; tt++) {
            const float dl = sdl[S][tt][dloc];
            const float uu = suu[S][tt][dloc];
            const float4 Bv = *(const float4*)&sbc[S][tt][nb];
            const float4 Cv = *(const float4*)&sbc[S][tt][16 + nb];

            const float du = dl * uu;
            h0 = fmaf(__expf(dl * A0), h0, du * Bv.x);
            h1 = fmaf(__expf(dl * A1), h1, du * Bv.y);
            h2 = fmaf(__expf(dl * A2), h2, du * Bv.z);
            h3 = fmaf(__expf(dl * A3), h3, du * Bv.w);

            float p = fmaf(h0, Cv.x, fmaf(h1, Cv.y, fmaf(h2, Cv.z, h3 * Cv.w)));
            p += __shfl_xor_sync(0xffffffffu, p, 1);
            p += __shfl_xor_sync(0xffffffffu, p, 2);

            if (q == 0) {
                const float resv = srs[S][tt][dloc];
                const float gate = resv * (1.f / (1.f + __expf(-resv)));
                g_y[ybase + (size_t)(c * TB + tt) * DINNER] = (p + uu * Dd) * gate;
            }
        }
        __syncthreads();
        if (c + NSTG < NCH) { SCAN_ISSUE(S, c + NSTG); }
        else                { CP_COMMIT(); }   // keep group count invariant
    }
}

// =================================================================================
// launch
// =================================================================================
extern "C" void kernel_launch(void* const* d_in, const int* in_sizes, int n_in,
                              void* d_out, int out_size)
{
    const float* x      = (const float*)d_in[0];
    const float* W_in   = (const float*)d_in[1];
    const float* conv_w = (const float*)d_in[2];
    const float* conv_b = (const float*)d_in[3];
    const float* W_x    = (const float*)d_in[4];
    const float* W_dt   = (const float*)d_in[5];
    const float* b_dt   = (const float*)d_in[6];
    const float* A_log  = (const float*)d_in[7];
    const float* Dv     = (const float*)d_in[8];
    const float* W_out  = (const float*)d_in[9];
    float* out = (float*)d_out;

    // --- in_proj ---
    split_x_kernel<<<(M_ROWS * DMODEL / 4) / 256, 256>>>(x);
    splitT_kernel<0><<<dim3(DPROJ / 32, DMODEL / 32), 256>>>(W_in);
    gemm_hmma<0><<<dim3(DPROJ / 128, M_ROWS / 128), 256>>>(nullptr);

    // --- mid pipeline ---
    conv_silu_kernel<<<(M_ROWS * DINNER) / 256, 256>>>(conv_w, conv_b);
    xproj_kernel<<<M_ROWS / 16, 128>>>(W_x);
    dtproj_kernel<<<dim3(DINNER / 128, M_ROWS / 16), 128>>>(W_dt, b_dt);
    scan_kernel<<<dim3(DINNER / 32, B_SZ), 128>>>(A_log, Dv);

    // --- out_proj ---
    split_y_kernel<<<(M_ROWS * DINNER / 4) / 256, 256>>>();
    splitT_kernel<1><<<dim3(DMODEL / 32, DINNER / 32), 256>>>(W_out);
    gemm_hmma<1><<<dim3(DMODEL / 128, M_ROWS / 128), 256>>>(out);
}

// round 9
// speedup vs baseline: 3.1975x; 1.0366x over previous
#include <cuda_runtime.h>
#include <cuda_bf16.h>
#include <math.h>
#include <stdint.h>

#define T_LEN   2048
#define B_SZ    4
#define DMODEL  1024
#define DINNER  2048
#define DSTATE  16
#define DTRANK  64
#define NXP     96
#define M_ROWS  (B_SZ*T_LEN)   // 8192
#define DPROJ   (2*DINNER)     // 4096

// ---------------- scratch (device globals; proven 323MB set) ----------
__device__ __align__(16) float g_P[(size_t)M_ROWS * DPROJ];
__device__ __align__(16) float g_uc[(size_t)M_ROWS * DINNER];
__device__ __align__(16) float g_xdbl[(size_t)M_ROWS * NXP];
__device__ __align__(16) float g_delta[(size_t)M_ROWS * DINNER];
__device__ __align__(16) float g_y[(size_t)M_ROWS * DINNER];

// ---- bf16 hi/lo operands ALIASED into scratch (lifetimes verified disjoint) ----
__device__ __forceinline__ __nv_bfloat16* A1H() { return (__nv_bfloat16*)g_delta; }
__device__ __forceinline__ __nv_bfloat16* A1L() { return (__nv_bfloat16*)g_delta + (size_t)M_ROWS * DMODEL; }
__device__ __forceinline__ __nv_bfloat16* W1H() { return (__nv_bfloat16*)g_uc; }
__device__ __forceinline__ __nv_bfloat16* W1L() { return (__nv_bfloat16*)g_uc + (size_t)DPROJ * DMODEL; }
__device__ __forceinline__ __nv_bfloat16* A2H() { return (__nv_bfloat16*)g_delta; }
__device__ __forceinline__ __nv_bfloat16* A2L() { return (__nv_bfloat16*)g_uc; }
__device__ __forceinline__ __nv_bfloat16* W2H() { return (__nv_bfloat16*)g_P; }
__device__ __forceinline__ __nv_bfloat16* W2L() { return (__nv_bfloat16*)g_P + (size_t)DMODEL * DINNER; }

// ---------------- helpers ----------------
__device__ __forceinline__ uint32_t smem_u32(const void* p) {
    uint32_t a;
    asm("{ .reg .u64 t; cvta.to.shared.u64 t, %1; cvt.u32.u64 %0, t; }" : "=r"(a) : "l"(p));
    return a;
}
__device__ __forceinline__ void cp16(uint32_t d, const void* s) {
    asm volatile("cp.async.cg.shared.global [%0], [%1], 16;" :: "r"(d), "l"(s));
}
#define CP_COMMIT() asm volatile("cp.async.commit_group;" ::: "memory")
#define CP_WAIT0()  asm volatile("cp.async.wait_group 0;"  ::: "memory")
#define CP_WAIT1()  asm volatile("cp.async.wait_group 1;"  ::: "memory")
#define CP_WAIT3()  asm volatile("cp.async.wait_group 3;"  ::: "memory")

__device__ __forceinline__ void ldsm4(uint32_t* r, uint32_t a) {
    asm volatile("ldmatrix.sync.aligned.m8n8.x4.shared.b16 {%0,%1,%2,%3}, [%4];"
        : "=r"(r[0]), "=r"(r[1]), "=r"(r[2]), "=r"(r[3]) : "r"(a));
}
__device__ __forceinline__ void mma16816(float* c, const uint32_t* a, const uint32_t* b) {
    asm volatile("mma.sync.aligned.m16n8k16.row.col.f32.bf16.bf16.f32 "
        "{%0,%1,%2,%3}, {%4,%5,%6,%7}, {%8,%9}, {%0,%1,%2,%3};"
        : "+f"(c[0]), "+f"(c[1]), "+f"(c[2]), "+f"(c[3])
        : "r"(a[0]), "r"(a[1]), "r"(a[2]), "r"(a[3]), "r"(b[0]), "r"(b[1]));
}

__device__ __forceinline__ size_t map_tbc(int m, int col) {
    return (size_t)(m & (T_LEN - 1)) * (B_SZ * DMODEL) + (size_t)(m >> 11) * DMODEL + col;
}

// =================================================================================
// Split kernels (unchanged from R8)
// =================================================================================
__device__ __forceinline__ void split_store4(float4 v, __nv_bfloat16* hp, __nv_bfloat16* lp) {
    __nv_bfloat16 h0 = __float2bfloat16_rn(v.x), h1 = __float2bfloat16_rn(v.y);
    __nv_bfloat16 h2 = __float2bfloat16_rn(v.z), h3 = __float2bfloat16_rn(v.w);
    __nv_bfloat16 l0 = __float2bfloat16_rn(v.x - __bfloat162float(h0));
    __nv_bfloat16 l1 = __float2bfloat16_rn(v.y - __bfloat162float(h1));
    __nv_bfloat16 l2 = __float2bfloat16_rn(v.z - __bfloat162float(h2));
    __nv_bfloat16 l3 = __float2bfloat16_rn(v.w - __bfloat162float(h3));
    *(ushort4*)hp = make_ushort4(__bfloat16_as_ushort(h0), __bfloat16_as_ushort(h1),
                                 __bfloat16_as_ushort(h2), __bfloat16_as_ushort(h3));
    *(ushort4*)lp = make_ushort4(__bfloat16_as_ushort(l0), __bfloat16_as_ushort(l1),
                                 __bfloat16_as_ushort(l2), __bfloat16_as_ushort(l3));
}

__global__ __launch_bounds__(256)
void split_x_kernel(const float* __restrict__ x)
{
    const int q = blockIdx.x * 256 + threadIdx.x;
    const int c = (q & 255) * 4;
    const int m = q >> 8;
    const int t = m & (T_LEN - 1), b = m >> 11;
    float4 v = *(const float4*)(x + (size_t)t * (B_SZ * DMODEL) + b * DMODEL + c);
    const size_t o = (size_t)m * DMODEL + c;
    split_store4(v, A1H() + o, A1L() + o);
}

__global__ __launch_bounds__(256)
void split_y_kernel()
{
    const int q = blockIdx.x * 256 + threadIdx.x;
    const size_t o = (size_t)q * 4;
    float4 v = *(const float4*)(g_y + o);
    split_store4(v, A2H() + o, A2L() + o);
}

template<int WHICH>
__global__ __launch_bounds__(256)
void splitT_kernel(const float* __restrict__ W)
{
    constexpr int K = WHICH ? DINNER : DMODEL;
    constexpr int N = WHICH ? DMODEL : DPROJ;
    __shared__ float tile[32][33];
    const int n0 = blockIdx.x * 32, k0 = blockIdx.y * 32;
    const int tid = threadIdx.x;
    #pragma unroll
    for (int p = 0; p < 4; p++) {
        const int idx = tid + p * 256;
        const int kr = idx >> 5, nc = idx & 31;
        tile[kr][nc] = W[(size_t)(k0 + kr) * N + n0 + nc];
    }
    __syncthreads();
    const int nr = tid >> 3;
    const int kq = (tid & 7) * 4;
    float4 v = make_float4(tile[kq + 0][nr], tile[kq + 1][nr], tile[kq + 2][nr], tile[kq + 3][nr]);
    const size_t o = (size_t)(n0 + nr) * K + (k0 + kq);
    __nv_bfloat16* Th = WHICH ? W2H() : W1H();
    __nv_bfloat16* Tl = WHICH ? W2L() : W1L();
    split_store4(v, Th + o, Tl + o);
}

// =================================================================================
// bf16 hi/lo split GEMM v2: ldmatrix fragments + cp.async 2-buffer pipeline.
// CTA 128x128, K-chunk 16, 8 warps of 64x32.
// SMEM: [stage 2][mat 4][128 rows x 48B]  (32B data + 16B pad; 48KB static total).
// Row stride 48B => ldmatrix row addresses conflict-free; cp16 dst 16B-aligned.
// =================================================================================
#define GROW 48                       // bytes per smem row
#define MATB (128 * GROW)             // 6144 bytes per matrix
#define STGB (4 * MATB)               // 24576 bytes per stage

template<int MODE>
__global__ __launch_bounds__(256)
void gemm_hmma(float* __restrict__ Cparam)
{
    constexpr int N  = MODE ? DMODEL : DPROJ;
    constexpr int K  = MODE ? DINNER : DMODEL;
    constexpr int CH = K / 16;

    __shared__ __align__(16) char smb[2 * STGB];   // 48KB static

    const int tid  = threadIdx.x;
    const int lane = tid & 31, wid = tid >> 5;
    const int wm = wid & 1;
    const int wn = wid >> 1;
    const int bm = blockIdx.y * 128;
    const int bn = blockIdx.x * 128;

    const __nv_bfloat16* srcs[4] = {
        (MODE ? A2H() : A1H()) + (size_t)bm * K,
        (MODE ? A2L() : A1L()) + (size_t)bm * K,
        (MODE ? W2H() : W1H()) + (size_t)bn * K,
        (MODE ? W2L() : W1L()) + (size_t)bn * K
    };
    float* C = MODE ? Cparam : g_P;

    const uint32_t sb = smem_u32(smb);

    // copy duty: 4 cp16 per thread per stage.
    // mat = tid>>6; per mat 64 threads cover 128 rows x 2 (16B chunks).
    const int cmat = tid >> 6;
    const int cidx = tid & 63;
    const __nv_bfloat16* csrc = srcs[cmat];

    #define ISSUE(S, CHK) do {                                                   \
        const uint32_t dbase = sb + (uint32_t)(S) * STGB + cmat * MATB;          \
        _Pragma("unroll")                                                        \
        for (int jj = 0; jj < 4; jj++) {                                         \
            const int lin = jj * 64 + cidx;                                      \
            const int r = lin >> 1, cc = lin & 1;                                \
            cp16(dbase + r * GROW + cc * 16,                                     \
                 csrc + (size_t)r * K + (CHK) * 16 + cc * 8);                    \
        }                                                                        \
        CP_COMMIT();                                                             \
    } while (0)

    float acc[4][4][4];
    #pragma unroll
    for (int mi = 0; mi < 4; mi++)
        #pragma unroll
        for (int nj = 0; nj < 4; nj++)
            #pragma unroll
            for (int e = 0; e < 4; e++) acc[mi][nj][e] = 0.f;

    ISSUE(0, 0);
    if (CH > 1) ISSUE(1, 1);

    // ldmatrix lane addressing (within a 16x16 tile at row base R of a matrix):
    //   addr = matbase + (R + (lane&15))*GROW + (lane>>4)*16
    const int lrow = lane & 15;
    const int lcol = (lane >> 4) * 16;

    for (int i = 0; i < CH; i++) {
        const int s = i & 1;
        if (i + 1 < CH) { CP_WAIT1(); } else { CP_WAIT0(); }
        __syncthreads();

        const uint32_t Ah = sb + s * STGB;
        const uint32_t Al = Ah + MATB;
        const uint32_t Bh = Ah + 2 * MATB;
        const uint32_t Bl = Ah + 3 * MATB;

        uint32_t ah[4][4], al[4][4], bh[4][2], bl[4][2];
        #pragma unroll
        for (int mi = 0; mi < 4; mi++) {
            const uint32_t off = (uint32_t)(wm * 64 + mi * 16 + lrow) * GROW + lcol;
            ldsm4(ah[mi], Ah + off);
            ldsm4(al[mi], Al + off);
        }
        #pragma unroll
        for (int p = 0; p < 2; p++) {   // nj pairs (2p, 2p+1)
            const uint32_t off = (uint32_t)(wn * 32 + p * 16 + lrow) * GROW + lcol;
            uint32_t r4[4];
            ldsm4(r4, Bh + off);
            bh[2 * p][0] = r4[0]; bh[2 * p + 1][0] = r4[1];
            bh[2 * p][1] = r4[2]; bh[2 * p + 1][1] = r4[3];
            ldsm4(r4, Bl + off);
            bl[2 * p][0] = r4[0]; bl[2 * p + 1][0] = r4[1];
            bl[2 * p][1] = r4[2]; bl[2 * p + 1][1] = r4[3];
        }

        #pragma unroll
        for (int mi = 0; mi < 4; mi++)
            #pragma unroll
            for (int nj = 0; nj < 4; nj++) {
                mma16816(acc[mi][nj], ah[mi], bh[nj]);
                mma16816(acc[mi][nj], ah[mi], bl[nj]);
                mma16816(acc[mi][nj], al[mi], bh[nj]);
            }

        __syncthreads();
        if (i + 2 < CH) ISSUE(s, i + 2);
    }

    const int tg2 = (lane & 3) * 2;
    const int gq  = lane >> 2;
    #pragma unroll
    for (int mi = 0; mi < 4; mi++) {
        const int row0 = bm + wm * 64 + mi * 16 + gq;
        #pragma unroll
        for (int nj = 0; nj < 4; nj++) {
            const int col = bn + wn * 32 + nj * 8 + tg2;
            const size_t o0 = MODE ? map_tbc(row0, col)     : (size_t)row0 * N + col;
            const size_t o1 = MODE ? map_tbc(row0 + 8, col) : (size_t)(row0 + 8) * N + col;
            *(float2*)(C + o0) = make_float2(acc[mi][nj][0], acc[mi][nj][1]);
            *(float2*)(C + o1) = make_float2(acc[mi][nj][2], acc[mi][nj][3]);
        }
    }
}

// =================================================================================
// Depthwise causal conv (k=4) + bias + silu. (unchanged)
// =================================================================================
__global__ __launch_bounds__(256)
void conv_silu_kernel(const float* __restrict__ cw, const float* __restrict__ cb)
{
    const int idx = blockIdx.x * 256 + threadIdx.x;
    const int d = idx & (DINNER - 1);
    const int m = idx >> 11;
    const int t = m & (T_LEN - 1);
    const int b = m >> 11;

    const float4 w = *(const float4*)(cw + d * 4);
    float acc = cb[d];
    const size_t rowbase = (size_t)(b * T_LEN) * DPROJ + d;
    if (t >= 3) acc = fmaf(g_P[rowbase + (size_t)(t - 3) * DPROJ], w.x, acc);
    if (t >= 2) acc = fmaf(g_P[rowbase + (size_t)(t - 2) * DPROJ], w.y, acc);
    if (t >= 1) acc = fmaf(g_P[rowbase + (size_t)(t - 1) * DPROJ], w.z, acc);
    acc = fmaf(g_P[rowbase + (size_t)t * DPROJ], w.w, acc);
    acc = acc * (1.f / (1.f + __expf(-acc)));
    g_uc[idx] = acc;
}

// =================================================================================
// x_proj (unchanged)
// =================================================================================
__global__ __launch_bounds__(128)
void xproj_kernel(const float* __restrict__ W_x)
{
    __shared__ float swl[64 * 96];
    __shared__ float su[16][64];
    const int m0 = blockIdx.x * 16;
    const int tid = threadIdx.x;

    float acc[16];
    #pragma unroll
    for (int mi = 0; mi < 16; mi++) acc[mi] = 0.f;

    for (int kb = 0; kb < DINNER; kb += 64) {
        __syncthreads();
        #pragma unroll 4
        for (int i = tid; i < 64 * 96; i += 128) swl[i] = W_x[kb * 96 + i];
        #pragma unroll
        for (int i = tid; i < 16 * 64; i += 128) {
            const int mi = i >> 6, c = i & 63;
            su[mi][c] = g_uc[(size_t)(m0 + mi) * DINNER + kb + c];
        }
        __syncthreads();
        if (tid < 96) {
            #pragma unroll 2
            for (int r = 0; r < 64; r++) {
                const float w = swl[r * 96 + tid];
                #pragma unroll
                for (int mi = 0; mi < 16; mi++)
                    acc[mi] = fmaf(su[mi][r], w, acc[mi]);
            }
        }
    }
    if (tid < 96) {
        #pragma unroll
        for (int mi = 0; mi < 16; mi++)
            g_xdbl[(size_t)(m0 + mi) * NXP + tid] = acc[mi];
    }
}

// =================================================================================
// dt_proj + softplus (unchanged)
// =================================================================================
__global__ __launch_bounds__(128)
void dtproj_kernel(const float* __restrict__ W_dt, const float* __restrict__ b_dt)
{
    __shared__ float sw[64][128];
    __shared__ float sx[16][64];
    const int d0 = blockIdx.x * 128;
    const int m0 = blockIdx.y * 16;
    const int tid = threadIdx.x;

    #pragma unroll 4
    for (int i = tid; i < 64 * 128; i += 128) {
        const int r = i >> 7, dd = i & 127;
        sw[r][dd] = W_dt[(size_t)r * DINNER + d0 + dd];
    }
    #pragma unroll
    for (int i = tid; i < 16 * 64; i += 128) {
        const int mi = i >> 6, r = i & 63;
        sx[mi][r] = g_xdbl[(size_t)(m0 + mi) * NXP + r];
    }
    __syncthreads();

    float acc[16];
    const float bb = b_dt[d0 + tid];
    #pragma unroll
    for (int mi = 0; mi < 16; mi++) acc[mi] = bb;

    #pragma unroll 2
    for (int r = 0; r < 64; r++) {
        const float w = sw[r][tid];
        #pragma unroll
        for (int mi = 0; mi < 16; mi++)
            acc[mi] = fmaf(sx[mi][r], w, acc[mi]);
    }
    #pragma unroll
    for (int mi = 0; mi < 16; mi++) {
        const float z = acc[mi];
        const float sp = (z > 15.f) ? z : log1pf(__expf(z));
        g_delta[(size_t)(m0 + mi) * DINNER + d0 + tid] = sp;
    }
}

// =================================================================================
// Selective scan (unchanged R8 pipelined version)
// =================================================================================
#define TB   16
#define NSTG 4

__global__ __launch_bounds__(128)
void scan_kernel(const float* __restrict__ A_log, const float* __restrict__ Dv)
{
    __shared__ __align__(16) float sdl[NSTG][TB][32];
    __shared__ __align__(16) float suu[NSTG][TB][32];
    __shared__ __align__(16) float srs[NSTG][TB][32];
    __shared__ __align__(16) float sbc[NSTG][TB][32];

    const int b = blockIdx.y;
    const int d0 = blockIdx.x * 32;
    const int tid = threadIdx.x;
    const int w = tid >> 5, lane = tid & 31;
    const int g = lane >> 2, q = lane & 3;
    const int dloc = w * 8 + g;
    const int d = d0 + dloc;
    const int nb = q * 4;

    const float A0 = -__expf(A_log[d * DSTATE + nb + 0]);
    const float A1 = -__expf(A_log[d * DSTATE + nb + 1]);
    const float A2 = -__expf(A_log[d * DSTATE + nb + 2]);
    const float A3 = -__expf(A_log[d * DSTATE + nb + 3]);
    const float Dd = Dv[d];

    const int t_ld = tid >> 3;
    const int seg  = (tid & 7) * 4;

    const size_t mb = (size_t)b * T_LEN;

    const uint32_t a_dl = smem_u32(&sdl[0][t_ld][seg]);
    const uint32_t a_uu = smem_u32(&suu[0][t_ld][seg]);
    const uint32_t a_rs = smem_u32(&srs[0][t_ld][seg]);
    const uint32_t a_bc = smem_u32(&sbc[0][t_ld][seg]);
    const uint32_t stg_bytes = TB * 32 * 4;

    #define SCAN_ISSUE(S, Cc) do {                                                     \
        const size_t _m = mb + (size_t)(Cc) * TB + t_ld;                               \
        cp16(a_dl + (S) * stg_bytes, g_delta + _m * DINNER + d0 + seg);                \
        cp16(a_uu + (S) * stg_bytes, g_uc    + _m * DINNER + d0 + seg);                \
        cp16(a_rs + (S) * stg_bytes, g_P     + _m * DPROJ + DINNER + d0 + seg);        \
        cp16(a_bc + (S) * stg_bytes, g_xdbl  + _m * NXP + DTRANK + seg);               \
        CP_COMMIT();                                                                   \
    } while (0)

    #pragma unroll
    for (int p = 0; p < NSTG; p++) SCAN_ISSUE(p, p);

    float h0 = 0.f, h1 = 0.f, h2 = 0.f, h3 = 0.f;
    size_t ybase = mb * DINNER + d;
    constexpr int NCH = T_LEN / TB;

    for (int c = 0; c < NCH; c++) {
        const int S = c & (NSTG - 1);
        CP_WAIT3();
        __syncthreads();

        #pragma unroll
        for (int tt = 0; tt < TB; tt++) {
            const float dl = sdl[S][tt][dloc];
            const float uu = suu[S][tt][dloc];
            const float4 Bv = *(const float4*)&sbc[S][tt][nb];
            const float4 Cv = *(const float4*)&sbc[S][tt][16 + nb];

            const float du = dl * uu;
            h0 = fmaf(__expf(dl * A0), h0, du * Bv.x);
            h1 = fmaf(__expf(dl * A1), h1, du * Bv.y);
            h2 = fmaf(__expf(dl * A2), h2, du * Bv.z);
            h3 = fmaf(__expf(dl * A3), h3, du * Bv.w);

            float p = fmaf(h0, Cv.x, fmaf(h1, Cv.y, fmaf(h2, Cv.z, h3 * Cv.w)));
            p += __shfl_xor_sync(0xffffffffu, p, 1);
            p += __shfl_xor_sync(0xffffffffu, p, 2);

            if (q == 0) {
                const float resv = srs[S][tt][dloc];
                const float gate = resv * (1.f / (1.f + __expf(-resv)));
                g_y[ybase + (size_t)(c * TB + tt) * DINNER] = (p + uu * Dd) * gate;
            }
        }
        __syncthreads();
        if (c + NSTG < NCH) { SCAN_ISSUE(S, c + NSTG); }
        else                { CP_COMMIT(); }
    }
}

// =================================================================================
// launch
// =================================================================================
extern "C" void kernel_launch(void* const* d_in, const int* in_sizes, int n_in,
                              void* d_out, int out_size)
{
    const float* x      = (const float*)d_in[0];
    const float* W_in   = (const float*)d_in[1];
    const float* conv_w = (const float*)d_in[2];
    const float* conv_b = (const float*)d_in[3];
    const float* W_x    = (const float*)d_in[4];
    const float* W_dt   = (const float*)d_in[5];
    const float* b_dt   = (const float*)d_in[6];
    const float* A_log  = (const float*)d_in[7];
    const float* Dv     = (const float*)d_in[8];
    const float* W_out  = (const float*)d_in[9];
    float* out = (float*)d_out;

    // --- in_proj ---
    split_x_kernel<<<(M_ROWS * DMODEL / 4) / 256, 256>>>(x);
    splitT_kernel<0><<<dim3(DPROJ / 32, DMODEL / 32), 256>>>(W_in);
    gemm_hmma<0><<<dim3(DPROJ / 128, M_ROWS / 128), 256>>>(nullptr);

    // --- mid pipeline ---
    conv_silu_kernel<<<(M_ROWS * DINNER) / 256, 256>>>(conv_w, conv_b);
    xproj_kernel<<<M_ROWS / 16, 128>>>(W_x);
    dtproj_kernel<<<dim3(DINNER / 128, M_ROWS / 16), 128>>>(W_dt, b_dt);
    scan_kernel<<<dim3(DINNER / 32, B_SZ), 128>>>(A_log, Dv);

    // --- out_proj ---
    split_y_kernel<<<(M_ROWS * DINNER / 4) / 256, 256>>>();
    splitT_kernel<1><<<dim3(DMODEL / 32, DINNER / 32), 256>>>(W_out);
    gemm_hmma<1><<<dim3(DMODEL / 128, M_ROWS / 128), 256>>>(out);
}

// round 10
// speedup vs baseline: 3.3467x; 1.0467x over previous
#include <cuda_runtime.h>
#include <cuda_bf16.h>
#include <math.h>
#include <stdint.h>

#define T_LEN   2048
#define B_SZ    4
#define DMODEL  1024
#define DINNER  2048
#define DSTATE  16
#define DTRANK  64
#define NXP     96
#define M_ROWS  (B_SZ*T_LEN)   // 8192
#define DPROJ   (2*DINNER)     // 4096

// ---------------- scratch (device globals; proven 323MB set) ----------
__device__ __align__(16) float g_P[(size_t)M_ROWS * DPROJ];     // in_proj out; later u-half holds A2 hi/lo
__device__ __align__(16) float g_uc[(size_t)M_ROWS * DINNER];
__device__ __align__(16) float g_xdbl[(size_t)M_ROWS * NXP];
__device__ __align__(16) float g_delta[(size_t)M_ROWS * DINNER];
__device__ __align__(16) float g_y[(size_t)M_ROWS * DINNER];    // now backs W2 hi/lo only

// ---- bf16 hi/lo operands ALIASED into scratch (lifetimes verified disjoint) ----
// A1 (split of x):    g_delta until dtproj writes it
// W1 (split W_in^T):  g_uc    until conv writes it
// A2 (split of y):    interleaved in g_P u-halves (row m: hi @ +0..4KB, lo @ +4..8KB), written by scan
// W2 (split W_out^T): g_y (free all run)
__device__ __forceinline__ __nv_bfloat16* A1H() { return (__nv_bfloat16*)g_delta; }
__device__ __forceinline__ __nv_bfloat16* A1L() { return (__nv_bfloat16*)g_delta + (size_t)M_ROWS * DMODEL; }
__device__ __forceinline__ __nv_bfloat16* W1H() { return (__nv_bfloat16*)g_uc; }
__device__ __forceinline__ __nv_bfloat16* W1L() { return (__nv_bfloat16*)g_uc + (size_t)DPROJ * DMODEL; }
__device__ __forceinline__ __nv_bfloat16* W2H() { return (__nv_bfloat16*)g_y; }
__device__ __forceinline__ __nv_bfloat16* W2L() { return (__nv_bfloat16*)g_y + (size_t)DMODEL * DINNER; }

// ---------------- helpers ----------------
__device__ __forceinline__ uint32_t smem_u32(const void* p) {
    uint32_t a;
    asm("{ .reg .u64 t; cvta.to.shared.u64 t, %1; cvt.u32.u64 %0, t; }" : "=r"(a) : "l"(p));
    return a;
}
__device__ __forceinline__ void cp16(uint32_t d, const void* s) {
    asm volatile("cp.async.cg.shared.global [%0], [%1], 16;" :: "r"(d), "l"(s));
}
#define CP_COMMIT() asm volatile("cp.async.commit_group;" ::: "memory")
#define CP_WAIT0()  asm volatile("cp.async.wait_group 0;"  ::: "memory")
#define CP_WAIT1()  asm volatile("cp.async.wait_group 1;"  ::: "memory")
#define CP_WAIT5()  asm volatile("cp.async.wait_group 5;"  ::: "memory")

__device__ __forceinline__ void ldsm4(uint32_t* r, uint32_t a) {
    asm volatile("ldmatrix.sync.aligned.m8n8.x4.shared.b16 {%0,%1,%2,%3}, [%4];"
        : "=r"(r[0]), "=r"(r[1]), "=r"(r[2]), "=r"(r[3]) : "r"(a));
}
__device__ __forceinline__ void mma16816(float* c, const uint32_t* a, const uint32_t* b) {
    asm volatile("mma.sync.aligned.m16n8k16.row.col.f32.bf16.bf16.f32 "
        "{%0,%1,%2,%3}, {%4,%5,%6,%7}, {%8,%9}, {%0,%1,%2,%3};"
        : "+f"(c[0]), "+f"(c[1]), "+f"(c[2]), "+f"(c[3])
        : "r"(a[0]), "r"(a[1]), "r"(a[2]), "r"(a[3]), "r"(b[0]), "r"(b[1]));
}

__device__ __forceinline__ size_t map_tbc(int m, int col) {
    return (size_t)(m & (T_LEN - 1)) * (B_SZ * DMODEL) + (size_t)(m >> 11) * DMODEL + col;
}

// =================================================================================
// Split kernels
// =================================================================================
__device__ __forceinline__ void split_store4(float4 v, __nv_bfloat16* hp, __nv_bfloat16* lp) {
    __nv_bfloat16 h0 = __float2bfloat16_rn(v.x), h1 = __float2bfloat16_rn(v.y);
    __nv_bfloat16 h2 = __float2bfloat16_rn(v.z), h3 = __float2bfloat16_rn(v.w);
    __nv_bfloat16 l0 = __float2bfloat16_rn(v.x - __bfloat162float(h0));
    __nv_bfloat16 l1 = __float2bfloat16_rn(v.y - __bfloat162float(h1));
    __nv_bfloat16 l2 = __float2bfloat16_rn(v.z - __bfloat162float(h2));
    __nv_bfloat16 l3 = __float2bfloat16_rn(v.w - __bfloat162float(h3));
    *(ushort4*)hp = make_ushort4(__bfloat16_as_ushort(h0), __bfloat16_as_ushort(h1),
                                 __bfloat16_as_ushort(h2), __bfloat16_as_ushort(h3));
    *(ushort4*)lp = make_ushort4(__bfloat16_as_ushort(l0), __bfloat16_as_ushort(l1),
                                 __bfloat16_as_ushort(l2), __bfloat16_as_ushort(l3));
}

__global__ __launch_bounds__(256)
void split_x_kernel(const float* __restrict__ x)
{
    const int q = blockIdx.x * 256 + threadIdx.x;
    const int c = (q & 255) * 4;
    const int m = q >> 8;
    const int t = m & (T_LEN - 1), b = m >> 11;
    float4 v = *(const float4*)(x + (size_t)t * (B_SZ * DMODEL) + b * DMODEL + c);
    const size_t o = (size_t)m * DMODEL + c;
    split_store4(v, A1H() + o, A1L() + o);
}

template<int WHICH>
__global__ __launch_bounds__(256)
void splitT_kernel(const float* __restrict__ W)
{
    constexpr int K = WHICH ? DINNER : DMODEL;
    constexpr int N = WHICH ? DMODEL : DPROJ;
    __shared__ float tile[32][33];
    const int n0 = blockIdx.x * 32, k0 = blockIdx.y * 32;
    const int tid = threadIdx.x;
    #pragma unroll
    for (int p = 0; p < 4; p++) {
        const int idx = tid + p * 256;
        const int kr = idx >> 5, nc = idx & 31;
        tile[kr][nc] = W[(size_t)(k0 + kr) * N + n0 + nc];
    }
    __syncthreads();
    const int nr = tid >> 3;
    const int kq = (tid & 7) * 4;
    float4 v = make_float4(tile[kq + 0][nr], tile[kq + 1][nr], tile[kq + 2][nr], tile[kq + 3][nr]);
    const size_t o = (size_t)(n0 + nr) * K + (k0 + kq);
    __nv_bfloat16* Th = WHICH ? W2H() : W1H();
    __nv_bfloat16* Tl = WHICH ? W2L() : W1L();
    split_store4(v, Th + o, Tl + o);
}

// =================================================================================
// bf16 hi/lo split GEMM (proven R9 structure) with per-matrix row strides.
// MODE 0: g_P = A1 @ W1  (N=4096, K=1024); A row stride = K
// MODE 1: out = A2 @ W2  (N=1024, K=2048); A2 interleaved in g_P u-halves,
//         row stride = 2*DPROJ bf16, lo at +DINNER. Output through map_tbc.
// =================================================================================
#define GROW 48
#define MATB (128 * GROW)
#define STGB (4 * MATB)

template<int MODE>
__global__ __launch_bounds__(256)
void gemm_hmma(float* __restrict__ Cparam)
{
    constexpr int N  = MODE ? DMODEL : DPROJ;
    constexpr int K  = MODE ? DINNER : DMODEL;
    constexpr int CH = K / 16;

    __shared__ __align__(16) char smb[2 * STGB];   // 48KB static

    const int tid  = threadIdx.x;
    const int lane = tid & 31, wid = tid >> 5;
    const int wm = wid & 1;
    const int wn = wid >> 1;
    const int bm = blockIdx.y * 128;
    const int bn = blockIdx.x * 128;

    const __nv_bfloat16* srcs[4];
    size_t strides[4];
    if (MODE == 0) {
        srcs[0] = A1H() + (size_t)bm * K;
        srcs[1] = A1L() + (size_t)bm * K;
        strides[0] = strides[1] = K;
    } else {
        srcs[0] = (const __nv_bfloat16*)g_P + (size_t)bm * (2 * DPROJ);
        srcs[1] = srcs[0] + DINNER;
        strides[0] = strides[1] = 2 * DPROJ;
    }
    srcs[2] = (MODE ? W2H() : W1H()) + (size_t)bn * K;
    srcs[3] = (MODE ? W2L() : W1L()) + (size_t)bn * K;
    strides[2] = strides[3] = K;

    float* C = MODE ? Cparam : g_P;
    const uint32_t sb = smem_u32(smb);

    const int cmat = tid >> 6;
    const int cidx = tid & 63;
    const __nv_bfloat16* csrc = srcs[cmat];
    const size_t cstr = strides[cmat];

    #define ISSUE(S, CHK) do {                                                   \
        const uint32_t dbase = sb + (uint32_t)(S) * STGB + cmat * MATB;          \
        _Pragma("unroll")                                                        \
        for (int jj = 0; jj < 4; jj++) {                                         \
            const int lin = jj * 64 + cidx;                                      \
            const int r = lin >> 1, cc = lin & 1;                                \
            cp16(dbase + r * GROW + cc * 16,                                     \
                 csrc + (size_t)r * cstr + (CHK) * 16 + cc * 8);                 \
        }                                                                        \
        CP_COMMIT();                                                             \
    } while (0)

    float acc[4][4][4];
    #pragma unroll
    for (int mi = 0; mi < 4; mi++)
        #pragma unroll
        for (int nj = 0; nj < 4; nj++)
            #pragma unroll
            for (int e = 0; e < 4; e++) acc[mi][nj][e] = 0.f;

    ISSUE(0, 0);
    if (CH > 1) ISSUE(1, 1);

    const int lrow = lane & 15;
    const int lcol = (lane >> 4) * 16;

    for (int i = 0; i < CH; i++) {
        const int s = i & 1;
        if (i + 1 < CH) { CP_WAIT1(); } else { CP_WAIT0(); }
        __syncthreads();

        const uint32_t Ah = sb + s * STGB;
        const uint32_t Al = Ah + MATB;
        const uint32_t Bh = Ah + 2 * MATB;
        const uint32_t Bl = Ah + 3 * MATB;

        uint32_t ah[4][4], al[4][4], bh[4][2], bl[4][2];
        #pragma unroll
        for (int mi = 0; mi < 4; mi++) {
            const uint32_t off = (uint32_t)(wm * 64 + mi * 16 + lrow) * GROW + lcol;
            ldsm4(ah[mi], Ah + off);
            ldsm4(al[mi], Al + off);
        }
        #pragma unroll
        for (int p = 0; p < 2; p++) {
            const uint32_t off = (uint32_t)(wn * 32 + p * 16 + lrow) * GROW + lcol;
            uint32_t r4[4];
            ldsm4(r4, Bh + off);
            bh[2 * p][0] = r4[0]; bh[2 * p + 1][0] = r4[1];
            bh[2 * p][1] = r4[2]; bh[2 * p + 1][1] = r4[3];
            ldsm4(r4, Bl + off);
            bl[2 * p][0] = r4[0]; bl[2 * p + 1][0] = r4[1];
            bl[2 * p][1] = r4[2]; bl[2 * p + 1][1] = r4[3];
        }

        #pragma unroll
        for (int mi = 0; mi < 4; mi++)
            #pragma unroll
            for (int nj = 0; nj < 4; nj++) {
                mma16816(acc[mi][nj], ah[mi], bh[nj]);
                mma16816(acc[mi][nj], ah[mi], bl[nj]);
                mma16816(acc[mi][nj], al[mi], bh[nj]);
            }

        __syncthreads();
        if (i + 2 < CH) ISSUE(s, i + 2);
    }

    const int tg2 = (lane & 3) * 2;
    const int gq  = lane >> 2;
    #pragma unroll
    for (int mi = 0; mi < 4; mi++) {
        const int row0 = bm + wm * 64 + mi * 16 + gq;
        #pragma unroll
        for (int nj = 0; nj < 4; nj++) {
            const int col = bn + wn * 32 + nj * 8 + tg2;
            const size_t o0 = MODE ? map_tbc(row0, col)     : (size_t)row0 * N + col;
            const size_t o1 = MODE ? map_tbc(row0 + 8, col) : (size_t)(row0 + 8) * N + col;
            *(float2*)(C + o0) = make_float2(acc[mi][nj][0], acc[mi][nj][1]);
            *(float2*)(C + o1) = make_float2(acc[mi][nj][2], acc[mi][nj][3]);
        }
    }
}

// =================================================================================
// Depthwise causal conv (k=4) + bias + silu, v2:
// 4 timesteps x float4-of-d per thread; 7 vectorized loads -> 16 outputs.
// =================================================================================
__global__ __launch_bounds__(256)
void conv_silu_kernel(const float* __restrict__ cw, const float* __restrict__ cb)
{
    const int q = blockIdx.x * 256 + threadIdx.x;   // 1M threads total
    const int d  = (q & 511) << 2;                  // 0..2044 step 4
    const int r  = q >> 9;
    const int t0 = (r & 511) << 2;                  // 0..2044 step 4
    const int b  = r >> 9;

    float4 w[4];
    #pragma unroll
    for (int i = 0; i < 4; i++) w[i] = *(const float4*)(cw + (d + i) * 4);
    const float4 cbv = *(const float4*)(cb + d);

    float4 in[7];
    #pragma unroll
    for (int j = 0; j < 7; j++) {
        const int t = t0 + j - 3;
        in[j] = (t >= 0)
            ? *(const float4*)(g_P + (size_t)(b * T_LEN + t) * DPROJ + d)
            : make_float4(0.f, 0.f, 0.f, 0.f);
    }

    #pragma unroll
    for (int j = 0; j < 4; j++) {
        float4 o;
        o.x = cbv.x + w[0].x*in[j].x + w[0].y*in[j+1].x + w[0].z*in[j+2].x + w[0].w*in[j+3].x;
        o.y = cbv.y + w[1].x*in[j].y + w[1].y*in[j+1].y + w[1].z*in[j+2].y + w[1].w*in[j+3].y;
        o.z = cbv.z + w[2].x*in[j].z + w[2].y*in[j+1].z + w[2].z*in[j+2].z + w[2].w*in[j+3].z;
        o.w = cbv.w + w[3].x*in[j].w + w[3].y*in[j+1].w + w[3].z*in[j+2].w + w[3].w*in[j+3].w;
        o.x = o.x * (1.f / (1.f + __expf(-o.x)));
        o.y = o.y * (1.f / (1.f + __expf(-o.y)));
        o.z = o.z * (1.f / (1.f + __expf(-o.z)));
        o.w = o.w * (1.f / (1.f + __expf(-o.w)));
        *(float4*)(g_uc + (size_t)(b * T_LEN + t0 + j) * DINNER + d) = o;
    }
}

// =================================================================================
// x_proj (unchanged)
// =================================================================================
__global__ __launch_bounds__(128)
void xproj_kernel(const float* __restrict__ W_x)
{
    __shared__ float swl[64 * 96];
    __shared__ float su[16][64];
    const int m0 = blockIdx.x * 16;
    const int tid = threadIdx.x;

    float acc[16];
    #pragma unroll
    for (int mi = 0; mi < 16; mi++) acc[mi] = 0.f;

    for (int kb = 0; kb < DINNER; kb += 64) {
        __syncthreads();
        #pragma unroll 4
        for (int i = tid; i < 64 * 96; i += 128) swl[i] = W_x[kb * 96 + i];
        #pragma unroll
        for (int i = tid; i < 16 * 64; i += 128) {
            const int mi = i >> 6, c = i & 63;
            su[mi][c] = g_uc[(size_t)(m0 + mi) * DINNER + kb + c];
        }
        __syncthreads();
        if (tid < 96) {
            #pragma unroll 2
            for (int r = 0; r < 64; r++) {
                const float w = swl[r * 96 + tid];
                #pragma unroll
                for (int mi = 0; mi < 16; mi++)
                    acc[mi] = fmaf(su[mi][r], w, acc[mi]);
            }
        }
    }
    if (tid < 96) {
        #pragma unroll
        for (int mi = 0; mi < 16; mi++)
            g_xdbl[(size_t)(m0 + mi) * NXP + tid] = acc[mi];
    }
}

// =================================================================================
// dt_proj + softplus (unchanged)
// =================================================================================
__global__ __launch_bounds__(128)
void dtproj_kernel(const float* __restrict__ W_dt, const float* __restrict__ b_dt)
{
    __shared__ float sw[64][128];
    __shared__ float sx[16][64];
    const int d0 = blockIdx.x * 128;
    const int m0 = blockIdx.y * 16;
    const int tid = threadIdx.x;

    #pragma unroll 4
    for (int i = tid; i < 64 * 128; i += 128) {
        const int r = i >> 7, dd = i & 127;
        sw[r][dd] = W_dt[(size_t)r * DINNER + d0 + dd];
    }
    #pragma unroll
    for (int i = tid; i < 16 * 64; i += 128) {
        const int mi = i >> 6, r = i & 63;
        sx[mi][r] = g_xdbl[(size_t)(m0 + mi) * NXP + r];
    }
    __syncthreads();

    float acc[16];
    const float bb = b_dt[d0 + tid];
    #pragma unroll
    for (int mi = 0; mi < 16; mi++) acc[mi] = bb;

    #pragma unroll 2
    for (int r = 0; r < 64; r++) {
        const float w = sw[r][tid];
        #pragma unroll
        for (int mi = 0; mi < 16; mi++)
            acc[mi] = fmaf(sx[mi][r], w, acc[mi]);
    }
    #pragma unroll
    for (int mi = 0; mi < 16; mi++) {
        const float z = acc[mi];
        const float sp = (z > 15.f) ? z : log1pf(__expf(z));
        g_delta[(size_t)(m0 + mi) * DINNER + d0 + tid] = sp;
    }
}

// =================================================================================
// Selective scan v3: 6-stage cp.async pipeline (48KB smem), 16 timesteps/stage.
// Epilogue writes the bf16 hi/lo split of y directly into the g_P u-half of the
// row (hi @ bf16 [0..DINNER), lo @ [DINNER..2*DINNER)); res-half untouched.
// =================================================================================
#define TB   16
#define NSTG 6

__global__ __launch_bounds__(128)
void scan_kernel(const float* __restrict__ A_log, const float* __restrict__ Dv)
{
    __shared__ __align__(16) float sdl[NSTG][TB][32];
    __shared__ __align__(16) float suu[NSTG][TB][32];
    __shared__ __align__(16) float srs[NSTG][TB][32];
    __shared__ __align__(16) float sbc[NSTG][TB][32];

    const int b = blockIdx.y;
    const int d0 = blockIdx.x * 32;
    const int tid = threadIdx.x;
    const int w = tid >> 5, lane = tid & 31;
    const int g = lane >> 2, q = lane & 3;
    const int dloc = w * 8 + g;
    const int d = d0 + dloc;
    const int nb = q * 4;

    const float A0 = -__expf(A_log[d * DSTATE + nb + 0]);
    const float A1 = -__expf(A_log[d * DSTATE + nb + 1]);
    const float A2 = -__expf(A_log[d * DSTATE + nb + 2]);
    const float A3 = -__expf(A_log[d * DSTATE + nb + 3]);
    const float Dd = Dv[d];

    const int t_ld = tid >> 3;
    const int seg  = (tid & 7) * 4;

    const size_t mb = (size_t)b * T_LEN;

    const uint32_t a_dl = smem_u32(&sdl[0][t_ld][seg]);
    const uint32_t a_uu = smem_u32(&suu[0][t_ld][seg]);
    const uint32_t a_rs = smem_u32(&srs[0][t_ld][seg]);
    const uint32_t a_bc = smem_u32(&sbc[0][t_ld][seg]);
    const uint32_t stg_bytes = TB * 32 * 4;

    #define SCAN_ISSUE(S, Cc) do {                                                     \
        const size_t _m = mb + (size_t)(Cc) * TB + t_ld;                               \
        cp16(a_dl + (S) * stg_bytes, g_delta + _m * DINNER + d0 + seg);                \
        cp16(a_uu + (S) * stg_bytes, g_uc    + _m * DINNER + d0 + seg);                \
        cp16(a_rs + (S) * stg_bytes, g_P     + _m * DPROJ + DINNER + d0 + seg);        \
        cp16(a_bc + (S) * stg_bytes, g_xdbl  + _m * NXP + DTRANK + seg);               \
        CP_COMMIT();                                                                   \
    } while (0)

    #pragma unroll
    for (int p = 0; p < NSTG; p++) SCAN_ISSUE(p, p);

    float h0 = 0.f, h1 = 0.f, h2 = 0.f, h3 = 0.f;
    constexpr int NCH = T_LEN / TB;

    for (int c = 0; c < NCH; c++) {
        const int S = c % NSTG;
        CP_WAIT5();
        __syncthreads();

        #pragma unroll
        for (int tt = 0; tt < TB; tt++) {
            const float dl = sdl[S][tt][dloc];
            const float uu = suu[S][tt][dloc];
            const float4 Bv = *(const float4*)&sbc[S][tt][nb];
            const float4 Cv = *(const float4*)&sbc[S][tt][16 + nb];

            const float du = dl * uu;
            h0 = fmaf(__expf(dl * A0), h0, du * Bv.x);
            h1 = fmaf(__expf(dl * A1), h1, du * Bv.y);
            h2 = fmaf(__expf(dl * A2), h2, du * Bv.z);
            h3 = fmaf(__expf(dl * A3), h3, du * Bv.w);

            float p = fmaf(h0, Cv.x, fmaf(h1, Cv.y, fmaf(h2, Cv.z, h3 * Cv.w)));
            p += __shfl_xor_sync(0xffffffffu, p, 1);
            p += __shfl_xor_sync(0xffffffffu, p, 2);

            if (q == 0) {
                const float resv = srs[S][tt][dloc];
                const float gate = resv * (1.f / (1.f + __expf(-resv)));
                const float yv = (p + uu * Dd) * gate;
                const __nv_bfloat16 hv = __float2bfloat16_rn(yv);
                const __nv_bfloat16 lv = __float2bfloat16_rn(yv - __bfloat162float(hv));
                __nv_bfloat16* rowp = (__nv_bfloat16*)g_P
                                      + (mb + (size_t)(c * TB + tt)) * (2 * DPROJ);
                rowp[d] = hv;
                rowp[DINNER + d] = lv;
            }
        }
        __syncthreads();
        if (c + NSTG < NCH) { SCAN_ISSUE(S, c + NSTG); }
        else                { CP_COMMIT(); }
    }
}

// =================================================================================
// launch
// =================================================================================
extern "C" void kernel_launch(void* const* d_in, const int* in_sizes, int n_in,
                              void* d_out, int out_size)
{
    const float* x      = (const float*)d_in[0];
    const float* W_in   = (const float*)d_in[1];
    const float* conv_w = (const float*)d_in[2];
    const float* conv_b = (const float*)d_in[3];
    const float* W_x    = (const float*)d_in[4];
    const float* W_dt   = (const float*)d_in[5];
    const float* b_dt   = (const float*)d_in[6];
    const float* A_log  = (const float*)d_in[7];
    const float* Dv     = (const float*)d_in[8];
    const float* W_out  = (const float*)d_in[9];
    float* out = (float*)d_out;

    // --- in_proj ---
    split_x_kernel<<<(M_ROWS * DMODEL / 4) / 256, 256>>>(x);
    splitT_kernel<0><<<dim3(DPROJ / 32, DMODEL / 32), 256>>>(W_in);
    gemm_hmma<0><<<dim3(DPROJ / 128, M_ROWS / 128), 256>>>(nullptr);

    // --- mid pipeline ---
    conv_silu_kernel<<<(B_SZ * (T_LEN / 4) * (DINNER / 4)) / 256, 256>>>(conv_w, conv_b);
    xproj_kernel<<<M_ROWS / 16, 128>>>(W_x);
    dtproj_kernel<<<dim3(DINNER / 128, M_ROWS / 16), 128>>>(W_dt, b_dt);
    splitT_kernel<1><<<dim3(DMODEL / 32, DINNER / 32), 256>>>(W_out);
    scan_kernel<<<dim3(DINNER / 32, B_SZ), 128>>>(A_log, Dv);

    // --- out_proj (A2 read directly from g_P u-halves; no split_y) ---
    gemm_hmma<1><<<dim3(DMODEL / 128, M_ROWS / 128), 256>>>(out);
}

// round 11
// speedup vs baseline: 3.9374x; 1.1765x over previous
#include <cuda_runtime.h>
#include <cuda_bf16.h>
#include <cuda_fp16.h>
#include <math.h>
#include <stdint.h>

#define T_LEN   2048
#define B_SZ    4
#define DMODEL  1024
#define DINNER  2048
#define DSTATE  16
#define DTRANK  64
#define NXP     96
#define M_ROWS  (B_SZ*T_LEN)   // 8192
#define DPROJ   (2*DINNER)     // 4096

// ---------------- scratch (device globals; proven 323MB set) ----------
__device__ __align__(16) float g_P[(size_t)M_ROWS * DPROJ];     // in_proj out; later u-half holds A2 hi/lo (fp16)
__device__ __align__(16) float g_uc[(size_t)M_ROWS * DINNER];
__device__ __align__(16) float g_xdbl[(size_t)M_ROWS * NXP];
__device__ __align__(16) float g_delta[(size_t)M_ROWS * DINNER];
__device__ __align__(16) float g_y[(size_t)M_ROWS * DINNER];    // backs W2 (fp16) only

// ---- 2-byte operands ALIASED into scratch (lifetimes verified disjoint) ----
__device__ __forceinline__ __nv_bfloat16* A1H() { return (__nv_bfloat16*)g_delta; }
__device__ __forceinline__ __nv_bfloat16* A1L() { return (__nv_bfloat16*)g_delta + (size_t)M_ROWS * DMODEL; }
__device__ __forceinline__ __nv_bfloat16* W1H() { return (__nv_bfloat16*)g_uc; }
__device__ __forceinline__ __nv_bfloat16* W1L() { return (__nv_bfloat16*)g_uc + (size_t)DPROJ * DMODEL; }
__device__ __forceinline__ __half*        W2H() { return (__half*)g_y; }

// ---------------- helpers ----------------
__device__ __forceinline__ uint32_t smem_u32(const void* p) {
    uint32_t a;
    asm("{ .reg .u64 t; cvta.to.shared.u64 t, %1; cvt.u32.u64 %0, t; }" : "=r"(a) : "l"(p));
    return a;
}
__device__ __forceinline__ void cp16(uint32_t d, const void* s) {
    asm volatile("cp.async.cg.shared.global [%0], [%1], 16;" :: "r"(d), "l"(s));
}
#define CP_COMMIT() asm volatile("cp.async.commit_group;" ::: "memory")
#define CP_WAIT0()  asm volatile("cp.async.wait_group 0;"  ::: "memory")
#define CP_WAIT1()  asm volatile("cp.async.wait_group 1;"  ::: "memory")
#define CP_WAIT5()  asm volatile("cp.async.wait_group 5;"  ::: "memory")

__device__ __forceinline__ void ldsm4(uint32_t* r, uint32_t a) {
    asm volatile("ldmatrix.sync.aligned.m8n8.x4.shared.b16 {%0,%1,%2,%3}, [%4];"
        : "=r"(r[0]), "=r"(r[1]), "=r"(r[2]), "=r"(r[3]) : "r"(a));
}
__device__ __forceinline__ void mma_bf16(float* c, const uint32_t* a, const uint32_t* b) {
    asm volatile("mma.sync.aligned.m16n8k16.row.col.f32.bf16.bf16.f32 "
        "{%0,%1,%2,%3}, {%4,%5,%6,%7}, {%8,%9}, {%0,%1,%2,%3};"
        : "+f"(c[0]), "+f"(c[1]), "+f"(c[2]), "+f"(c[3])
        : "r"(a[0]), "r"(a[1]), "r"(a[2]), "r"(a[3]), "r"(b[0]), "r"(b[1]));
}
__device__ __forceinline__ void mma_fp16(float* c, const uint32_t* a, const uint32_t* b) {
    asm volatile("mma.sync.aligned.m16n8k16.row.col.f32.f16.f16.f32 "
        "{%0,%1,%2,%3}, {%4,%5,%6,%7}, {%8,%9}, {%0,%1,%2,%3};"
        : "+f"(c[0]), "+f"(c[1]), "+f"(c[2]), "+f"(c[3])
        : "r"(a[0]), "r"(a[1]), "r"(a[2]), "r"(a[3]), "r"(b[0]), "r"(b[1]));
}

__device__ __forceinline__ size_t map_tbc(int m, int col) {
    return (size_t)(m & (T_LEN - 1)) * (B_SZ * DMODEL) + (size_t)(m >> 11) * DMODEL + col;
}

// =================================================================================
// Split kernels
// =================================================================================
__device__ __forceinline__ void split_store4(float4 v, __nv_bfloat16* hp, __nv_bfloat16* lp) {
    __nv_bfloat16 h0 = __float2bfloat16_rn(v.x), h1 = __float2bfloat16_rn(v.y);
    __nv_bfloat16 h2 = __float2bfloat16_rn(v.z), h3 = __float2bfloat16_rn(v.w);
    __nv_bfloat16 l0 = __float2bfloat16_rn(v.x - __bfloat162float(h0));
    __nv_bfloat16 l1 = __float2bfloat16_rn(v.y - __bfloat162float(h1));
    __nv_bfloat16 l2 = __float2bfloat16_rn(v.z - __bfloat162float(h2));
    __nv_bfloat16 l3 = __float2bfloat16_rn(v.w - __bfloat162float(h3));
    *(ushort4*)hp = make_ushort4(__bfloat16_as_ushort(h0), __bfloat16_as_ushort(h1),
                                 __bfloat16_as_ushort(h2), __bfloat16_as_ushort(h3));
    *(ushort4*)lp = make_ushort4(__bfloat16_as_ushort(l0), __bfloat16_as_ushort(l1),
                                 __bfloat16_as_ushort(l2), __bfloat16_as_ushort(l3));
}

__global__ __launch_bounds__(256)
void split_x_kernel(const float* __restrict__ x)
{
    const int q = blockIdx.x * 256 + threadIdx.x;
    const int c = (q & 255) * 4;
    const int m = q >> 8;
    const int t = m & (T_LEN - 1), b = m >> 11;
    float4 v = *(const float4*)(x + (size_t)t * (B_SZ * DMODEL) + b * DMODEL + c);
    const size_t o = (size_t)m * DMODEL + c;
    split_store4(v, A1H() + o, A1L() + o);
}

// WHICH=0: W_in -> bf16 hi/lo (W1H/W1L). WHICH=1: W_out -> fp16 single (W2H).
template<int WHICH>
__global__ __launch_bounds__(256)
void splitT_kernel(const float* __restrict__ W)
{
    constexpr int K = WHICH ? DINNER : DMODEL;
    constexpr int N = WHICH ? DMODEL : DPROJ;
    __shared__ float tile[32][33];
    const int n0 = blockIdx.x * 32, k0 = blockIdx.y * 32;
    const int tid = threadIdx.x;
    #pragma unroll
    for (int p = 0; p < 4; p++) {
        const int idx = tid + p * 256;
        const int kr = idx >> 5, nc = idx & 31;
        tile[kr][nc] = W[(size_t)(k0 + kr) * N + n0 + nc];
    }
    __syncthreads();
    const int nr = tid >> 3;
    const int kq = (tid & 7) * 4;
    float4 v = make_float4(tile[kq + 0][nr], tile[kq + 1][nr], tile[kq + 2][nr], tile[kq + 3][nr]);
    const size_t o = (size_t)(n0 + nr) * K + (k0 + kq);
    if (WHICH == 0) {
        split_store4(v, W1H() + o, W1L() + o);
    } else {
        __half h0 = __float2half_rn(v.x), h1 = __float2half_rn(v.y);
        __half h2 = __float2half_rn(v.z), h3 = __float2half_rn(v.w);
        *(ushort4*)(W2H() + o) = make_ushort4(__half_as_ushort(h0), __half_as_ushort(h1),
                                              __half_as_ushort(h2), __half_as_ushort(h3));
    }
}

// =================================================================================
// Split GEMM via mma.sync.
// MODE 0 (in_proj): bf16 3-term (AhBh + AhBl + AlBh). 4 smem mats. N=4096 K=1024.
// MODE 1 (out_proj): fp16 2-term ((Ah+Al)·Bh, B rounded to fp16). 3 smem mats.
//         A2 interleaved in g_P u-halves (2B row stride 2*DPROJ, lo at +DINNER).
//         N=1024 K=2048, output through map_tbc.
// =================================================================================
#define GROW 48
#define MATB (128 * GROW)

template<int MODE>
__global__ __launch_bounds__(256)
void gemm_hmma(float* __restrict__ Cparam)
{
    constexpr int N  = MODE ? DMODEL : DPROJ;
    constexpr int K  = MODE ? DINNER : DMODEL;
    constexpr int CH = K / 16;
    constexpr int NMAT = MODE ? 3 : 4;
    constexpr int STGB = NMAT * MATB;

    __shared__ __align__(16) char smb[2 * STGB];   // 48KB (MODE0) / 36.9KB (MODE1)

    const int tid  = threadIdx.x;
    const int lane = tid & 31, wid = tid >> 5;
    const int wm = wid & 1;
    const int wn = wid >> 1;
    const int bm = blockIdx.y * 128;
    const int bn = blockIdx.x * 128;

    const uint16_t* srcs[4];
    size_t strides[4];
    if (MODE == 0) {
        srcs[0] = (const uint16_t*)A1H() + (size_t)bm * K;
        srcs[1] = (const uint16_t*)A1L() + (size_t)bm * K;
        srcs[2] = (const uint16_t*)W1H() + (size_t)bn * K;
        srcs[3] = (const uint16_t*)W1L() + (size_t)bn * K;
        strides[0] = strides[1] = strides[2] = strides[3] = K;
    } else {
        srcs[0] = (const uint16_t*)g_P + (size_t)bm * (2 * DPROJ);   // A2 hi (fp16)
        srcs[1] = srcs[0] + DINNER;                                   // A2 lo (fp16)
        srcs[2] = (const uint16_t*)W2H() + (size_t)bn * K;            // W2 (fp16)
        srcs[3] = srcs[2];
        strides[0] = strides[1] = 2 * DPROJ;
        strides[2] = strides[3] = K;
    }

    float* C = MODE ? Cparam : g_P;
    const uint32_t sb = smem_u32(smb);

    const int cmat = tid >> 6;
    const int cidx = tid & 63;
    const uint16_t* csrc = srcs[cmat];
    const size_t cstr = strides[cmat];
    const bool cdo = (MODE == 0) || (cmat < 3);

    #define ISSUE(S, CHK) do {                                                   \
        if (cdo) {                                                               \
            const uint32_t dbase = sb + (uint32_t)(S) * STGB + cmat * MATB;      \
            _Pragma("unroll")                                                    \
            for (int jj = 0; jj < 4; jj++) {                                     \
                const int lin = jj * 64 + cidx;                                  \
                const int r = lin >> 1, cc = lin & 1;                            \
                cp16(dbase + r * GROW + cc * 16,                                 \
                     csrc + (size_t)r * cstr + (CHK) * 16 + cc * 8);             \
            }                                                                    \
        }                                                                        \
        CP_COMMIT();                                                             \
    } while (0)

    float acc[4][4][4];
    #pragma unroll
    for (int mi = 0; mi < 4; mi++)
        #pragma unroll
        for (int nj = 0; nj < 4; nj++)
            #pragma unroll
            for (int e = 0; e < 4; e++) acc[mi][nj][e] = 0.f;

    ISSUE(0, 0);
    if (CH > 1) ISSUE(1, 1);

    const int lrow = lane & 15;
    const int lcol = (lane >> 4) * 16;

    for (int i = 0; i < CH; i++) {
        const int s = i & 1;
        if (i + 1 < CH) { CP_WAIT1(); } else { CP_WAIT0(); }
        __syncthreads();

        const uint32_t Ah = sb + s * STGB;
        const uint32_t Al = Ah + MATB;
        const uint32_t Bh = Ah + 2 * MATB;
        const uint32_t Bl = Ah + 3 * MATB;   // MODE1: unused

        uint32_t ah[4][4], al[4][4], bh[4][2], bl[4][2];
        #pragma unroll
        for (int mi = 0; mi < 4; mi++) {
            const uint32_t off = (uint32_t)(wm * 64 + mi * 16 + lrow) * GROW + lcol;
            ldsm4(ah[mi], Ah + off);
            ldsm4(al[mi], Al + off);
        }
        #pragma unroll
        for (int p = 0; p < 2; p++) {
            const uint32_t off = (uint32_t)(wn * 32 + p * 16 + lrow) * GROW + lcol;
            uint32_t r4[4];
            ldsm4(r4, Bh + off);
            bh[2 * p][0] = r4[0]; bh[2 * p + 1][0] = r4[1];
            bh[2 * p][1] = r4[2]; bh[2 * p + 1][1] = r4[3];
            if (MODE == 0) {
                ldsm4(r4, Bl + off);
                bl[2 * p][0] = r4[0]; bl[2 * p + 1][0] = r4[1];
                bl[2 * p][1] = r4[2]; bl[2 * p + 1][1] = r4[3];
            }
        }

        #pragma unroll
        for (int mi = 0; mi < 4; mi++)
            #pragma unroll
            for (int nj = 0; nj < 4; nj++) {
                if (MODE == 0) {
                    mma_bf16(acc[mi][nj], ah[mi], bh[nj]);
                    mma_bf16(acc[mi][nj], ah[mi], bl[nj]);
                    mma_bf16(acc[mi][nj], al[mi], bh[nj]);
                } else {
                    mma_fp16(acc[mi][nj], ah[mi], bh[nj]);
                    mma_fp16(acc[mi][nj], al[mi], bh[nj]);
                }
            }

        __syncthreads();
        if (i + 2 < CH) ISSUE(s, i + 2);
    }

    const int tg2 = (lane & 3) * 2;
    const int gq  = lane >> 2;
    #pragma unroll
    for (int mi = 0; mi < 4; mi++) {
        const int row0 = bm + wm * 64 + mi * 16 + gq;
        #pragma unroll
        for (int nj = 0; nj < 4; nj++) {
            const int col = bn + wn * 32 + nj * 8 + tg2;
            const size_t o0 = MODE ? map_tbc(row0, col)     : (size_t)row0 * N + col;
            const size_t o1 = MODE ? map_tbc(row0 + 8, col) : (size_t)(row0 + 8) * N + col;
            *(float2*)(C + o0) = make_float2(acc[mi][nj][0], acc[mi][nj][1]);
            *(float2*)(C + o1) = make_float2(acc[mi][nj][2], acc[mi][nj][3]);
        }
    }
}

// =================================================================================
// Depthwise causal conv (k=4) + bias + silu (proven R10 version)
// =================================================================================
__global__ __launch_bounds__(256)
void conv_silu_kernel(const float* __restrict__ cw, const float* __restrict__ cb)
{
    const int q = blockIdx.x * 256 + threadIdx.x;
    const int d  = (q & 511) << 2;
    const int r  = q >> 9;
    const int t0 = (r & 511) << 2;
    const int b  = r >> 9;

    float4 w[4];
    #pragma unroll
    for (int i = 0; i < 4; i++) w[i] = *(const float4*)(cw + (d + i) * 4);
    const float4 cbv = *(const float4*)(cb + d);

    float4 in[7];
    #pragma unroll
    for (int j = 0; j < 7; j++) {
        const int t = t0 + j - 3;
        in[j] = (t >= 0)
            ? *(const float4*)(g_P + (size_t)(b * T_LEN + t) * DPROJ + d)
            : make_float4(0.f, 0.f, 0.f, 0.f);
    }

    #pragma unroll
    for (int j = 0; j < 4; j++) {
        float4 o;
        o.x = cbv.x + w[0].x*in[j].x + w[0].y*in[j+1].x + w[0].z*in[j+2].x + w[0].w*in[j+3].x;
        o.y = cbv.y + w[1].x*in[j].y + w[1].y*in[j+1].y + w[1].z*in[j+2].y + w[1].w*in[j+3].y;
        o.z = cbv.z + w[2].x*in[j].z + w[2].y*in[j+1].z + w[2].z*in[j+2].z + w[2].w*in[j+3].z;
        o.w = cbv.w + w[3].x*in[j].w + w[3].y*in[j+1].w + w[3].z*in[j+2].w + w[3].w*in[j+3].w;
        o.x = o.x * (1.f / (1.f + __expf(-o.x)));
        o.y = o.y * (1.f / (1.f + __expf(-o.y)));
        o.z = o.z * (1.f / (1.f + __expf(-o.z)));
        o.w = o.w * (1.f / (1.f + __expf(-o.w)));
        *(float4*)(g_uc + (size_t)(b * T_LEN + t0 + j) * DINNER + d) = o;
    }
}

// =================================================================================
// x_proj v2: 256 threads, 32 m-rows/block, register-blocked 4 rows x 3 cols.
// smem: W chunk [64][96] + transposed u chunk [64][36-padded].
// =================================================================================
__global__ __launch_bounds__(256)
void xproj_kernel(const float* __restrict__ W_x)
{
    __shared__ float swl[64 * 96];     // [r][c] linear
    __shared__ float sut[64][36];      // [r][m], padded
    const int m0 = blockIdx.x * 32;
    const int tid = threadIdx.x;
    const int rowg = tid >> 5;         // 0..7 -> rows rowg*4..+3
    const int colg = tid & 31;         // 0..31 -> cols colg*3..+2

    float acc[4][3];
    #pragma unroll
    for (int i = 0; i < 4; i++)
        #pragma unroll
        for (int j = 0; j < 3; j++) acc[i][j] = 0.f;

    const int lm = tid >> 3;           // 0..31 (u row this thread loads)
    const int lk = (tid & 7) * 8;      // k base (2 float4s)

    for (int kb = 0; kb < DINNER; kb += 64) {
        __syncthreads();
        // W chunk: 1536 float4
        #pragma unroll
        for (int j = 0; j < 6; j++) {
            const int idx = tid + j * 256;
            *(float4*)&swl[idx * 4] = *(const float4*)(W_x + (size_t)kb * 96 + idx * 4);
        }
        // u chunk transposed
        {
            const float4 v0 = *(const float4*)(g_uc + (size_t)(m0 + lm) * DINNER + kb + lk);
            const float4 v1 = *(const float4*)(g_uc + (size_t)(m0 + lm) * DINNER + kb + lk + 4);
            sut[lk + 0][lm] = v0.x; sut[lk + 1][lm] = v0.y;
            sut[lk + 2][lm] = v0.z; sut[lk + 3][lm] = v0.w;
            sut[lk + 4][lm] = v1.x; sut[lk + 5][lm] = v1.y;
            sut[lk + 6][lm] = v1.z; sut[lk + 7][lm] = v1.w;
        }
        __syncthreads();

        #pragma unroll 4
        for (int r = 0; r < 64; r++) {
            const float4 u4 = *(const float4*)&sut[r][rowg * 4];
            const float w0 = swl[r * 96 + colg * 3 + 0];
            const float w1 = swl[r * 96 + colg * 3 + 1];
            const float w2 = swl[r * 96 + colg * 3 + 2];
            acc[0][0] = fmaf(u4.x, w0, acc[0][0]); acc[0][1] = fmaf(u4.x, w1, acc[0][1]); acc[0][2] = fmaf(u4.x, w2, acc[0][2]);
            acc[1][0] = fmaf(u4.y, w0, acc[1][0]); acc[1][1] = fmaf(u4.y, w1, acc[1][1]); acc[1][2] = fmaf(u4.y, w2, acc[1][2]);
            acc[2][0] = fmaf(u4.z, w0, acc[2][0]); acc[2][1] = fmaf(u4.z, w1, acc[2][1]); acc[2][2] = fmaf(u4.z, w2, acc[2][2]);
            acc[3][0] = fmaf(u4.w, w0, acc[3][0]); acc[3][1] = fmaf(u4.w, w1, acc[3][1]); acc[3][2] = fmaf(u4.w, w2, acc[3][2]);
        }
    }
    #pragma unroll
    for (int i = 0; i < 4; i++)
        #pragma unroll
        for (int j = 0; j < 3; j++)
            g_xdbl[(size_t)(m0 + rowg * 4 + i) * NXP + colg * 3 + j] = acc[i][j];
}

// =================================================================================
// dt_proj v2 + softplus: 64 m-rows/block, transposed-x smem, float4 LDS.
// =================================================================================
__global__ __launch_bounds__(128)
void dtproj_kernel(const float* __restrict__ W_dt, const float* __restrict__ b_dt)
{
    __shared__ float sw[64][128];      // 32KB
    __shared__ float sxt[64][68];      // [r][mi], padded; 17.4KB -> total 49.4KB? NO: 64*68*4=17408; 32768+17408=50176 > 49152!
    // (see note) -- pad 66 instead: 64*66*4 = 16896; total 49664 still >48K. pad 64: conflicts.
    const int d0 = blockIdx.x * 128;
    const int m0 = blockIdx.y * 64;
    const int tid = threadIdx.x;

    // load W chunk [64][128]
    #pragma unroll
    for (int i = 0; i < 64; i++)
        sw[i][tid] = W_dt[(size_t)i * DINNER + d0 + tid];

    // load x chunk transposed: thread mi = tid>>1, k half = (tid&1)*32
    {
        const int mi = tid >> 1;
        const int kh = (tid & 1) * 32;
        #pragma unroll
        for (int j = 0; j < 8; j++) {
            const float4 v = *(const float4*)(g_xdbl + (size_t)(m0 + mi) * NXP + kh + j * 4);
            sxt[kh + j * 4 + 0][mi] = v.x;
            sxt[kh + j * 4 + 1][mi] = v.y;
            sxt[kh + j * 4 + 2][mi] = v.z;
            sxt[kh + j * 4 + 3][mi] = v.w;
        }
    }
    __syncthreads();

    float acc[64];
    const float bb = b_dt[d0 + tid];
    #pragma unroll
    for (int mi = 0; mi < 64; mi++) acc[mi] = bb;

    for (int r = 0; r < 64; r++) {
        const float w = sw[r][tid];
        #pragma unroll
        for (int m4 = 0; m4 < 16; m4++) {
            const float4 xv = *(const float4*)&sxt[r][m4 * 4];
            acc[m4 * 4 + 0] = fmaf(xv.x, w, acc[m4 * 4 + 0]);
            acc[m4 * 4 + 1] = fmaf(xv.y, w, acc[m4 * 4 + 1]);
            acc[m4 * 4 + 2] = fmaf(xv.z, w, acc[m4 * 4 + 2]);
            acc[m4 * 4 + 3] = fmaf(xv.w, w, acc[m4 * 4 + 3]);
        }
    }
    #pragma unroll
    for (int mi = 0; mi < 64; mi++) {
        const float z = acc[mi];
        const float sp = (z > 15.f) ? z : log1pf(__expf(z));
        g_delta[(size_t)(m0 + mi) * DINNER + d0 + tid] = sp;
    }
}

// =================================================================================
// Selective scan: 6-stage cp.async pipeline; epilogue writes fp16 hi/lo of y
// into the g_P u-half of the row.
// =================================================================================
#define TB   16
#define NSTG 6

__global__ __launch_bounds__(128)
void scan_kernel(const float* __restrict__ A_log, const float* __restrict__ Dv)
{
    __shared__ __align__(16) float sdl[NSTG][TB][32];
    __shared__ __align__(16) float suu[NSTG][TB][32];
    __shared__ __align__(16) float srs[NSTG][TB][32];
    __shared__ __align__(16) float sbc[NSTG][TB][32];

    const int b = blockIdx.y;
    const int d0 = blockIdx.x * 32;
    const int tid = threadIdx.x;
    const int w = tid >> 5, lane = tid & 31;
    const int g = lane >> 2, q = lane & 3;
    const int dloc = w * 8 + g;
    const int d = d0 + dloc;
    const int nb = q * 4;

    const float A0 = -__expf(A_log[d * DSTATE + nb + 0]);
    const float A1 = -__expf(A_log[d * DSTATE + nb + 1]);
    const float A2 = -__expf(A_log[d * DSTATE + nb + 2]);
    const float A3 = -__expf(A_log[d * DSTATE + nb + 3]);
    const float Dd = Dv[d];

    const int t_ld = tid >> 3;
    const int seg  = (tid & 7) * 4;

    const size_t mb = (size_t)b * T_LEN;

    const uint32_t a_dl = smem_u32(&sdl[0][t_ld][seg]);
    const uint32_t a_uu = smem_u32(&suu[0][t_ld][seg]);
    const uint32_t a_rs = smem_u32(&srs[0][t_ld][seg]);
    const uint32_t a_bc = smem_u32(&sbc[0][t_ld][seg]);
    const uint32_t stg_bytes = TB * 32 * 4;

    #define SCAN_ISSUE(S, Cc) do {                                                     \
        const size_t _m = mb + (size_t)(Cc) * TB + t_ld;                               \
        cp16(a_dl + (S) * stg_bytes, g_delta + _m * DINNER + d0 + seg);                \
        cp16(a_uu + (S) * stg_bytes, g_uc    + _m * DINNER + d0 + seg);                \
        cp16(a_rs + (S) * stg_bytes, g_P     + _m * DPROJ + DINNER + d0 + seg);        \
        cp16(a_bc + (S) * stg_bytes, g_xdbl  + _m * NXP + DTRANK + seg);               \
        CP_COMMIT();                                                                   \
    } while (0)

    #pragma unroll
    for (int p = 0; p < NSTG; p++) SCAN_ISSUE(p, p);

    float h0 = 0.f, h1 = 0.f, h2 = 0.f, h3 = 0.f;
    constexpr int NCH = T_LEN / TB;

    for (int c = 0; c < NCH; c++) {
        const int S = c % NSTG;
        CP_WAIT5();
        __syncthreads();

        #pragma unroll
        for (int tt = 0; tt < TB; tt++) {
            const float dl = sdl[S][tt][dloc];
            const float uu = suu[S][tt][dloc];
            const float4 Bv = *(const float4*)&sbc[S][tt][nb];
            const float4 Cv = *(const float4*)&sbc[S][tt][16 + nb];

            const float du = dl * uu;
            h0 = fmaf(__expf(dl * A0), h0, du * Bv.x);
            h1 = fmaf(__expf(dl * A1), h1, du * Bv.y);
            h2 = fmaf(__expf(dl * A2), h2, du * Bv.z);
            h3 = fmaf(__expf(dl * A3), h3, du * Bv.w);

            float p = fmaf(h0, Cv.x, fmaf(h1, Cv.y, fmaf(h2, Cv.z, h3 * Cv.w)));
            p += __shfl_xor_sync(0xffffffffu, p, 1);
            p += __shfl_xor_sync(0xffffffffu, p, 2);

            if (q == 0) {
                const float resv = srs[S][tt][dloc];
                const float gate = resv * (1.f / (1.f + __expf(-resv)));
                const float yv = (p + uu * Dd) * gate;
                const __half hv = __float2half_rn(yv);
                const __half lv = __float2half_rn(yv - __half2float(hv));
                __half* rowp = (__half*)g_P + (mb + (size_t)(c * TB + tt)) * (2 * DPROJ);
                rowp[d] = hv;
                rowp[DINNER + d] = lv;
            }
        }
        __syncthreads();
        if (c + NSTG < NCH) { SCAN_ISSUE(S, c + NSTG); }
        else                { CP_COMMIT(); }
    }
}

// =================================================================================
// launch
// =================================================================================
extern "C" void kernel_launch(void* const* d_in, const int* in_sizes, int n_in,
                              void* d_out, int out_size)
{
    const float* x      = (const float*)d_in[0];
    const float* W_in   = (const float*)d_in[1];
    const float* conv_w = (const float*)d_in[2];
    const float* conv_b = (const float*)d_in[3];
    const float* W_x    = (const float*)d_in[4];
    const float* W_dt   = (const float*)d_in[5];
    const float* b_dt   = (const float*)d_in[6];
    const float* A_log  = (const float*)d_in[7];
    const float* Dv     = (const float*)d_in[8];
    const float* W_out  = (const float*)d_in[9];
    float* out = (float*)d_out;

    // --- in_proj (bf16 3-term) ---
    split_x_kernel<<<(M_ROWS * DMODEL / 4) / 256, 256>>>(x);
    splitT_kernel<0><<<dim3(DPROJ / 32, DMODEL / 32), 256>>>(W_in);
    gemm_hmma<0><<<dim3(DPROJ / 128, M_ROWS / 128), 256>>>(nullptr);

    // --- mid pipeline ---
    conv_silu_kernel<<<(B_SZ * (T_LEN / 4) * (DINNER / 4)) / 256, 256>>>(conv_w, conv_b);
    xproj_kernel<<<M_ROWS / 32, 256>>>(W_x);
    dtproj_kernel<<<dim3(DINNER / 128, M_ROWS / 64), 128>>>(W_dt, b_dt);
    splitT_kernel<1><<<dim3(DMODEL / 32, DINNER / 32), 256>>>(W_out);
    scan_kernel<<<dim3(DINNER / 32, B_SZ), 128>>>(A_log, Dv);

    // --- out_proj (fp16 2-term) ---
    gemm_hmma<1><<<dim3(DMODEL / 128, M_ROWS / 128), 256>>>(out);
}

// round 12
// speedup vs baseline: 4.4961x; 1.1419x over previous
#include <cuda_runtime.h>
#include <cuda_bf16.h>
#include <cuda_fp16.h>
#include <math.h>
#include <stdint.h>

#define T_LEN   2048
#define B_SZ    4
#define DMODEL  1024
#define DINNER  2048
#define DSTATE  16
#define DTRANK  64
#define NXP     96
#define M_ROWS  (B_SZ*T_LEN)   // 8192
#define DPROJ   (2*DINNER)     // 4096

// ---------------- scratch (device globals; proven 323MB set) ----------
__device__ __align__(16) float g_P[(size_t)M_ROWS * DPROJ];     // in_proj out; later u-half holds A2 hi/lo (fp16)
__device__ __align__(16) float g_uc[(size_t)M_ROWS * DINNER];
__device__ __align__(16) float g_xdbl[(size_t)M_ROWS * NXP];
__device__ __align__(16) float g_delta[(size_t)M_ROWS * DINNER];
__device__ __align__(16) float g_y[(size_t)M_ROWS * DINNER];    // backs W2 (fp16) only

// ---- fp16 operands ALIASED into scratch (lifetimes verified disjoint) ----
// A1 (split of x, fp16 hi/lo): g_delta until dtproj writes it
// W1 (W_in^T, fp16):           g_uc    until conv writes it
// A2 (split of y, fp16 hi/lo): interleaved in g_P u-halves, written by scan
// W2 (W_out^T, fp16):          g_y (free all run)
__device__ __forceinline__ __half* A1H() { return (__half*)g_delta; }
__device__ __forceinline__ __half* A1L() { return (__half*)g_delta + (size_t)M_ROWS * DMODEL; }
__device__ __forceinline__ __half* W1H() { return (__half*)g_uc; }
__device__ __forceinline__ __half* W2H() { return (__half*)g_y; }

// ---------------- helpers ----------------
__device__ __forceinline__ uint32_t smem_u32(const void* p) {
    uint32_t a;
    asm("{ .reg .u64 t; cvta.to.shared.u64 t, %1; cvt.u32.u64 %0, t; }" : "=r"(a) : "l"(p));
    return a;
}
__device__ __forceinline__ void cp16(uint32_t d, const void* s) {
    asm volatile("cp.async.cg.shared.global [%0], [%1], 16;" :: "r"(d), "l"(s));
}
#define CP_COMMIT() asm volatile("cp.async.commit_group;" ::: "memory")
#define CP_WAIT0()  asm volatile("cp.async.wait_group 0;"  ::: "memory")
#define CP_WAIT1()  asm volatile("cp.async.wait_group 1;"  ::: "memory")
#define CP_WAIT5()  asm volatile("cp.async.wait_group 5;"  ::: "memory")

__device__ __forceinline__ void ldsm4(uint32_t* r, uint32_t a) {
    asm volatile("ldmatrix.sync.aligned.m8n8.x4.shared.b16 {%0,%1,%2,%3}, [%4];"
        : "=r"(r[0]), "=r"(r[1]), "=r"(r[2]), "=r"(r[3]) : "r"(a));
}
__device__ __forceinline__ void mma_fp16(float* c, const uint32_t* a, const uint32_t* b) {
    asm volatile("mma.sync.aligned.m16n8k16.row.col.f32.f16.f16.f32 "
        "{%0,%1,%2,%3}, {%4,%5,%6,%7}, {%8,%9}, {%0,%1,%2,%3};"
        : "+f"(c[0]), "+f"(c[1]), "+f"(c[2]), "+f"(c[3])
        : "r"(a[0]), "r"(a[1]), "r"(a[2]), "r"(a[3]), "r"(b[0]), "r"(b[1]));
}

__device__ __forceinline__ size_t map_tbc(int m, int col) {
    return (size_t)(m & (T_LEN - 1)) * (B_SZ * DMODEL) + (size_t)(m >> 11) * DMODEL + col;
}

// =================================================================================
// Split kernels (fp16)
// =================================================================================
__device__ __forceinline__ void split_store4h(float4 v, __half* hp, __half* lp) {
    __half h0 = __float2half_rn(v.x), h1 = __float2half_rn(v.y);
    __half h2 = __float2half_rn(v.z), h3 = __float2half_rn(v.w);
    __half l0 = __float2half_rn(v.x - __half2float(h0));
    __half l1 = __float2half_rn(v.y - __half2float(h1));
    __half l2 = __float2half_rn(v.z - __half2float(h2));
    __half l3 = __float2half_rn(v.w - __half2float(h3));
    *(ushort4*)hp = make_ushort4(__half_as_ushort(h0), __half_as_ushort(h1),
                                 __half_as_ushort(h2), __half_as_ushort(h3));
    *(ushort4*)lp = make_ushort4(__half_as_ushort(l0), __half_as_ushort(l1),
                                 __half_as_ushort(l2), __half_as_ushort(l3));
}

__global__ __launch_bounds__(256)
void split_x_kernel(const float* __restrict__ x)
{
    const int q = blockIdx.x * 256 + threadIdx.x;
    const int c = (q & 255) * 4;
    const int m = q >> 8;
    const int t = m & (T_LEN - 1), b = m >> 11;
    float4 v = *(const float4*)(x + (size_t)t * (B_SZ * DMODEL) + b * DMODEL + c);
    const size_t o = (size_t)m * DMODEL + c;
    split_store4h(v, A1H() + o, A1L() + o);
}

// W [K,N] row-major -> W^T [N,K] fp16 single. WHICH=0 -> W1H, WHICH=1 -> W2H.
template<int WHICH>
__global__ __launch_bounds__(256)
void splitT_kernel(const float* __restrict__ W)
{
    constexpr int K = WHICH ? DINNER : DMODEL;
    constexpr int N = WHICH ? DMODEL : DPROJ;
    __shared__ float tile[32][33];
    const int n0 = blockIdx.x * 32, k0 = blockIdx.y * 32;
    const int tid = threadIdx.x;
    #pragma unroll
    for (int p = 0; p < 4; p++) {
        const int idx = tid + p * 256;
        const int kr = idx >> 5, nc = idx & 31;
        tile[kr][nc] = W[(size_t)(k0 + kr) * N + n0 + nc];
    }
    __syncthreads();
    const int nr = tid >> 3;
    const int kq = (tid & 7) * 4;
    float4 v = make_float4(tile[kq + 0][nr], tile[kq + 1][nr], tile[kq + 2][nr], tile[kq + 3][nr]);
    const size_t o = (size_t)(n0 + nr) * K + (k0 + kq);
    __half* Th = WHICH ? W2H() : W1H();
    __half h0 = __float2half_rn(v.x), h1 = __float2half_rn(v.y);
    __half h2 = __float2half_rn(v.z), h3 = __float2half_rn(v.w);
    *(ushort4*)(Th + o) = make_ushort4(__half_as_ushort(h0), __half_as_ushort(h1),
                                       __half_as_ushort(h2), __half_as_ushort(h3));
}

// =================================================================================
// fp16 2-term split GEMM via mma.sync: C = (Ah + Al) @ B  (B rounded to fp16).
// CTA 128x128, K-chunk 16, 2-buffer cp.async, 8 warps of 64x32, 3 smem matrices.
// MODE 0 (in_proj):  g_P = A1 @ W1; N=4096 K=1024; A row stride K.
// MODE 1 (out_proj): out = A2 @ W2; N=1024 K=2048; A2 interleaved in g_P u-halves
//         (row stride 2*DPROJ halves, lo at +DINNER); output through map_tbc.
// =================================================================================
#define GROW 48
#define MATB (128 * GROW)
#define STGB (3 * MATB)    // 18432

template<int MODE>
__global__ __launch_bounds__(256)
void gemm_hmma(float* __restrict__ Cparam)
{
    constexpr int N  = MODE ? DMODEL : DPROJ;
    constexpr int K  = MODE ? DINNER : DMODEL;
    constexpr int CH = K / 16;

    __shared__ __align__(16) char smb[2 * STGB];   // 36.9KB static

    const int tid  = threadIdx.x;
    const int lane = tid & 31, wid = tid >> 5;
    const int wm = wid & 1;
    const int wn = wid >> 1;
    const int bm = blockIdx.y * 128;
    const int bn = blockIdx.x * 128;

    const uint16_t* srcs[3];
    size_t strides[3];
    if (MODE == 0) {
        srcs[0] = (const uint16_t*)A1H() + (size_t)bm * K;
        srcs[1] = (const uint16_t*)A1L() + (size_t)bm * K;
        srcs[2] = (const uint16_t*)W1H() + (size_t)bn * K;
        strides[0] = strides[1] = strides[2] = K;
    } else {
        srcs[0] = (const uint16_t*)g_P + (size_t)bm * (2 * DPROJ);   // A2 hi
        srcs[1] = srcs[0] + DINNER;                                   // A2 lo
        srcs[2] = (const uint16_t*)W2H() + (size_t)bn * K;            // W2
        strides[0] = strides[1] = 2 * DPROJ;
        strides[2] = K;
    }

    float* C = MODE ? Cparam : g_P;
    const uint32_t sb = smem_u32(smb);

    const int cmat = tid >> 6;           // 0..3; group 3 idles
    const int cidx = tid & 63;
    const uint16_t* csrc = srcs[cmat < 3 ? cmat : 2];
    const size_t cstr = strides[cmat < 3 ? cmat : 2];
    const bool cdo = (cmat < 3);

    #define ISSUE(S, CHK) do {                                                   \
        if (cdo) {                                                               \
            const uint32_t dbase = sb + (uint32_t)(S) * STGB + cmat * MATB;      \
            _Pragma("unroll")                                                    \
            for (int jj = 0; jj < 4; jj++) {                                     \
                const int lin = jj * 64 + cidx;                                  \
                const int r = lin >> 1, cc = lin & 1;                            \
                cp16(dbase + r * GROW + cc * 16,                                 \
                     csrc + (size_t)r * cstr + (CHK) * 16 + cc * 8);             \
            }                                                                    \
        }                                                                        \
        CP_COMMIT();                                                             \
    } while (0)

    float acc[4][4][4];
    #pragma unroll
    for (int mi = 0; mi < 4; mi++)
        #pragma unroll
        for (int nj = 0; nj < 4; nj++)
            #pragma unroll
            for (int e = 0; e < 4; e++) acc[mi][nj][e] = 0.f;

    ISSUE(0, 0);
    if (CH > 1) ISSUE(1, 1);

    const int lrow = lane & 15;
    const int lcol = (lane >> 4) * 16;

    for (int i = 0; i < CH; i++) {
        const int s = i & 1;
        if (i + 1 < CH) { CP_WAIT1(); } else { CP_WAIT0(); }
        __syncthreads();

        const uint32_t Ah = sb + s * STGB;
        const uint32_t Al = Ah + MATB;
        const uint32_t Bh = Ah + 2 * MATB;

        uint32_t ah[4][4], al[4][4], bh[4][2];
        #pragma unroll
        for (int mi = 0; mi < 4; mi++) {
            const uint32_t off = (uint32_t)(wm * 64 + mi * 16 + lrow) * GROW + lcol;
            ldsm4(ah[mi], Ah + off);
            ldsm4(al[mi], Al + off);
        }
        #pragma unroll
        for (int p = 0; p < 2; p++) {
            const uint32_t off = (uint32_t)(wn * 32 + p * 16 + lrow) * GROW + lcol;
            uint32_t r4[4];
            ldsm4(r4, Bh + off);
            bh[2 * p][0] = r4[0]; bh[2 * p + 1][0] = r4[1];
            bh[2 * p][1] = r4[2]; bh[2 * p + 1][1] = r4[3];
        }

        #pragma unroll
        for (int mi = 0; mi < 4; mi++)
            #pragma unroll
            for (int nj = 0; nj < 4; nj++) {
                mma_fp16(acc[mi][nj], ah[mi], bh[nj]);
                mma_fp16(acc[mi][nj], al[mi], bh[nj]);
            }

        __syncthreads();
        if (i + 2 < CH) ISSUE(s, i + 2);
    }

    const int tg2 = (lane & 3) * 2;
    const int gq  = lane >> 2;
    #pragma unroll
    for (int mi = 0; mi < 4; mi++) {
        const int row0 = bm + wm * 64 + mi * 16 + gq;
        #pragma unroll
        for (int nj = 0; nj < 4; nj++) {
            const int col = bn + wn * 32 + nj * 8 + tg2;
            const size_t o0 = MODE ? map_tbc(row0, col)     : (size_t)row0 * N + col;
            const size_t o1 = MODE ? map_tbc(row0 + 8, col) : (size_t)(row0 + 8) * N + col;
            *(float2*)(C + o0) = make_float2(acc[mi][nj][0], acc[mi][nj][1]);
            *(float2*)(C + o1) = make_float2(acc[mi][nj][2], acc[mi][nj][3]);
        }
    }
}

// =================================================================================
// Depthwise causal conv (k=4) + bias + silu (proven R10 version)
// =================================================================================
__global__ __launch_bounds__(256)
void conv_silu_kernel(const float* __restrict__ cw, const float* __restrict__ cb)
{
    const int q = blockIdx.x * 256 + threadIdx.x;
    const int d  = (q & 511) << 2;
    const int r  = q >> 9;
    const int t0 = (r & 511) << 2;
    const int b  = r >> 9;

    float4 w[4];
    #pragma unroll
    for (int i = 0; i < 4; i++) w[i] = *(const float4*)(cw + (d + i) * 4);
    const float4 cbv = *(const float4*)(cb + d);

    float4 in[7];
    #pragma unroll
    for (int j = 0; j < 7; j++) {
        const int t = t0 + j - 3;
        in[j] = (t >= 0)
            ? *(const float4*)(g_P + (size_t)(b * T_LEN + t) * DPROJ + d)
            : make_float4(0.f, 0.f, 0.f, 0.f);
    }

    #pragma unroll
    for (int j = 0; j < 4; j++) {
        float4 o;
        o.x = cbv.x + w[0].x*in[j].x + w[0].y*in[j+1].x + w[0].z*in[j+2].x + w[0].w*in[j+3].x;
        o.y = cbv.y + w[1].x*in[j].y + w[1].y*in[j+1].y + w[1].z*in[j+2].y + w[1].w*in[j+3].y;
        o.z = cbv.z + w[2].x*in[j].z + w[2].y*in[j+1].z + w[2].z*in[j+2].z + w[2].w*in[j+3].z;
        o.w = cbv.w + w[3].x*in[j].w + w[3].y*in[j+1].w + w[3].z*in[j+2].w + w[3].w*in[j+3].w;
        o.x = o.x * (1.f / (1.f + __expf(-o.x)));
        o.y = o.y * (1.f / (1.f + __expf(-o.y)));
        o.z = o.z * (1.f / (1.f + __expf(-o.z)));
        o.w = o.w * (1.f / (1.f + __expf(-o.w)));
        *(float4*)(g_uc + (size_t)(b * T_LEN + t0 + j) * DINNER + d) = o;
    }
}

// =================================================================================
// x_proj v2 (proven R11 version)
// =================================================================================
__global__ __launch_bounds__(256)
void xproj_kernel(const float* __restrict__ W_x)
{
    __shared__ float swl[64 * 96];
    __shared__ float sut[64][36];
    const int m0 = blockIdx.x * 32;
    const int tid = threadIdx.x;
    const int rowg = tid >> 5;
    const int colg = tid & 31;

    float acc[4][3];
    #pragma unroll
    for (int i = 0; i < 4; i++)
        #pragma unroll
        for (int j = 0; j < 3; j++) acc[i][j] = 0.f;

    const int lm = tid >> 3;
    const int lk = (tid & 7) * 8;

    for (int kb = 0; kb < DINNER; kb += 64) {
        __syncthreads();
        #pragma unroll
        for (int j = 0; j < 6; j++) {
            const int idx = tid + j * 256;
            *(float4*)&swl[idx * 4] = *(const float4*)(W_x + (size_t)kb * 96 + idx * 4);
        }
        {
            const float4 v0 = *(const float4*)(g_uc + (size_t)(m0 + lm) * DINNER + kb + lk);
            const float4 v1 = *(const float4*)(g_uc + (size_t)(m0 + lm) * DINNER + kb + lk + 4);
            sut[lk + 0][lm] = v0.x; sut[lk + 1][lm] = v0.y;
            sut[lk + 2][lm] = v0.z; sut[lk + 3][lm] = v0.w;
            sut[lk + 4][lm] = v1.x; sut[lk + 5][lm] = v1.y;
            sut[lk + 6][lm] = v1.z; sut[lk + 7][lm] = v1.w;
        }
        __syncthreads();

        #pragma unroll 4
        for (int r = 0; r < 64; r++) {
            const float4 u4 = *(const float4*)&sut[r][rowg * 4];
            const float w0 = swl[r * 96 + colg * 3 + 0];
            const float w1 = swl[r * 96 + colg * 3 + 1];
            const float w2 = swl[r * 96 + colg * 3 + 2];
            acc[0][0] = fmaf(u4.x, w0, acc[0][0]); acc[0][1] = fmaf(u4.x, w1, acc[0][1]); acc[0][2] = fmaf(u4.x, w2, acc[0][2]);
            acc[1][0] = fmaf(u4.y, w0, acc[1][0]); acc[1][1] = fmaf(u4.y, w1, acc[1][1]); acc[1][2] = fmaf(u4.y, w2, acc[1][2]);
            acc[2][0] = fmaf(u4.z, w0, acc[2][0]); acc[2][1] = fmaf(u4.z, w1, acc[2][1]); acc[2][2] = fmaf(u4.z, w2, acc[2][2]);
            acc[3][0] = fmaf(u4.w, w0, acc[3][0]); acc[3][1] = fmaf(u4.w, w1, acc[3][1]); acc[3][2] = fmaf(u4.w, w2, acc[3][2]);
        }
    }
    #pragma unroll
    for (int i = 0; i < 4; i++)
        #pragma unroll
        for (int j = 0; j < 3; j++)
            g_xdbl[(size_t)(m0 + rowg * 4 + i) * NXP + colg * 3 + j] = acc[i][j];
}

// =================================================================================
// dt_proj v2 + softplus (proven R11 version)
// =================================================================================
__global__ __launch_bounds__(128)
void dtproj_kernel(const float* __restrict__ W_dt, const float* __restrict__ b_dt)
{
    __shared__ float sw[64][128];
    __shared__ float sxt[64][68];
    const int d0 = blockIdx.x * 128;
    const int m0 = blockIdx.y * 64;
    const int tid = threadIdx.x;

    #pragma unroll
    for (int i = 0; i < 64; i++)
        sw[i][tid] = W_dt[(size_t)i * DINNER + d0 + tid];

    {
        const int mi = tid >> 1;
        const int kh = (tid & 1) * 32;
        #pragma unroll
        for (int j = 0; j < 8; j++) {
            const float4 v = *(const float4*)(g_xdbl + (size_t)(m0 + mi) * NXP + kh + j * 4);
            sxt[kh + j * 4 + 0][mi] = v.x;
            sxt[kh + j * 4 + 1][mi] = v.y;
            sxt[kh + j * 4 + 2][mi] = v.z;
            sxt[kh + j * 4 + 3][mi] = v.w;
        }
    }
    __syncthreads();

    float acc[64];
    const float bb = b_dt[d0 + tid];
    #pragma unroll
    for (int mi = 0; mi < 64; mi++) acc[mi] = bb;

    for (int r = 0; r < 64; r++) {
        const float w = sw[r][tid];
        #pragma unroll
        for (int m4 = 0; m4 < 16; m4++) {
            const float4 xv = *(const float4*)&sxt[r][m4 * 4];
            acc[m4 * 4 + 0] = fmaf(xv.x, w, acc[m4 * 4 + 0]);
            acc[m4 * 4 + 1] = fmaf(xv.y, w, acc[m4 * 4 + 1]);
            acc[m4 * 4 + 2] = fmaf(xv.z, w, acc[m4 * 4 + 2]);
            acc[m4 * 4 + 3] = fmaf(xv.w, w, acc[m4 * 4 + 3]);
        }
    }
    #pragma unroll
    for (int mi = 0; mi < 64; mi++) {
        const float z = acc[mi];
        const float sp = (z > 15.f) ? z : log1pf(__expf(z));
        g_delta[(size_t)(m0 + mi) * DINNER + d0 + tid] = sp;
    }
}

// =================================================================================
// Selective scan (proven R11 version): 6-stage cp.async pipeline; epilogue writes
// fp16 hi/lo of y into the g_P u-half of the row.
// =================================================================================
#define TB   16
#define NSTG 6

__global__ __launch_bounds__(128)
void scan_kernel(const float* __restrict__ A_log, const float* __restrict__ Dv)
{
    __shared__ __align__(16) float sdl[NSTG][TB][32];
    __shared__ __align__(16) float suu[NSTG][TB][32];
    __shared__ __align__(16) float srs[NSTG][TB][32];
    __shared__ __align__(16) float sbc[NSTG][TB][32];

    const int b = blockIdx.y;
    const int d0 = blockIdx.x * 32;
    const int tid = threadIdx.x;
    const int w = tid >> 5, lane = tid & 31;
    const int g = lane >> 2, q = lane & 3;
    const int dloc = w * 8 + g;
    const int d = d0 + dloc;
    const int nb = q * 4;

    const float A0 = -__expf(A_log[d * DSTATE + nb + 0]);
    const float A1 = -__expf(A_log[d * DSTATE + nb + 1]);
    const float A2 = -__expf(A_log[d * DSTATE + nb + 2]);
    const float A3 = -__expf(A_log[d * DSTATE + nb + 3]);
    const float Dd = Dv[d];

    const int t_ld = tid >> 3;
    const int seg  = (tid & 7) * 4;

    const size_t mb = (size_t)b * T_LEN;

    const uint32_t a_dl = smem_u32(&sdl[0][t_ld][seg]);
    const uint32_t a_uu = smem_u32(&suu[0][t_ld][seg]);
    const uint32_t a_rs = smem_u32(&srs[0][t_ld][seg]);
    const uint32_t a_bc = smem_u32(&sbc[0][t_ld][seg]);
    const uint32_t stg_bytes = TB * 32 * 4;

    #define SCAN_ISSUE(S, Cc) do {                                                     \
        const size_t _m = mb + (size_t)(Cc) * TB + t_ld;                               \
        cp16(a_dl + (S) * stg_bytes, g_delta + _m * DINNER + d0 + seg);                \
        cp16(a_uu + (S) * stg_bytes, g_uc    + _m * DINNER + d0 + seg);                \
        cp16(a_rs + (S) * stg_bytes, g_P     + _m * DPROJ + DINNER + d0 + seg);        \
        cp16(a_bc + (S) * stg_bytes, g_xdbl  + _m * NXP + DTRANK + seg);               \
        CP_COMMIT();                                                                   \
    } while (0)

    #pragma unroll
    for (int p = 0; p < NSTG; p++) SCAN_ISSUE(p, p);

    float h0 = 0.f, h1 = 0.f, h2 = 0.f, h3 = 0.f;
    constexpr int NCH = T_LEN / TB;

    for (int c = 0; c < NCH; c++) {
        const int S = c % NSTG;
        CP_WAIT5();
        __syncthreads();

        #pragma unroll
        for (int tt = 0; tt < TB; tt++) {
            const float dl = sdl[S][tt][dloc];
            const float uu = suu[S][tt][dloc];
            const float4 Bv = *(const float4*)&sbc[S][tt][nb];
            const float4 Cv = *(const float4*)&sbc[S][tt][16 + nb];

            const float du = dl * uu;
            h0 = fmaf(__expf(dl * A0), h0, du * Bv.x);
            h1 = fmaf(__expf(dl * A1), h1, du * Bv.y);
            h2 = fmaf(__expf(dl * A2), h2, du * Bv.z);
            h3 = fmaf(__expf(dl * A3), h3, du * Bv.w);

            float p = fmaf(h0, Cv.x, fmaf(h1, Cv.y, fmaf(h2, Cv.z, h3 * Cv.w)));
            p += __shfl_xor_sync(0xffffffffu, p, 1);
            p += __shfl_xor_sync(0xffffffffu, p, 2);

            if (q == 0) {
                const float resv = srs[S][tt][dloc];
                const float gate = resv * (1.f / (1.f + __expf(-resv)));
                const float yv = (p + uu * Dd) * gate;
                const __half hv = __float2half_rn(yv);
                const __half lv = __float2half_rn(yv - __half2float(hv));
                __half* rowp = (__half*)g_P + (mb + (size_t)(c * TB + tt)) * (2 * DPROJ);
                rowp[d] = hv;
                rowp[DINNER + d] = lv;
            }
        }
        __syncthreads();
        if (c + NSTG < NCH) { SCAN_ISSUE(S, c + NSTG); }
        else                { CP_COMMIT(); }
    }
}

// =================================================================================
// launch
// =================================================================================
extern "C" void kernel_launch(void* const* d_in, const int* in_sizes, int n_in,
                              void* d_out, int out_size)
{
    const float* x      = (const float*)d_in[0];
    const float* W_in   = (const float*)d_in[1];
    const float* conv_w = (const float*)d_in[2];
    const float* conv_b = (const float*)d_in[3];
    const float* W_x    = (const float*)d_in[4];
    const float* W_dt   = (const float*)d_in[5];
    const float* b_dt   = (const float*)d_in[6];
    const float* A_log  = (const float*)d_in[7];
    const float* Dv     = (const float*)d_in[8];
    const float* W_out  = (const float*)d_in[9];
    float* out = (float*)d_out;

    // --- in_proj (fp16 2-term) ---
    split_x_kernel<<<(M_ROWS * DMODEL / 4) / 256, 256>>>(x);
    splitT_kernel<0><<<dim3(DPROJ / 32, DMODEL / 32), 256>>>(W_in);
    gemm_hmma<0><<<dim3(DPROJ / 128, M_ROWS / 128), 256>>>(nullptr);

    // --- mid pipeline ---
    conv_silu_kernel<<<(B_SZ * (T_LEN / 4) * (DINNER / 4)) / 256, 256>>>(conv_w, conv_b);
    xproj_kernel<<<M_ROWS / 32, 256>>>(W_x);
    dtproj_kernel<<<dim3(DINNER / 128, M_ROWS / 64), 128>>>(W_dt, b_dt);
    splitT_kernel<1><<<dim3(DMODEL / 32, DINNER / 32), 256>>>(W_out);
    scan_kernel<<<dim3(DINNER / 32, B_SZ), 128>>>(A_log, Dv);

    // --- out_proj (fp16 2-term) ---
    gemm_hmma<1><<<dim3(DMODEL / 128, M_ROWS / 128), 256>>>(out);
}

// round 13
// speedup vs baseline: 5.8950x; 1.3111x over previous
#include <cuda_runtime.h>
#include <cuda_bf16.h>
#include <cuda_fp16.h>
#include <math.h>
#include <stdint.h>

#define T_LEN   2048
#define B_SZ    4
#define DMODEL  1024
#define DINNER  2048
#define DSTATE  16
#define DTRANK  64
#define NXP     96
#define M_ROWS  (B_SZ*T_LEN)   // 8192
#define DPROJ   (2*DINNER)     // 4096

// ---------------- scratch (device globals; proven 323MB set) ----------
__device__ __align__(16) float g_P[(size_t)M_ROWS * DPROJ];     // in_proj out; later u-half holds A2 (fp16)
__device__ __align__(16) float g_uc[(size_t)M_ROWS * DINNER];
__device__ __align__(16) float g_xdbl[(size_t)M_ROWS * NXP];
__device__ __align__(16) float g_delta[(size_t)M_ROWS * DINNER];
__device__ __align__(16) float g_y[(size_t)M_ROWS * DINNER];    // backs W2 (fp16) only

// ---- fp16 operands ALIASED into scratch (lifetimes verified disjoint) ----
// A1 (x -> fp16):   g_delta until dtproj writes it
// W1 (W_in^T fp16): g_uc    until conv writes it
// A2 (y -> fp16):   g_P u-half of each row (row stride 2*DPROJ halves), written by scan
// W2 (W_out^T fp16): g_y (free all run)
__device__ __forceinline__ __half* A1H() { return (__half*)g_delta; }
__device__ __forceinline__ __half* W1H() { return (__half*)g_uc; }
__device__ __forceinline__ __half* W2H() { return (__half*)g_y; }

// ---------------- helpers ----------------
__device__ __forceinline__ uint32_t smem_u32(const void* p) {
    uint32_t a;
    asm("{ .reg .u64 t; cvta.to.shared.u64 t, %1; cvt.u32.u64 %0, t; }" : "=r"(a) : "l"(p));
    return a;
}
__device__ __forceinline__ void cp16(uint32_t d, const void* s) {
    asm volatile("cp.async.cg.shared.global [%0], [%1], 16;" :: "r"(d), "l"(s));
}
#define CP_COMMIT() asm volatile("cp.async.commit_group;" ::: "memory")
#define CP_WAIT0()  asm volatile("cp.async.wait_group 0;"  ::: "memory")
#define CP_WAIT1()  asm volatile("cp.async.wait_group 1;"  ::: "memory")
#define CP_WAIT5()  asm volatile("cp.async.wait_group 5;"  ::: "memory")

__device__ __forceinline__ void ldsm4(uint32_t* r, uint32_t a) {
    asm volatile("ldmatrix.sync.aligned.m8n8.x4.shared.b16 {%0,%1,%2,%3}, [%4];"
        : "=r"(r[0]), "=r"(r[1]), "=r"(r[2]), "=r"(r[3]) : "r"(a));
}
__device__ __forceinline__ void mma_fp16(float* c, const uint32_t* a, const uint32_t* b) {
    asm volatile("mma.sync.aligned.m16n8k16.row.col.f32.f16.f16.f32 "
        "{%0,%1,%2,%3}, {%4,%5,%6,%7}, {%8,%9}, {%0,%1,%2,%3};"
        : "+f"(c[0]), "+f"(c[1]), "+f"(c[2]), "+f"(c[3])
        : "r"(a[0]), "r"(a[1]), "r"(a[2]), "r"(a[3]), "r"(b[0]), "r"(b[1]));
}

__device__ __forceinline__ size_t map_tbc(int m, int col) {
    return (size_t)(m & (T_LEN - 1)) * (B_SZ * DMODEL) + (size_t)(m >> 11) * DMODEL + col;
}

// =================================================================================
// Conversion kernels (fp32 -> single fp16)
// =================================================================================
__device__ __forceinline__ void cvt_store4h(float4 v, __half* hp) {
    __half h0 = __float2half_rn(v.x), h1 = __float2half_rn(v.y);
    __half h2 = __float2half_rn(v.z), h3 = __float2half_rn(v.w);
    *(ushort4*)hp = make_ushort4(__half_as_ushort(h0), __half_as_ushort(h1),
                                 __half_as_ushort(h2), __half_as_ushort(h3));
}

__global__ __launch_bounds__(256)
void split_x_kernel(const float* __restrict__ x)
{
    const int q = blockIdx.x * 256 + threadIdx.x;
    const int c = (q & 255) * 4;
    const int m = q >> 8;
    const int t = m & (T_LEN - 1), b = m >> 11;
    float4 v = *(const float4*)(x + (size_t)t * (B_SZ * DMODEL) + b * DMODEL + c);
    cvt_store4h(v, A1H() + (size_t)m * DMODEL + c);
}

// W [K,N] row-major -> W^T [N,K] fp16 single. WHICH=0 -> W1H, WHICH=1 -> W2H.
template<int WHICH>
__global__ __launch_bounds__(256)
void splitT_kernel(const float* __restrict__ W)
{
    constexpr int K = WHICH ? DINNER : DMODEL;
    constexpr int N = WHICH ? DMODEL : DPROJ;
    __shared__ float tile[32][33];
    const int n0 = blockIdx.x * 32, k0 = blockIdx.y * 32;
    const int tid = threadIdx.x;
    #pragma unroll
    for (int p = 0; p < 4; p++) {
        const int idx = tid + p * 256;
        const int kr = idx >> 5, nc = idx & 31;
        tile[kr][nc] = W[(size_t)(k0 + kr) * N + n0 + nc];
    }
    __syncthreads();
    const int nr = tid >> 3;
    const int kq = (tid & 7) * 4;
    float4 v = make_float4(tile[kq + 0][nr], tile[kq + 1][nr], tile[kq + 2][nr], tile[kq + 3][nr]);
    __half* Th = WHICH ? W2H() : W1H();
    cvt_store4h(v, Th + (size_t)(n0 + nr) * K + (k0 + kq));
}

// =================================================================================
// fp16 1-term GEMM via mma.sync: C = A @ B (both rounded to fp16).
// CTA 128x128, K-chunk 16, 2-buffer cp.async, 8 warps of 64x32, 2 smem matrices.
// MODE 0 (in_proj):  g_P = A1 @ W1; N=4096 K=1024; A row stride K.
// MODE 1 (out_proj): out = A2 @ W2; N=1024 K=2048; A2 in g_P u-halves
//         (row stride 2*DPROJ halves); output through map_tbc.
// =================================================================================
#define GROW 48
#define MATB (128 * GROW)
#define STGB (2 * MATB)    // 12288

template<int MODE>
__global__ __launch_bounds__(256)
void gemm_hmma(float* __restrict__ Cparam)
{
    constexpr int N  = MODE ? DMODEL : DPROJ;
    constexpr int K  = MODE ? DINNER : DMODEL;
    constexpr int CH = K / 16;

    __shared__ __align__(16) char smb[2 * STGB];   // 24.6KB static

    const int tid  = threadIdx.x;
    const int lane = tid & 31, wid = tid >> 5;
    const int wm = wid & 1;
    const int wn = wid >> 1;
    const int bm = blockIdx.y * 128;
    const int bn = blockIdx.x * 128;

    const uint16_t* srcA;
    size_t strA;
    if (MODE == 0) {
        srcA = (const uint16_t*)A1H() + (size_t)bm * K;
        strA = K;
    } else {
        srcA = (const uint16_t*)g_P + (size_t)bm * (2 * DPROJ);
        strA = 2 * DPROJ;
    }
    const uint16_t* srcB = (const uint16_t*)(MODE ? W2H() : W1H()) + (size_t)bn * K;

    float* C = MODE ? Cparam : g_P;
    const uint32_t sb = smem_u32(smb);

    const int cmat = tid >> 7;           // 0:A 1:B
    const int cidx = tid & 127;          // 128 threads per matrix
    const uint16_t* csrc = cmat ? srcB : srcA;
    const size_t cstr = cmat ? (size_t)K : strA;

    #define ISSUE(S, CHK) do {                                                   \
        const uint32_t dbase = sb + (uint32_t)(S) * STGB + cmat * MATB;          \
        _Pragma("unroll")                                                        \
        for (int jj = 0; jj < 2; jj++) {                                         \
            const int lin = jj * 128 + cidx;                                     \
            const int r = lin >> 1, cc = lin & 1;                                \
            cp16(dbase + r * GROW + cc * 16,                                     \
                 csrc + (size_t)r * cstr + (CHK) * 16 + cc * 8);                 \
        }                                                                        \
        CP_COMMIT();                                                             \
    } while (0)

    float acc[4][4][4];
    #pragma unroll
    for (int mi = 0; mi < 4; mi++)
        #pragma unroll
        for (int nj = 0; nj < 4; nj++)
            #pragma unroll
            for (int e = 0; e < 4; e++) acc[mi][nj][e] = 0.f;

    ISSUE(0, 0);
    if (CH > 1) ISSUE(1, 1);

    const int lrow = lane & 15;
    const int lcol = (lane >> 4) * 16;

    for (int i = 0; i < CH; i++) {
        const int s = i & 1;
        if (i + 1 < CH) { CP_WAIT1(); } else { CP_WAIT0(); }
        __syncthreads();

        const uint32_t Ab = sb + s * STGB;
        const uint32_t Bb = Ab + MATB;

        uint32_t ar[4][4], br[4][2];
        #pragma unroll
        for (int mi = 0; mi < 4; mi++) {
            const uint32_t off = (uint32_t)(wm * 64 + mi * 16 + lrow) * GROW + lcol;
            ldsm4(ar[mi], Ab + off);
        }
        #pragma unroll
        for (int p = 0; p < 2; p++) {
            const uint32_t off = (uint32_t)(wn * 32 + p * 16 + lrow) * GROW + lcol;
            uint32_t r4[4];
            ldsm4(r4, Bb + off);
            br[2 * p][0] = r4[0]; br[2 * p + 1][0] = r4[1];
            br[2 * p][1] = r4[2]; br[2 * p + 1][1] = r4[3];
        }

        #pragma unroll
        for (int mi = 0; mi < 4; mi++)
            #pragma unroll
            for (int nj = 0; nj < 4; nj++)
                mma_fp16(acc[mi][nj], ar[mi], br[nj]);

        __syncthreads();
        if (i + 2 < CH) ISSUE(s, i + 2);
    }

    const int tg2 = (lane & 3) * 2;
    const int gq  = lane >> 2;
    #pragma unroll
    for (int mi = 0; mi < 4; mi++) {
        const int row0 = bm + wm * 64 + mi * 16 + gq;
        #pragma unroll
        for (int nj = 0; nj < 4; nj++) {
            const int col = bn + wn * 32 + nj * 8 + tg2;
            const size_t o0 = MODE ? map_tbc(row0, col)     : (size_t)row0 * N + col;
            const size_t o1 = MODE ? map_tbc(row0 + 8, col) : (size_t)(row0 + 8) * N + col;
            *(float2*)(C + o0) = make_float2(acc[mi][nj][0], acc[mi][nj][1]);
            *(float2*)(C + o1) = make_float2(acc[mi][nj][2], acc[mi][nj][3]);
        }
    }
}

// =================================================================================
// Depthwise causal conv (k=4) + bias + silu (proven R10 version)
// =================================================================================
__global__ __launch_bounds__(256)
void conv_silu_kernel(const float* __restrict__ cw, const float* __restrict__ cb)
{
    const int q = blockIdx.x * 256 + threadIdx.x;
    const int d  = (q & 511) << 2;
    const int r  = q >> 9;
    const int t0 = (r & 511) << 2;
    const int b  = r >> 9;

    float4 w[4];
    #pragma unroll
    for (int i = 0; i < 4; i++) w[i] = *(const float4*)(cw + (d + i) * 4);
    const float4 cbv = *(const float4*)(cb + d);

    float4 in[7];
    #pragma unroll
    for (int j = 0; j < 7; j++) {
        const int t = t0 + j - 3;
        in[j] = (t >= 0)
            ? *(const float4*)(g_P + (size_t)(b * T_LEN + t) * DPROJ + d)
            : make_float4(0.f, 0.f, 0.f, 0.f);
    }

    #pragma unroll
    for (int j = 0; j < 4; j++) {
        float4 o;
        o.x = cbv.x + w[0].x*in[j].x + w[0].y*in[j+1].x + w[0].z*in[j+2].x + w[0].w*in[j+3].x;
        o.y = cbv.y + w[1].x*in[j].y + w[1].y*in[j+1].y + w[1].z*in[j+2].y + w[1].w*in[j+3].y;
        o.z = cbv.z + w[2].x*in[j].z + w[2].y*in[j+1].z + w[2].z*in[j+2].z + w[2].w*in[j+3].z;
        o.w = cbv.w + w[3].x*in[j].w + w[3].y*in[j+1].w + w[3].z*in[j+2].w + w[3].w*in[j+3].w;
        o.x = o.x * (1.f / (1.f + __expf(-o.x)));
        o.y = o.y * (1.f / (1.f + __expf(-o.y)));
        o.z = o.z * (1.f / (1.f + __expf(-o.z)));
        o.w = o.w * (1.f / (1.f + __expf(-o.w)));
        *(float4*)(g_uc + (size_t)(b * T_LEN + t0 + j) * DINNER + d) = o;
    }
}

// =================================================================================
// x_proj v2 (proven R11 version)
// =================================================================================
__global__ __launch_bounds__(256)
void xproj_kernel(const float* __restrict__ W_x)
{
    __shared__ float swl[64 * 96];
    __shared__ float sut[64][36];
    const int m0 = blockIdx.x * 32;
    const int tid = threadIdx.x;
    const int rowg = tid >> 5;
    const int colg = tid & 31;

    float acc[4][3];
    #pragma unroll
    for (int i = 0; i < 4; i++)
        #pragma unroll
        for (int j = 0; j < 3; j++) acc[i][j] = 0.f;

    const int lm = tid >> 3;
    const int lk = (tid & 7) * 8;

    for (int kb = 0; kb < DINNER; kb += 64) {
        __syncthreads();
        #pragma unroll
        for (int j = 0; j < 6; j++) {
            const int idx = tid + j * 256;
            *(float4*)&swl[idx * 4] = *(const float4*)(W_x + (size_t)kb * 96 + idx * 4);
        }
        {
            const float4 v0 = *(const float4*)(g_uc + (size_t)(m0 + lm) * DINNER + kb + lk);
            const float4 v1 = *(const float4*)(g_uc + (size_t)(m0 + lm) * DINNER + kb + lk + 4);
            sut[lk + 0][lm] = v0.x; sut[lk + 1][lm] = v0.y;
            sut[lk + 2][lm] = v0.z; sut[lk + 3][lm] = v0.w;
            sut[lk + 4][lm] = v1.x; sut[lk + 5][lm] = v1.y;
            sut[lk + 6][lm] = v1.z; sut[lk + 7][lm] = v1.w;
        }
        __syncthreads();

        #pragma unroll 4
        for (int r = 0; r < 64; r++) {
            const float4 u4 = *(const float4*)&sut[r][rowg * 4];
            const float w0 = swl[r * 96 + colg * 3 + 0];
            const float w1 = swl[r * 96 + colg * 3 + 1];
            const float w2 = swl[r * 96 + colg * 3 + 2];
            acc[0][0] = fmaf(u4.x, w0, acc[0][0]); acc[0][1] = fmaf(u4.x, w1, acc[0][1]); acc[0][2] = fmaf(u4.x, w2, acc[0][2]);
            acc[1][0] = fmaf(u4.y, w0, acc[1][0]); acc[1][1] = fmaf(u4.y, w1, acc[1][1]); acc[1][2] = fmaf(u4.y, w2, acc[1][2]);
            acc[2][0] = fmaf(u4.z, w0, acc[2][0]); acc[2][1] = fmaf(u4.z, w1, acc[2][1]); acc[2][2] = fmaf(u4.z, w2, acc[2][2]);
            acc[3][0] = fmaf(u4.w, w0, acc[3][0]); acc[3][1] = fmaf(u4.w, w1, acc[3][1]); acc[3][2] = fmaf(u4.w, w2, acc[3][2]);
        }
    }
    #pragma unroll
    for (int i = 0; i < 4; i++)
        #pragma unroll
        for (int j = 0; j < 3; j++)
            g_xdbl[(size_t)(m0 + rowg * 4 + i) * NXP + colg * 3 + j] = acc[i][j];
}

// =================================================================================
// dt_proj v2 + softplus (proven R11 version)
// =================================================================================
__global__ __launch_bounds__(128)
void dtproj_kernel(const float* __restrict__ W_dt, const float* __restrict__ b_dt)
{
    __shared__ float sw[64][128];
    __shared__ float sxt[64][68];
    const int d0 = blockIdx.x * 128;
    const int m0 = blockIdx.y * 64;
    const int tid = threadIdx.x;

    #pragma unroll
    for (int i = 0; i < 64; i++)
        sw[i][tid] = W_dt[(size_t)i * DINNER + d0 + tid];

    {
        const int mi = tid >> 1;
        const int kh = (tid & 1) * 32;
        #pragma unroll
        for (int j = 0; j < 8; j++) {
            const float4 v = *(const float4*)(g_xdbl + (size_t)(m0 + mi) * NXP + kh + j * 4);
            sxt[kh + j * 4 + 0][mi] = v.x;
            sxt[kh + j * 4 + 1][mi] = v.y;
            sxt[kh + j * 4 + 2][mi] = v.z;
            sxt[kh + j * 4 + 3][mi] = v.w;
        }
    }
    __syncthreads();

    float acc[64];
    const float bb = b_dt[d0 + tid];
    #pragma unroll
    for (int mi = 0; mi < 64; mi++) acc[mi] = bb;

    for (int r = 0; r < 64; r++) {
        const float w = sw[r][tid];
        #pragma unroll
        for (int m4 = 0; m4 < 16; m4++) {
            const float4 xv = *(const float4*)&sxt[r][m4 * 4];
            acc[m4 * 4 + 0] = fmaf(xv.x, w, acc[m4 * 4 + 0]);
            acc[m4 * 4 + 1] = fmaf(xv.y, w, acc[m4 * 4 + 1]);
            acc[m4 * 4 + 2] = fmaf(xv.z, w, acc[m4 * 4 + 2]);
            acc[m4 * 4 + 3] = fmaf(xv.w, w, acc[m4 * 4 + 3]);
        }
    }
    #pragma unroll
    for (int mi = 0; mi < 64; mi++) {
        const float z = acc[mi];
        const float sp = (z > 15.f) ? z : log1pf(__expf(z));
        g_delta[(size_t)(m0 + mi) * DINNER + d0 + tid] = sp;
    }
}

// =================================================================================
// Selective scan: 6-stage cp.async pipeline; epilogue writes single fp16 of y
// into the g_P u-half of the row.
// =================================================================================
#define TB   16
#define NSTG 6

__global__ __launch_bounds__(128)
void scan_kernel(const float* __restrict__ A_log, const float* __restrict__ Dv)
{
    __shared__ __align__(16) float sdl[NSTG][TB][32];
    __shared__ __align__(16) float suu[NSTG][TB][32];
    __shared__ __align__(16) float srs[NSTG][TB][32];
    __shared__ __align__(16) float sbc[NSTG][TB][32];

    const int b = blockIdx.y;
    const int d0 = blockIdx.x * 32;
    const int tid = threadIdx.x;
    const int w = tid >> 5, lane = tid & 31;
    const int g = lane >> 2, q = lane & 3;
    const int dloc = w * 8 + g;
    const int d = d0 + dloc;
    const int nb = q * 4;

    const float A0 = -__expf(A_log[d * DSTATE + nb + 0]);
    const float A1 = -__expf(A_log[d * DSTATE + nb + 1]);
    const float A2 = -__expf(A_log[d * DSTATE + nb + 2]);
    const float A3 = -__expf(A_log[d * DSTATE + nb + 3]);
    const float Dd = Dv[d];

    const int t_ld = tid >> 3;
    const int seg  = (tid & 7) * 4;

    const size_t mb = (size_t)b * T_LEN;

    const uint32_t a_dl = smem_u32(&sdl[0][t_ld][seg]);
    const uint32_t a_uu = smem_u32(&suu[0][t_ld][seg]);
    const uint32_t a_rs = smem_u32(&srs[0][t_ld][seg]);
    const uint32_t a_bc = smem_u32(&sbc[0][t_ld][seg]);
    const uint32_t stg_bytes = TB * 32 * 4;

    #define SCAN_ISSUE(S, Cc) do {                                                     \
        const size_t _m = mb + (size_t)(Cc) * TB + t_ld;                               \
        cp16(a_dl + (S) * stg_bytes, g_delta + _m * DINNER + d0 + seg);                \
        cp16(a_uu + (S) * stg_bytes, g_uc    + _m * DINNER + d0 + seg);                \
        cp16(a_rs + (S) * stg_bytes, g_P     + _m * DPROJ + DINNER + d0 + seg);        \
        cp16(a_bc + (S) * stg_bytes, g_xdbl  + _m * NXP + DTRANK + seg);               \
        CP_COMMIT();                                                                   \
    } while (0)

    #pragma unroll
    for (int p = 0; p < NSTG; p++) SCAN_ISSUE(p, p);

    float h0 = 0.f, h1 = 0.f, h2 = 0.f, h3 = 0.f;
    constexpr int NCH = T_LEN / TB;

    for (int c = 0; c < NCH; c++) {
        const int S = c % NSTG;
        CP_WAIT5();
        __syncthreads();

        #pragma unroll
        for (int tt = 0; tt < TB; tt++) {
            const float dl = sdl[S][tt][dloc];
            const float uu = suu[S][tt][dloc];
            const float4 Bv = *(const float4*)&sbc[S][tt][nb];
            const float4 Cv = *(const float4*)&sbc[S][tt][16 + nb];

            const float du = dl * uu;
            h0 = fmaf(__expf(dl * A0), h0, du * Bv.x);
            h1 = fmaf(__expf(dl * A1), h1, du * Bv.y);
            h2 = fmaf(__expf(dl * A2), h2, du * Bv.z);
            h3 = fmaf(__expf(dl * A3), h3, du * Bv.w);

            float p = fmaf(h0, Cv.x, fmaf(h1, Cv.y, fmaf(h2, Cv.z, h3 * Cv.w)));
            p += __shfl_xor_sync(0xffffffffu, p, 1);
            p += __shfl_xor_sync(0xffffffffu, p, 2);

            if (q == 0) {
                const float resv = srs[S][tt][dloc];
                const float gate = resv * (1.f / (1.f + __expf(-resv)));
                const float yv = (p + uu * Dd) * gate;
                __half* rowp = (__half*)g_P + (mb + (size_t)(c * TB + tt)) * (2 * DPROJ);
                rowp[d] = __float2half_rn(yv);
            }
        }
        __syncthreads();
        if (c + NSTG < NCH) { SCAN_ISSUE(S, c + NSTG); }
        else                { CP_COMMIT(); }
    }
}

// =================================================================================
// launch
// =================================================================================
extern "C" void kernel_launch(void* const* d_in, const int* in_sizes, int n_in,
                              void* d_out, int out_size)
{
    const float* x      = (const float*)d_in[0];
    const float* W_in   = (const float*)d_in[1];
    const float* conv_w = (const float*)d_in[2];
    const float* conv_b = (const float*)d_in[3];
    const float* W_x    = (const float*)d_in[4];
    const float* W_dt   = (const float*)d_in[5];
    const float* b_dt   = (const float*)d_in[6];
    const float* A_log  = (const float*)d_in[7];
    const float* Dv     = (const float*)d_in[8];
    const float* W_out  = (const float*)d_in[9];
    float* out = (float*)d_out;

    // --- in_proj (fp16 1-term) ---
    split_x_kernel<<<(M_ROWS * DMODEL / 4) / 256, 256>>>(x);
    splitT_kernel<0><<<dim3(DPROJ / 32, DMODEL / 32), 256>>>(W_in);
    gemm_hmma<0><<<dim3(DPROJ / 128, M_ROWS / 128), 256>>>(nullptr);

    // --- mid pipeline ---
    conv_silu_kernel<<<(B_SZ * (T_LEN / 4) * (DINNER / 4)) / 256, 256>>>(conv_w, conv_b);
    xproj_kernel<<<M_ROWS / 32, 256>>>(W_x);
    dtproj_kernel<<<dim3(DINNER / 128, M_ROWS / 64), 128>>>(W_dt, b_dt);
    splitT_kernel<1><<<dim3(DMODEL / 32, DINNER / 32), 256>>>(W_out);
    scan_kernel<<<dim3(DINNER / 32, B_SZ), 128>>>(A_log, Dv);

    // --- out_proj (fp16 1-term) ---
    gemm_hmma<1><<<dim3(DMODEL / 128, M_ROWS / 128), 256>>>(out);
}

// round 14
// speedup vs baseline: 7.7169x; 1.3091x over previous
#include <cuda_runtime.h>
#include <cuda_bf16.h>
#include <cuda_fp16.h>
#include <math.h>
#include <stdint.h>

#define T_LEN   2048
#define B_SZ    4
#define DMODEL  1024
#define DINNER  2048
#define DSTATE  16
#define DTRANK  64
#define NXP     96
#define M_ROWS  (B_SZ*T_LEN)   // 8192
#define DPROJ   (2*DINNER)     // 4096

// ---------------- scratch (device globals; proven 323MB set) ----------
__device__ __align__(16) float g_P[(size_t)M_ROWS * DPROJ];     // in_proj out; res->gate in place; u-half later holds A2 (fp16)
__device__ __align__(16) float g_uc[(size_t)M_ROWS * DINNER];
__device__ __align__(16) float g_xdbl[(size_t)M_ROWS * NXP];
__device__ __align__(16) float g_delta[(size_t)M_ROWS * DINNER];
__device__ __align__(16) float g_y[(size_t)M_ROWS * DINNER];    // backs W2 (fp16) only

// ---- fp16 operands ALIASED into scratch (lifetimes verified disjoint) ----
__device__ __forceinline__ __half* A1H() { return (__half*)g_delta; }
__device__ __forceinline__ __half* W1H() { return (__half*)g_uc; }
__device__ __forceinline__ __half* W2H() { return (__half*)g_y; }

// ---------------- helpers ----------------
__device__ __forceinline__ uint32_t smem_u32(const void* p) {
    uint32_t a;
    asm("{ .reg .u64 t; cvta.to.shared.u64 t, %1; cvt.u32.u64 %0, t; }" : "=r"(a) : "l"(p));
    return a;
}
__device__ __forceinline__ void cp16(uint32_t d, const void* s) {
    asm volatile("cp.async.cg.shared.global [%0], [%1], 16;" :: "r"(d), "l"(s));
}
#define CP_COMMIT() asm volatile("cp.async.commit_group;" ::: "memory")
#define CP_WAIT0()  asm volatile("cp.async.wait_group 0;"  ::: "memory")
#define CP_WAIT1()  asm volatile("cp.async.wait_group 1;"  ::: "memory")
#define CP_WAIT5()  asm volatile("cp.async.wait_group 5;"  ::: "memory")

__device__ __forceinline__ void ldsm4(uint32_t* r, uint32_t a) {
    asm volatile("ldmatrix.sync.aligned.m8n8.x4.shared.b16 {%0,%1,%2,%3}, [%4];"
        : "=r"(r[0]), "=r"(r[1]), "=r"(r[2]), "=r"(r[3]) : "r"(a));
}
__device__ __forceinline__ void mma_fp16(float* c, const uint32_t* a, const uint32_t* b) {
    asm volatile("mma.sync.aligned.m16n8k16.row.col.f32.f16.f16.f32 "
        "{%0,%1,%2,%3}, {%4,%5,%6,%7}, {%8,%9}, {%0,%1,%2,%3};"
        : "+f"(c[0]), "+f"(c[1]), "+f"(c[2]), "+f"(c[3])
        : "r"(a[0]), "r"(a[1]), "r"(a[2]), "r"(a[3]), "r"(b[0]), "r"(b[1]));
}

__device__ __forceinline__ size_t map_tbc(int m, int col) {
    return (size_t)(m & (T_LEN - 1)) * (B_SZ * DMODEL) + (size_t)(m >> 11) * DMODEL + col;
}

// =================================================================================
// Conversion kernels (fp32 -> single fp16)
// =================================================================================
__device__ __forceinline__ void cvt_store4h(float4 v, __half* hp) {
    __half h0 = __float2half_rn(v.x), h1 = __float2half_rn(v.y);
    __half h2 = __float2half_rn(v.z), h3 = __float2half_rn(v.w);
    *(ushort4*)hp = make_ushort4(__half_as_ushort(h0), __half_as_ushort(h1),
                                 __half_as_ushort(h2), __half_as_ushort(h3));
}

__global__ __launch_bounds__(256)
void split_x_kernel(const float* __restrict__ x)
{
    const int q = blockIdx.x * 256 + threadIdx.x;
    const int c = (q & 255) * 4;
    const int m = q >> 8;
    const int t = m & (T_LEN - 1), b = m >> 11;
    float4 v = *(const float4*)(x + (size_t)t * (B_SZ * DMODEL) + b * DMODEL + c);
    cvt_store4h(v, A1H() + (size_t)m * DMODEL + c);
}

template<int WHICH>
__global__ __launch_bounds__(256)
void splitT_kernel(const float* __restrict__ W)
{
    constexpr int K = WHICH ? DINNER : DMODEL;
    constexpr int N = WHICH ? DMODEL : DPROJ;
    __shared__ float tile[32][33];
    const int n0 = blockIdx.x * 32, k0 = blockIdx.y * 32;
    const int tid = threadIdx.x;
    #pragma unroll
    for (int p = 0; p < 4; p++) {
        const int idx = tid + p * 256;
        const int kr = idx >> 5, nc = idx & 31;
        tile[kr][nc] = W[(size_t)(k0 + kr) * N + n0 + nc];
    }
    __syncthreads();
    const int nr = tid >> 3;
    const int kq = (tid & 7) * 4;
    float4 v = make_float4(tile[kq + 0][nr], tile[kq + 1][nr], tile[kq + 2][nr], tile[kq + 3][nr]);
    __half* Th = WHICH ? W2H() : W1H();
    cvt_store4h(v, Th + (size_t)(n0 + nr) * K + (k0 + kq));
}

// =================================================================================
// fp16 1-term GEMM via mma.sync. K-chunk 32, GROW=80 rows, 2 mats, 2 stages (40KB).
// MODE 0 (in_proj):  g_P = A1 @ W1; N=4096 K=1024.
// MODE 1 (out_proj): out = A2 @ W2; N=1024 K=2048; A2 in g_P u-halves
//         (row stride 2*DPROJ halves); output through map_tbc.
// =================================================================================
#define GROW 80                      // 64B data + 16B pad
#define MATB (128 * GROW)            // 10240
#define STGB (2 * MATB)              // 20480

template<int MODE>
__global__ __launch_bounds__(256)
void gemm_hmma(float* __restrict__ Cparam)
{
    constexpr int N  = MODE ? DMODEL : DPROJ;
    constexpr int K  = MODE ? DINNER : DMODEL;
    constexpr int CH = K / 32;

    __shared__ __align__(16) char smb[2 * STGB];   // 40KB static

    const int tid  = threadIdx.x;
    const int lane = tid & 31, wid = tid >> 5;
    const int wm = wid & 1;
    const int wn = wid >> 1;
    const int bm = blockIdx.y * 128;
    const int bn = blockIdx.x * 128;

    const uint16_t* srcA;
    size_t strA;
    if (MODE == 0) {
        srcA = (const uint16_t*)A1H() + (size_t)bm * K;
        strA = K;
    } else {
        srcA = (const uint16_t*)g_P + (size_t)bm * (2 * DPROJ);
        strA = 2 * DPROJ;
    }
    const uint16_t* srcB = (const uint16_t*)(MODE ? W2H() : W1H()) + (size_t)bn * K;

    float* C = MODE ? Cparam : g_P;
    const uint32_t sb = smem_u32(smb);

    const int cmat = tid >> 7;           // 0:A 1:B
    const int cidx = tid & 127;
    const uint16_t* csrc = cmat ? srcB : srcA;
    const size_t cstr = cmat ? (size_t)K : strA;

    // per stage: 2 mats x 128 rows x 64B = 1024 cp16; 4 per thread
    #define ISSUE(S, CHK) do {                                                   \
        const uint32_t dbase = sb + (uint32_t)(S) * STGB + cmat * MATB;          \
        _Pragma("unroll")                                                        \
        for (int jj = 0; jj < 4; jj++) {                                         \
            const int lin = jj * 128 + cidx;                                     \
            const int r = lin >> 2, cc = lin & 3;                                \
            cp16(dbase + r * GROW + cc * 16,                                     \
                 csrc + (size_t)r * cstr + (CHK) * 32 + cc * 8);                 \
        }                                                                        \
        CP_COMMIT();                                                             \
    } while (0)

    float acc[4][4][4];
    #pragma unroll
    for (int mi = 0; mi < 4; mi++)
        #pragma unroll
        for (int nj = 0; nj < 4; nj++)
            #pragma unroll
            for (int e = 0; e < 4; e++) acc[mi][nj][e] = 0.f;

    ISSUE(0, 0);
    if (CH > 1) ISSUE(1, 1);

    const int lrow = lane & 15;
    const int lsel = (lane >> 4) * 16;

    for (int i = 0; i < CH; i++) {
        const int s = i & 1;
        if (i + 1 < CH) { CP_WAIT1(); } else { CP_WAIT0(); }
        __syncthreads();

        const uint32_t Ab = sb + s * STGB;
        const uint32_t Bb = Ab + MATB;

        #pragma unroll
        for (int ks = 0; ks < 2; ks++) {
            const int kb = ks * 32 + lsel;
            uint32_t ar[4][4], br[4][2];
            #pragma unroll
            for (int mi = 0; mi < 4; mi++) {
                const uint32_t off = (uint32_t)(wm * 64 + mi * 16 + lrow) * GROW + kb;
                ldsm4(ar[mi], Ab + off);
            }
            #pragma unroll
            for (int p = 0; p < 2; p++) {
                const uint32_t off = (uint32_t)(wn * 32 + p * 16 + lrow) * GROW + kb;
                uint32_t r4[4];
                ldsm4(r4, Bb + off);
                br[2 * p][0] = r4[0]; br[2 * p + 1][0] = r4[1];
                br[2 * p][1] = r4[2]; br[2 * p + 1][1] = r4[3];
            }
            #pragma unroll
            for (int mi = 0; mi < 4; mi++)
                #pragma unroll
                for (int nj = 0; nj < 4; nj++)
                    mma_fp16(acc[mi][nj], ar[mi], br[nj]);
        }

        __syncthreads();
        if (i + 2 < CH) ISSUE(s, i + 2);
    }

    const int tg2 = (lane & 3) * 2;
    const int gq  = lane >> 2;
    #pragma unroll
    for (int mi = 0; mi < 4; mi++) {
        const int row0 = bm + wm * 64 + mi * 16 + gq;
        #pragma unroll
        for (int nj = 0; nj < 4; nj++) {
            const int col = bn + wn * 32 + nj * 8 + tg2;
            const size_t o0 = MODE ? map_tbc(row0, col)     : (size_t)row0 * N + col;
            const size_t o1 = MODE ? map_tbc(row0 + 8, col) : (size_t)(row0 + 8) * N + col;
            *(float2*)(C + o0) = make_float2(acc[mi][nj][0], acc[mi][nj][1]);
            *(float2*)(C + o1) = make_float2(acc[mi][nj][2], acc[mi][nj][3]);
        }
    }
}

// =================================================================================
// Depthwise causal conv (k=4) + bias + silu on u-half; ALSO gate = silu(res)
// written in place over the res-half (disjoint columns -> race-free).
// =================================================================================
__global__ __launch_bounds__(256)
void conv_silu_kernel(const float* __restrict__ cw, const float* __restrict__ cb)
{
    const int q = blockIdx.x * 256 + threadIdx.x;
    const int d  = (q & 511) << 2;
    const int r  = q >> 9;
    const int t0 = (r & 511) << 2;
    const int b  = r >> 9;

    float4 w[4];
    #pragma unroll
    for (int i = 0; i < 4; i++) w[i] = *(const float4*)(cw + (d + i) * 4);
    const float4 cbv = *(const float4*)(cb + d);

    float4 in[7];
    #pragma unroll
    for (int j = 0; j < 7; j++) {
        const int t = t0 + j - 3;
        in[j] = (t >= 0)
            ? *(const float4*)(g_P + (size_t)(b * T_LEN + t) * DPROJ + d)
            : make_float4(0.f, 0.f, 0.f, 0.f);
    }

    #pragma unroll
    for (int j = 0; j < 4; j++) {
        float4 o;
        o.x = cbv.x + w[0].x*in[j].x + w[0].y*in[j+1].x + w[0].z*in[j+2].x + w[0].w*in[j+3].x;
        o.y = cbv.y + w[1].x*in[j].y + w[1].y*in[j+1].y + w[1].z*in[j+2].y + w[1].w*in[j+3].y;
        o.z = cbv.z + w[2].x*in[j].z + w[2].y*in[j+1].z + w[2].z*in[j+2].z + w[2].w*in[j+3].z;
        o.w = cbv.w + w[3].x*in[j].w + w[3].y*in[j+1].w + w[3].z*in[j+2].w + w[3].w*in[j+3].w;
        o.x = o.x * (1.f / (1.f + __expf(-o.x)));
        o.y = o.y * (1.f / (1.f + __expf(-o.y)));
        o.z = o.z * (1.f / (1.f + __expf(-o.z)));
        o.w = o.w * (1.f / (1.f + __expf(-o.w)));
        *(float4*)(g_uc + (size_t)(b * T_LEN + t0 + j) * DINNER + d) = o;
    }

    // gate = silu(res), in place
    #pragma unroll
    for (int j = 0; j < 4; j++) {
        float* rp = g_P + (size_t)(b * T_LEN + t0 + j) * DPROJ + DINNER + d;
        float4 rv = *(const float4*)rp;
        rv.x = rv.x * (1.f / (1.f + __expf(-rv.x)));
        rv.y = rv.y * (1.f / (1.f + __expf(-rv.y)));
        rv.z = rv.z * (1.f / (1.f + __expf(-rv.z)));
        rv.w = rv.w * (1.f / (1.f + __expf(-rv.w)));
        *(float4*)rp = rv;
    }
}

// =================================================================================
// x_proj v2 (proven R11 version)
// =================================================================================
__global__ __launch_bounds__(256)
void xproj_kernel(const float* __restrict__ W_x)
{
    __shared__ float swl[64 * 96];
    __shared__ float sut[64][36];
    const int m0 = blockIdx.x * 32;
    const int tid = threadIdx.x;
    const int rowg = tid >> 5;
    const int colg = tid & 31;

    float acc[4][3];
    #pragma unroll
    for (int i = 0; i < 4; i++)
        #pragma unroll
        for (int j = 0; j < 3; j++) acc[i][j] = 0.f;

    const int lm = tid >> 3;
    const int lk = (tid & 7) * 8;

    for (int kb = 0; kb < DINNER; kb += 64) {
        __syncthreads();
        #pragma unroll
        for (int j = 0; j < 6; j++) {
            const int idx = tid + j * 256;
            *(float4*)&swl[idx * 4] = *(const float4*)(W_x + (size_t)kb * 96 + idx * 4);
        }
        {
            const float4 v0 = *(const float4*)(g_uc + (size_t)(m0 + lm) * DINNER + kb + lk);
            const float4 v1 = *(const float4*)(g_uc + (size_t)(m0 + lm) * DINNER + kb + lk + 4);
            sut[lk + 0][lm] = v0.x; sut[lk + 1][lm] = v0.y;
            sut[lk + 2][lm] = v0.z; sut[lk + 3][lm] = v0.w;
            sut[lk + 4][lm] = v1.x; sut[lk + 5][lm] = v1.y;
            sut[lk + 6][lm] = v1.z; sut[lk + 7][lm] = v1.w;
        }
        __syncthreads();

        #pragma unroll 4
        for (int r = 0; r < 64; r++) {
            const float4 u4 = *(const float4*)&sut[r][rowg * 4];
            const float w0 = swl[r * 96 + colg * 3 + 0];
            const float w1 = swl[r * 96 + colg * 3 + 1];
            const float w2 = swl[r * 96 + colg * 3 + 2];
            acc[0][0] = fmaf(u4.x, w0, acc[0][0]); acc[0][1] = fmaf(u4.x, w1, acc[0][1]); acc[0][2] = fmaf(u4.x, w2, acc[0][2]);
            acc[1][0] = fmaf(u4.y, w0, acc[1][0]); acc[1][1] = fmaf(u4.y, w1, acc[1][1]); acc[1][2] = fmaf(u4.y, w2, acc[1][2]);
            acc[2][0] = fmaf(u4.z, w0, acc[2][0]); acc[2][1] = fmaf(u4.z, w1, acc[2][1]); acc[2][2] = fmaf(u4.z, w2, acc[2][2]);
            acc[3][0] = fmaf(u4.w, w0, acc[3][0]); acc[3][1] = fmaf(u4.w, w1, acc[3][1]); acc[3][2] = fmaf(u4.w, w2, acc[3][2]);
        }
    }
    #pragma unroll
    for (int i = 0; i < 4; i++)
        #pragma unroll
        for (int j = 0; j < 3; j++)
            g_xdbl[(size_t)(m0 + rowg * 4 + i) * NXP + colg * 3 + j] = acc[i][j];
}

// =================================================================================
// dt_proj v2 + softplus (proven R11 version)
// =================================================================================
__global__ __launch_bounds__(128)
void dtproj_kernel(const float* __restrict__ W_dt, const float* __restrict__ b_dt)
{
    __shared__ float sw[64][128];
    __shared__ float sxt[64][68];
    const int d0 = blockIdx.x * 128;
    const int m0 = blockIdx.y * 64;
    const int tid = threadIdx.x;

    #pragma unroll
    for (int i = 0; i < 64; i++)
        sw[i][tid] = W_dt[(size_t)i * DINNER + d0 + tid];

    {
        const int mi = tid >> 1;
        const int kh = (tid & 1) * 32;
        #pragma unroll
        for (int j = 0; j < 8; j++) {
            const float4 v = *(const float4*)(g_xdbl + (size_t)(m0 + mi) * NXP + kh + j * 4);
            sxt[kh + j * 4 + 0][mi] = v.x;
            sxt[kh + j * 4 + 1][mi] = v.y;
            sxt[kh + j * 4 + 2][mi] = v.z;
            sxt[kh + j * 4 + 3][mi] = v.w;
        }
    }
    __syncthreads();

    float acc[64];
    const float bb = b_dt[d0 + tid];
    #pragma unroll
    for (int mi = 0; mi < 64; mi++) acc[mi] = bb;

    for (int r = 0; r < 64; r++) {
        const float w = sw[r][tid];
        #pragma unroll
        for (int m4 = 0; m4 < 16; m4++) {
            const float4 xv = *(const float4*)&sxt[r][m4 * 4];
            acc[m4 * 4 + 0] = fmaf(xv.x, w, acc[m4 * 4 + 0]);
            acc[m4 * 4 + 1] = fmaf(xv.y, w, acc[m4 * 4 + 1]);
            acc[m4 * 4 + 2] = fmaf(xv.z, w, acc[m4 * 4 + 2]);
            acc[m4 * 4 + 3] = fmaf(xv.w, w, acc[m4 * 4 + 3]);
        }
    }
    #pragma unroll
    for (int mi = 0; mi < 64; mi++) {
        const float z = acc[mi];
        const float sp = (z > 15.f) ? z : log1pf(__expf(z));
        g_delta[(size_t)(m0 + mi) * DINNER + d0 + tid] = sp;
    }
}

// =================================================================================
// Selective scan: 6-stage cp.async pipeline; gate preloaded (srs holds silu(res));
// epilogue writes single fp16 of y into the g_P u-half of the row.
// =================================================================================
#define TB   16
#define NSTG 6

__global__ __launch_bounds__(128)
void scan_kernel(const float* __restrict__ A_log, const float* __restrict__ Dv)
{
    __shared__ __align__(16) float sdl[NSTG][TB][32];
    __shared__ __align__(16) float suu[NSTG][TB][32];
    __shared__ __align__(16) float srs[NSTG][TB][32];
    __shared__ __align__(16) float sbc[NSTG][TB][32];

    const int b = blockIdx.y;
    const int d0 = blockIdx.x * 32;
    const int tid = threadIdx.x;
    const int w = tid >> 5, lane = tid & 31;
    const int g = lane >> 2, q = lane & 3;
    const int dloc = w * 8 + g;
    const int d = d0 + dloc;
    const int nb = q * 4;

    const float A0 = -__expf(A_log[d * DSTATE + nb + 0]);
    const float A1 = -__expf(A_log[d * DSTATE + nb + 1]);
    const float A2 = -__expf(A_log[d * DSTATE + nb + 2]);
    const float A3 = -__expf(A_log[d * DSTATE + nb + 3]);
    const float Dd = Dv[d];

    const int t_ld = tid >> 3;
    const int seg  = (tid & 7) * 4;

    const size_t mb = (size_t)b * T_LEN;

    const uint32_t a_dl = smem_u32(&sdl[0][t_ld][seg]);
    const uint32_t a_uu = smem_u32(&suu[0][t_ld][seg]);
    const uint32_t a_rs = smem_u32(&srs[0][t_ld][seg]);
    const uint32_t a_bc = smem_u32(&sbc[0][t_ld][seg]);
    const uint32_t stg_bytes = TB * 32 * 4;

    #define SCAN_ISSUE(S, Cc) do {                                                     \
        const size_t _m = mb + (size_t)(Cc) * TB + t_ld;                               \
        cp16(a_dl + (S) * stg_bytes, g_delta + _m * DINNER + d0 + seg);                \
        cp16(a_uu + (S) * stg_bytes, g_uc    + _m * DINNER + d0 + seg);                \
        cp16(a_rs + (S) * stg_bytes, g_P     + _m * DPROJ + DINNER + d0 + seg);        \
        cp16(a_bc + (S) * stg_bytes, g_xdbl  + _m * NXP + DTRANK + seg);               \
        CP_COMMIT();                                                                   \
    } while (0)

    #pragma unroll
    for (int p = 0; p < NSTG; p++) SCAN_ISSUE(p, p);

    float h0 = 0.f, h1 = 0.f, h2 = 0.f, h3 = 0.f;
    constexpr int NCH = T_LEN / TB;

    for (int c = 0; c < NCH; c++) {
        const int S = c % NSTG;
        CP_WAIT5();
        __syncthreads();

        #pragma unroll
        for (int tt = 0; tt < TB; tt++) {
            const float dl = sdl[S][tt][dloc];
            const float uu = suu[S][tt][dloc];
            const float4 Bv = *(const float4*)&sbc[S][tt][nb];
            const float4 Cv = *(const float4*)&sbc[S][tt][16 + nb];

            const float du = dl * uu;
            h0 = fmaf(__expf(dl * A0), h0, du * Bv.x);
            h1 = fmaf(__expf(dl * A1), h1, du * Bv.y);
            h2 = fmaf(__expf(dl * A2), h2, du * Bv.z);
            h3 = fmaf(__expf(dl * A3), h3, du * Bv.w);

            float p = fmaf(h0, Cv.x, fmaf(h1, Cv.y, fmaf(h2, Cv.z, h3 * Cv.w)));
            p += __shfl_xor_sync(0xffffffffu, p, 1);
            p += __shfl_xor_sync(0xffffffffu, p, 2);

            if (q == 0) {
                const float gate = srs[S][tt][dloc];   // precomputed silu(res)
                const float yv = fmaf(uu, Dd, p) * gate;
                __half* rowp = (__half*)g_P + (mb + (size_t)(c * TB + tt)) * (2 * DPROJ);
                rowp[d] = __float2half_rn(yv);
            }
        }
        __syncthreads();
        if (c + NSTG < NCH) { SCAN_ISSUE(S, c + NSTG); }
        else                { CP_COMMIT(); }
    }
}

// =================================================================================
// launch
// =================================================================================
extern "C" void kernel_launch(void* const* d_in, const int* in_sizes, int n_in,
                              void* d_out, int out_size)
{
    const float* x      = (const float*)d_in[0];
    const float* W_in   = (const float*)d_in[1];
    const float* conv_w = (const float*)d_in[2];
    const float* conv_b = (const float*)d_in[3];
    const float* W_x    = (const float*)d_in[4];
    const float* W_dt   = (const float*)d_in[5];
    const float* b_dt   = (const float*)d_in[6];
    const float* A_log  = (const float*)d_in[7];
    const float* Dv     = (const float*)d_in[8];
    const float* W_out  = (const float*)d_in[9];
    float* out = (float*)d_out;

    // --- in_proj (fp16 1-term) ---
    split_x_kernel<<<(M_ROWS * DMODEL / 4) / 256, 256>>>(x);
    splitT_kernel<0><<<dim3(DPROJ / 32, DMODEL / 32), 256>>>(W_in);
    gemm_hmma<0><<<dim3(DPROJ / 128, M_ROWS / 128), 256>>>(nullptr);

    // --- mid pipeline ---
    conv_silu_kernel<<<(B_SZ * (T_LEN / 4) * (DINNER / 4)) / 256, 256>>>(conv_w, conv_b);
    xproj_kernel<<<M_ROWS / 32, 256>>>(W_x);
    dtproj_kernel<<<dim3(DINNER / 128, M_ROWS / 64), 128>>>(W_dt, b_dt);
    splitT_kernel<1><<<dim3(DMODEL / 32, DINNER / 32), 256>>>(W_out);
    scan_kernel<<<dim3(DINNER / 32, B_SZ), 128>>>(A_log, Dv);

    // --- out_proj (fp16 1-term) ---
    gemm_hmma<1><<<dim3(DMODEL / 128, M_ROWS / 128), 256>>>(out);
}

// round 15
// speedup vs baseline: 9.0810x; 1.1768x over previous
#include <cuda_runtime.h>
#include <cuda_bf16.h>
#include <cuda_fp16.h>
#include <math.h>
#include <stdint.h>

#define T_LEN   2048
#define B_SZ    4
#define DMODEL  1024
#define DINNER  2048
#define DSTATE  16
#define DTRANK  64
#define NXP     96
#define M_ROWS  (B_SZ*T_LEN)   // 8192
#define DPROJ   (2*DINNER)     // 4096

// ---------------- scratch (device globals; proven 323MB set) ----------
__device__ __align__(16) float g_P[(size_t)M_ROWS * DPROJ];     // in_proj out; res->gate in place; u-half later A2 fp16
__device__ __align__(16) float g_uc[(size_t)M_ROWS * DINNER];
__device__ __align__(16) float g_xdbl[(size_t)M_ROWS * NXP];
__device__ __align__(16) float g_delta[(size_t)M_ROWS * DINNER];
__device__ __align__(16) float g_y[(size_t)M_ROWS * DINNER];

// ---- fp16 operands ALIASED into scratch (lifetimes verified disjoint) ----
// A1 (x fp16):       g_delta, consumed by gemm0; then U16 (u fp16) written by conv,
//                    consumed by xproj; then dtproj overwrites g_delta with delta fp32.
// W1 (W_in^T fp16):  g_uc until conv writes it
// A2 (y fp16):       g_P u-halves, written by scan
// g_y halves layout: [0,2.1M) W2H | [4M,+262K) WXT16 | [8M,+131K) WDT16 | [12M,+524K) XDT16
__device__ __forceinline__ __half* A1H()   { return (__half*)g_delta; }
__device__ __forceinline__ __half* U16()   { return (__half*)g_delta; }
__device__ __forceinline__ __half* W1H()   { return (__half*)g_uc; }
__device__ __forceinline__ __half* W2H()   { return (__half*)g_y; }
__device__ __forceinline__ __half* WXT16() { return (__half*)g_y + 4194304; }   // [128][2048]
__device__ __forceinline__ __half* WDT16() { return (__half*)g_y + 8388608; }   // [2048][64]
__device__ __forceinline__ __half* XDT16() { return (__half*)g_y + 12582912; }  // [8192][64]

// ---------------- helpers ----------------
__device__ __forceinline__ uint32_t smem_u32(const void* p) {
    uint32_t a;
    asm("{ .reg .u64 t; cvta.to.shared.u64 t, %1; cvt.u32.u64 %0, t; }" : "=r"(a) : "l"(p));
    return a;
}
__device__ __forceinline__ void cp16(uint32_t d, const void* s) {
    asm volatile("cp.async.cg.shared.global [%0], [%1], 16;" :: "r"(d), "l"(s));
}
#define CP_COMMIT() asm volatile("cp.async.commit_group;" ::: "memory")
#define CP_WAIT0()  asm volatile("cp.async.wait_group 0;"  ::: "memory")
#define CP_WAIT1()  asm volatile("cp.async.wait_group 1;"  ::: "memory")
#define CP_WAIT5()  asm volatile("cp.async.wait_group 5;"  ::: "memory")

__device__ __forceinline__ void ldsm4(uint32_t* r, uint32_t a) {
    asm volatile("ldmatrix.sync.aligned.m8n8.x4.shared.b16 {%0,%1,%2,%3}, [%4];"
        : "=r"(r[0]), "=r"(r[1]), "=r"(r[2]), "=r"(r[3]) : "r"(a));
}
__device__ __forceinline__ void mma_fp16(float* c, const uint32_t* a, const uint32_t* b) {
    asm volatile("mma.sync.aligned.m16n8k16.row.col.f32.f16.f16.f32 "
        "{%0,%1,%2,%3}, {%4,%5,%6,%7}, {%8,%9}, {%0,%1,%2,%3};"
        : "+f"(c[0]), "+f"(c[1]), "+f"(c[2]), "+f"(c[3])
        : "r"(a[0]), "r"(a[1]), "r"(a[2]), "r"(a[3]), "r"(b[0]), "r"(b[1]));
}

__device__ __forceinline__ size_t map_tbc(int m, int col) {
    return (size_t)(m & (T_LEN - 1)) * (B_SZ * DMODEL) + (size_t)(m >> 11) * DMODEL + col;
}

// =================================================================================
// Conversion / prep kernels
// =================================================================================
__device__ __forceinline__ void cvt_store4h(float4 v, __half* hp) {
    __half h0 = __float2half_rn(v.x), h1 = __float2half_rn(v.y);
    __half h2 = __float2half_rn(v.z), h3 = __float2half_rn(v.w);
    *(ushort4*)hp = make_ushort4(__half_as_ushort(h0), __half_as_ushort(h1),
                                 __half_as_ushort(h2), __half_as_ushort(h3));
}

__global__ __launch_bounds__(256)
void split_x_kernel(const float* __restrict__ x)
{
    const int q = blockIdx.x * 256 + threadIdx.x;
    const int c = (q & 255) * 4;
    const int m = q >> 8;
    const int t = m & (T_LEN - 1), b = m >> 11;
    float4 v = *(const float4*)(x + (size_t)t * (B_SZ * DMODEL) + b * DMODEL + c);
    cvt_store4h(v, A1H() + (size_t)m * DMODEL + c);
}

template<int WHICH>
__global__ __launch_bounds__(256)
void splitT_kernel(const float* __restrict__ W)
{
    constexpr int K = WHICH ? DINNER : DMODEL;
    constexpr int N = WHICH ? DMODEL : DPROJ;
    __shared__ float tile[32][33];
    const int n0 = blockIdx.x * 32, k0 = blockIdx.y * 32;
    const int tid = threadIdx.x;
    #pragma unroll
    for (int p = 0; p < 4; p++) {
        const int idx = tid + p * 256;
        const int kr = idx >> 5, nc = idx & 31;
        tile[kr][nc] = W[(size_t)(k0 + kr) * N + n0 + nc];
    }
    __syncthreads();
    const int nr = tid >> 3;
    const int kq = (tid & 7) * 4;
    float4 v = make_float4(tile[kq + 0][nr], tile[kq + 1][nr], tile[kq + 2][nr], tile[kq + 3][nr]);
    __half* Th = WHICH ? W2H() : W1H();
    cvt_store4h(v, Th + (size_t)(n0 + nr) * K + (k0 + kq));
}

// W_x [2048][96] -> WXT16 [128][2048] fp16, rows 96..127 zero
__global__ __launch_bounds__(256)
void prep_wx_kernel(const float* __restrict__ W_x)
{
    const int idx = blockIdx.x * 256 + threadIdx.x;   // 128*2048 = 262144
    const int n = idx >> 11, k = idx & 2047;
    const float v = (n < NXP) ? W_x[(size_t)k * NXP + n] : 0.f;
    WXT16()[idx] = __float2half_rn(v);
}

// W_dt [64][2048] -> WDT16 [2048][64] fp16
__global__ __launch_bounds__(256)
void prep_wdt_kernel(const float* __restrict__ W_dt)
{
    const int idx = blockIdx.x * 256 + threadIdx.x;   // 2048*64 = 131072
    const int n = idx >> 6, k = idx & 63;
    WDT16()[idx] = __float2half_rn(W_dt[(size_t)k * DINNER + n]);
}

// =================================================================================
// fp16 1-term GEMM (proven R14). K-chunk 32, GROW=80, 2 mats, 2 stages.
// MODE 0 (in_proj):  g_P = A1 @ W1; N=4096 K=1024.
// MODE 1 (out_proj): out = A2 @ W2; N=1024 K=2048; A2 in g_P u-halves; map_tbc out.
// =================================================================================
#define GROW 80
#define MATB (128 * GROW)
#define STGB (2 * MATB)

template<int MODE>
__global__ __launch_bounds__(256)
void gemm_hmma(float* __restrict__ Cparam)
{
    constexpr int N  = MODE ? DMODEL : DPROJ;
    constexpr int K  = MODE ? DINNER : DMODEL;
    constexpr int CH = K / 32;

    __shared__ __align__(16) char smb[2 * STGB];

    const int tid  = threadIdx.x;
    const int lane = tid & 31, wid = tid >> 5;
    const int wm = wid & 1;
    const int wn = wid >> 1;
    const int bm = blockIdx.y * 128;
    const int bn = blockIdx.x * 128;

    const uint16_t* srcA;
    size_t strA;
    if (MODE == 0) {
        srcA = (const uint16_t*)A1H() + (size_t)bm * K;
        strA = K;
    } else {
        srcA = (const uint16_t*)g_P + (size_t)bm * (2 * DPROJ);
        strA = 2 * DPROJ;
    }
    const uint16_t* srcB = (const uint16_t*)(MODE ? W2H() : W1H()) + (size_t)bn * K;

    float* C = MODE ? Cparam : g_P;
    const uint32_t sb = smem_u32(smb);

    const int cmat = tid >> 7;
    const int cidx = tid & 127;
    const uint16_t* csrc = cmat ? srcB : srcA;
    const size_t cstr = cmat ? (size_t)K : strA;

    #define ISSUE(S, CHK) do {                                                   \
        const uint32_t dbase = sb + (uint32_t)(S) * STGB + cmat * MATB;          \
        _Pragma("unroll")                                                        \
        for (int jj = 0; jj < 4; jj++) {                                         \
            const int lin = jj * 128 + cidx;                                     \
            const int r = lin >> 2, cc = lin & 3;                                \
            cp16(dbase + r * GROW + cc * 16,                                     \
                 csrc + (size_t)r * cstr + (CHK) * 32 + cc * 8);                 \
        }                                                                        \
        CP_COMMIT();                                                             \
    } while (0)

    float acc[4][4][4];
    #pragma unroll
    for (int mi = 0; mi < 4; mi++)
        #pragma unroll
        for (int nj = 0; nj < 4; nj++)
            #pragma unroll
            for (int e = 0; e < 4; e++) acc[mi][nj][e] = 0.f;

    ISSUE(0, 0);
    if (CH > 1) ISSUE(1, 1);

    const int lrow = lane & 15;
    const int lsel = (lane >> 4) * 16;

    for (int i = 0; i < CH; i++) {
        const int s = i & 1;
        if (i + 1 < CH) { CP_WAIT1(); } else { CP_WAIT0(); }
        __syncthreads();

        const uint32_t Ab = sb + s * STGB;
        const uint32_t Bb = Ab + MATB;

        #pragma unroll
        for (int ks = 0; ks < 2; ks++) {
            const int kb = ks * 32 + lsel;
            uint32_t ar[4][4], br[4][2];
            #pragma unroll
            for (int mi = 0; mi < 4; mi++) {
                const uint32_t off = (uint32_t)(wm * 64 + mi * 16 + lrow) * GROW + kb;
                ldsm4(ar[mi], Ab + off);
            }
            #pragma unroll
            for (int p = 0; p < 2; p++) {
                const uint32_t off = (uint32_t)(wn * 32 + p * 16 + lrow) * GROW + kb;
                uint32_t r4[4];
                ldsm4(r4, Bb + off);
                br[2 * p][0] = r4[0]; br[2 * p + 1][0] = r4[1];
                br[2 * p][1] = r4[2]; br[2 * p + 1][1] = r4[3];
            }
            #pragma unroll
            for (int mi = 0; mi < 4; mi++)
                #pragma unroll
                for (int nj = 0; nj < 4; nj++)
                    mma_fp16(acc[mi][nj], ar[mi], br[nj]);
        }

        __syncthreads();
        if (i + 2 < CH) ISSUE(s, i + 2);
    }

    const int tg2 = (lane & 3) * 2;
    const int gq  = lane >> 2;
    #pragma unroll
    for (int mi = 0; mi < 4; mi++) {
        const int row0 = bm + wm * 64 + mi * 16 + gq;
        #pragma unroll
        for (int nj = 0; nj < 4; nj++) {
            const int col = bn + wn * 32 + nj * 8 + tg2;
            const size_t o0 = MODE ? map_tbc(row0, col)     : (size_t)row0 * N + col;
            const size_t o1 = MODE ? map_tbc(row0 + 8, col) : (size_t)(row0 + 8) * N + col;
            *(float2*)(C + o0) = make_float2(acc[mi][nj][0], acc[mi][nj][1]);
            *(float2*)(C + o1) = make_float2(acc[mi][nj][2], acc[mi][nj][3]);
        }
    }
}

// =================================================================================
// xproj via HMMA: x_dbl[8192, 96] = u16 @ WXT16^T (N padded to 128).
// Epilogue: fp32 -> g_xdbl (cols<96); fp16 dt-part -> XDT16 (cols<64).
// Grid: 64 blocks (M/128). CH = 2048/32 = 64.
// =================================================================================
__global__ __launch_bounds__(256)
void xproj_hmma()
{
    constexpr int K  = DINNER;
    constexpr int CH = K / 32;

    __shared__ __align__(16) char smb[2 * STGB];

    const int tid  = threadIdx.x;
    const int lane = tid & 31, wid = tid >> 5;
    const int wm = wid & 1;
    const int wn = wid >> 1;
    const int bm = blockIdx.x * 128;

    const uint16_t* srcA = (const uint16_t*)U16() + (size_t)bm * K;
    const uint16_t* srcB = (const uint16_t*)WXT16();

    const uint32_t sb = smem_u32(smb);
    const int cmat = tid >> 7;
    const int cidx = tid & 127;
    const uint16_t* csrc = cmat ? srcB : srcA;

    float acc[4][4][4];
    #pragma unroll
    for (int mi = 0; mi < 4; mi++)
        #pragma unroll
        for (int nj = 0; nj < 4; nj++)
            #pragma unroll
            for (int e = 0; e < 4; e++) acc[mi][nj][e] = 0.f;

    #define XISSUE(S, CHK) do {                                                  \
        const uint32_t dbase = sb + (uint32_t)(S) * STGB + cmat * MATB;          \
        _Pragma("unroll")                                                        \
        for (int jj = 0; jj < 4; jj++) {                                         \
            const int lin = jj * 128 + cidx;                                     \
            const int r = lin >> 2, cc = lin & 3;                                \
            cp16(dbase + r * GROW + cc * 16,                                     \
                 csrc + (size_t)r * K + (CHK) * 32 + cc * 8);                    \
        }                                                                        \
        CP_COMMIT();                                                             \
    } while (0)

    XISSUE(0, 0);
    XISSUE(1, 1);

    const int lrow = lane & 15;
    const int lsel = (lane >> 4) * 16;

    for (int i = 0; i < CH; i++) {
        const int s = i & 1;
        if (i + 1 < CH) { CP_WAIT1(); } else { CP_WAIT0(); }
        __syncthreads();

        const uint32_t Ab = sb + s * STGB;
        const uint32_t Bb = Ab + MATB;

        #pragma unroll
        for (int ks = 0; ks < 2; ks++) {
            const int kb = ks * 32 + lsel;
            uint32_t ar[4][4], br[4][2];
            #pragma unroll
            for (int mi = 0; mi < 4; mi++) {
                const uint32_t off = (uint32_t)(wm * 64 + mi * 16 + lrow) * GROW + kb;
                ldsm4(ar[mi], Ab + off);
            }
            #pragma unroll
            for (int p = 0; p < 2; p++) {
                const uint32_t off = (uint32_t)(wn * 32 + p * 16 + lrow) * GROW + kb;
                uint32_t r4[4];
                ldsm4(r4, Bb + off);
                br[2 * p][0] = r4[0]; br[2 * p + 1][0] = r4[1];
                br[2 * p][1] = r4[2]; br[2 * p + 1][1] = r4[3];
            }
            #pragma unroll
            for (int mi = 0; mi < 4; mi++)
                #pragma unroll
                for (int nj = 0; nj < 4; nj++)
                    mma_fp16(acc[mi][nj], ar[mi], br[nj]);
        }

        __syncthreads();
        if (i + 2 < CH) XISSUE(s, i + 2);
    }

    const int tg2 = (lane & 3) * 2;
    const int gq  = lane >> 2;
    #pragma unroll
    for (int mi = 0; mi < 4; mi++) {
        const int row0 = bm + wm * 64 + mi * 16 + gq;
        #pragma unroll
        for (int nj = 0; nj < 4; nj++) {
            const int col = wn * 32 + nj * 8 + tg2;
            if (col < NXP) {
                *(float2*)(g_xdbl + (size_t)row0 * NXP + col)
                    = make_float2(acc[mi][nj][0], acc[mi][nj][1]);
                *(float2*)(g_xdbl + (size_t)(row0 + 8) * NXP + col)
                    = make_float2(acc[mi][nj][2], acc[mi][nj][3]);
            }
            if (col < DTRANK) {
                *(__half2*)(XDT16() + (size_t)row0 * DTRANK + col)
                    = __floats2half2_rn(acc[mi][nj][0], acc[mi][nj][1]);
                *(__half2*)(XDT16() + (size_t)(row0 + 8) * DTRANK + col)
                    = __floats2half2_rn(acc[mi][nj][2], acc[mi][nj][3]);
            }
        }
    }
}

// =================================================================================
// dtproj via HMMA + softplus: delta[8192, 2048] = softplus(XDT16 @ WDT16^T + b_dt).
// K=64, CH=2. Grid (16, 64).
// =================================================================================
__global__ __launch_bounds__(256)
void dtproj_hmma(const float* __restrict__ b_dt)
{
    constexpr int K = DTRANK;

    __shared__ __align__(16) char smb[2 * STGB];

    const int tid  = threadIdx.x;
    const int lane = tid & 31, wid = tid >> 5;
    const int wm = wid & 1;
    const int wn = wid >> 1;
    const int bn = blockIdx.x * 128;
    const int bm = blockIdx.y * 128;

    const uint16_t* srcA = (const uint16_t*)XDT16() + (size_t)bm * K;
    const uint16_t* srcB = (const uint16_t*)WDT16() + (size_t)bn * K;

    const uint32_t sb = smem_u32(smb);
    const int cmat = tid >> 7;
    const int cidx = tid & 127;
    const uint16_t* csrc = cmat ? srcB : srcA;

    #define DISSUE(S, CHK) do {                                                  \
        const uint32_t dbase = sb + (uint32_t)(S) * STGB + cmat * MATB;          \
        _Pragma("unroll")                                                        \
        for (int jj = 0; jj < 4; jj++) {                                         \
            const int lin = jj * 128 + cidx;                                     \
            const int r = lin >> 2, cc = lin & 3;                                \
            cp16(dbase + r * GROW + cc * 16,                                     \
                 csrc + (size_t)r * K + (CHK) * 32 + cc * 8);                    \
        }                                                                        \
        CP_COMMIT();                                                             \
    } while (0)

    float acc[4][4][4];
    #pragma unroll
    for (int mi = 0; mi < 4; mi++)
        #pragma unroll
        for (int nj = 0; nj < 4; nj++)
            #pragma unroll
            for (int e = 0; e < 4; e++) acc[mi][nj][e] = 0.f;

    DISSUE(0, 0);
    DISSUE(1, 1);

    const int lrow = lane & 15;
    const int lsel = (lane >> 4) * 16;

    #pragma unroll
    for (int i = 0; i < 2; i++) {
        const int s = i;
        if (i == 0) { CP_WAIT1(); } else { CP_WAIT0(); }
        __syncthreads();

        const uint32_t Ab = sb + s * STGB;
        const uint32_t Bb = Ab + MATB;

        #pragma unroll
        for (int ks = 0; ks < 2; ks++) {
            const int kb = ks * 32 + lsel;
            uint32_t ar[4][4], br[4][2];
            #pragma unroll
            for (int mi = 0; mi < 4; mi++) {
                const uint32_t off = (uint32_t)(wm * 64 + mi * 16 + lrow) * GROW + kb;
                ldsm4(ar[mi], Ab + off);
            }
            #pragma unroll
            for (int p = 0; p < 2; p++) {
                const uint32_t off = (uint32_t)(wn * 32 + p * 16 + lrow) * GROW + kb;
                uint32_t r4[4];
                ldsm4(r4, Bb + off);
                br[2 * p][0] = r4[0]; br[2 * p + 1][0] = r4[1];
                br[2 * p][1] = r4[2]; br[2 * p + 1][1] = r4[3];
            }
            #pragma unroll
            for (int mi = 0; mi < 4; mi++)
                #pragma unroll
                for (int nj = 0; nj < 4; nj++)
                    mma_fp16(acc[mi][nj], ar[mi], br[nj]);
        }
        __syncthreads();
    }

    const int tg2 = (lane & 3) * 2;
    const int gq  = lane >> 2;
    #pragma unroll
    for (int mi = 0; mi < 4; mi++) {
        const int row0 = bm + wm * 64 + mi * 16 + gq;
        #pragma unroll
        for (int nj = 0; nj < 4; nj++) {
            const int col = bn + wn * 32 + nj * 8 + tg2;
            const float b0 = b_dt[col], b1 = b_dt[col + 1];
            #pragma unroll
            for (int e = 0; e < 2; e++) {
                const int row = row0 + e * 8;
                float z0 = acc[mi][nj][e * 2 + 0] + b0;
                float z1 = acc[mi][nj][e * 2 + 1] + b1;
                z0 = (z0 > 15.f) ? z0 : log1pf(__expf(z0));
                z1 = (z1 > 15.f) ? z1 : log1pf(__expf(z1));
                *(float2*)(g_delta + (size_t)row * DINNER + col) = make_float2(z0, z1);
            }
        }
    }
}

// =================================================================================
// Depthwise causal conv (k=4) + bias + silu on u-half (fp32 + fp16 outputs);
// gate = silu(res) in place.
// =================================================================================
__global__ __launch_bounds__(256)
void conv_silu_kernel(const float* __restrict__ cw, const float* __restrict__ cb)
{
    const int q = blockIdx.x * 256 + threadIdx.x;
    const int d  = (q & 511) << 2;
    const int r  = q >> 9;
    const int t0 = (r & 511) << 2;
    const int b  = r >> 9;

    float4 w[4];
    #pragma unroll
    for (int i = 0; i < 4; i++) w[i] = *(const float4*)(cw + (d + i) * 4);
    const float4 cbv = *(const float4*)(cb + d);

    float4 in[7];
    #pragma unroll
    for (int j = 0; j < 7; j++) {
        const int t = t0 + j - 3;
        in[j] = (t >= 0)
            ? *(const float4*)(g_P + (size_t)(b * T_LEN + t) * DPROJ + d)
            : make_float4(0.f, 0.f, 0.f, 0.f);
    }

    #pragma unroll
    for (int j = 0; j < 4; j++) {
        float4 o;
        o.x = cbv.x + w[0].x*in[j].x + w[0].y*in[j+1].x + w[0].z*in[j+2].x + w[0].w*in[j+3].x;
        o.y = cbv.y + w[1].x*in[j].y + w[1].y*in[j+1].y + w[1].z*in[j+2].y + w[1].w*in[j+3].y;
        o.z = cbv.z + w[2].x*in[j].z + w[2].y*in[j+1].z + w[2].z*in[j+2].z + w[2].w*in[j+3].z;
        o.w = cbv.w + w[3].x*in[j].w + w[3].y*in[j+1].w + w[3].z*in[j+2].w + w[3].w*in[j+3].w;
        o.x = o.x * (1.f / (1.f + __expf(-o.x)));
        o.y = o.y * (1.f / (1.f + __expf(-o.y)));
        o.z = o.z * (1.f / (1.f + __expf(-o.z)));
        o.w = o.w * (1.f / (1.f + __expf(-o.w)));
        const size_t mrow = (size_t)(b * T_LEN + t0 + j);
        *(float4*)(g_uc + mrow * DINNER + d) = o;
        // fp16 copy of u for xproj HMMA
        __half2 p0 = __floats2half2_rn(o.x, o.y);
        __half2 p1 = __floats2half2_rn(o.z, o.w);
        *(uint2*)(U16() + mrow * DINNER + d) =
            make_uint2(*(uint32_t*)&p0, *(uint32_t*)&p1);
    }

    // gate = silu(res), in place
    #pragma unroll
    for (int j = 0; j < 4; j++) {
        float* rp = g_P + (size_t)(b * T_LEN + t0 + j) * DPROJ + DINNER + d;
        float4 rv = *(const float4*)rp;
        rv.x = rv.x * (1.f / (1.f + __expf(-rv.x)));
        rv.y = rv.y * (1.f / (1.f + __expf(-rv.y)));
        rv.z = rv.z * (1.f / (1.f + __expf(-rv.z)));
        rv.w = rv.w * (1.f / (1.f + __expf(-rv.w)));
        *(float4*)rp = rv;
    }
}

// =================================================================================
// Selective scan (proven R14): 6-stage cp.async pipeline; gate preloaded;
// epilogue writes fp16 y into g_P u-half.
// =================================================================================
#define TB   16
#define NSTG 6

__global__ __launch_bounds__(128)
void scan_kernel(const float* __restrict__ A_log, const float* __restrict__ Dv)
{
    __shared__ __align__(16) float sdl[NSTG][TB][32];
    __shared__ __align__(16) float suu[NSTG][TB][32];
    __shared__ __align__(16) float srs[NSTG][TB][32];
    __shared__ __align__(16) float sbc[NSTG][TB][32];

    const int b = blockIdx.y;
    const int d0 = blockIdx.x * 32;
    const int tid = threadIdx.x;
    const int w = tid >> 5, lane = tid & 31;
    const int g = lane >> 2, q = lane & 3;
    const int dloc = w * 8 + g;
    const int d = d0 + dloc;
    const int nb = q * 4;

    const float A0 = -__expf(A_log[d * DSTATE + nb + 0]);
    const float A1 = -__expf(A_log[d * DSTATE + nb + 1]);
    const float A2 = -__expf(A_log[d * DSTATE + nb + 2]);
    const float A3 = -__expf(A_log[d * DSTATE + nb + 3]);
    const float Dd = Dv[d];

    const int t_ld = tid >> 3;
    const int seg  = (tid & 7) * 4;

    const size_t mb = (size_t)b * T_LEN;

    const uint32_t a_dl = smem_u32(&sdl[0][t_ld][seg]);
    const uint32_t a_uu = smem_u32(&suu[0][t_ld][seg]);
    const uint32_t a_rs = smem_u32(&srs[0][t_ld][seg]);
    const uint32_t a_bc = smem_u32(&sbc[0][t_ld][seg]);
    const uint32_t stg_bytes = TB * 32 * 4;

    #define SCAN_ISSUE(S, Cc) do {                                                     \
        const size_t _m = mb + (size_t)(Cc) * TB + t_ld;                               \
        cp16(a_dl + (S) * stg_bytes, g_delta + _m * DINNER + d0 + seg);                \
        cp16(a_uu + (S) * stg_bytes, g_uc    + _m * DINNER + d0 + seg);                \
        cp16(a_rs + (S) * stg_bytes, g_P     + _m * DPROJ + DINNER + d0 + seg);        \
        cp16(a_bc + (S) * stg_bytes, g_xdbl  + _m * NXP + DTRANK + seg);               \
        CP_COMMIT();                                                                   \
    } while (0)

    #pragma unroll
    for (int p = 0; p < NSTG; p++) SCAN_ISSUE(p, p);

    float h0 = 0.f, h1 = 0.f, h2 = 0.f, h3 = 0.f;
    constexpr int NCH = T_LEN / TB;

    for (int c = 0; c < NCH; c++) {
        const int S = c % NSTG;
        CP_WAIT5();
        __syncthreads();

        #pragma unroll
        for (int tt = 0; tt < TB; tt++) {
            const float dl = sdl[S][tt][dloc];
            const float uu = suu[S][tt][dloc];
            const float4 Bv = *(const float4*)&sbc[S][tt][nb];
            const float4 Cv = *(const float4*)&sbc[S][tt][16 + nb];

            const float du = dl * uu;
            h0 = fmaf(__expf(dl * A0), h0, du * Bv.x);
            h1 = fmaf(__expf(dl * A1), h1, du * Bv.y);
            h2 = fmaf(__expf(dl * A2), h2, du * Bv.z);
            h3 = fmaf(__expf(dl * A3), h3, du * Bv.w);

            float p = fmaf(h0, Cv.x, fmaf(h1, Cv.y, fmaf(h2, Cv.z, h3 * Cv.w)));
            p += __shfl_xor_sync(0xffffffffu, p, 1);
            p += __shfl_xor_sync(0xffffffffu, p, 2);

            if (q == 0) {
                const float gate = srs[S][tt][dloc];
                const float yv = fmaf(uu, Dd, p) * gate;
                __half* rowp = (__half*)g_P + (mb + (size_t)(c * TB + tt)) * (2 * DPROJ);
                rowp[d] = __float2half_rn(yv);
            }
        }
        __syncthreads();
        if (c + NSTG < NCH) { SCAN_ISSUE(S, c + NSTG); }
        else                { CP_COMMIT(); }
    }
}

// =================================================================================
// launch
// =================================================================================
extern "C" void kernel_launch(void* const* d_in, const int* in_sizes, int n_in,
                              void* d_out, int out_size)
{
    const float* x      = (const float*)d_in[0];
    const float* W_in   = (const float*)d_in[1];
    const float* conv_w = (const float*)d_in[2];
    const float* conv_b = (const float*)d_in[3];
    const float* W_x    = (const float*)d_in[4];
    const float* W_dt   = (const float*)d_in[5];
    const float* b_dt   = (const float*)d_in[6];
    const float* A_log  = (const float*)d_in[7];
    const float* Dv     = (const float*)d_in[8];
    const float* W_out  = (const float*)d_in[9];
    float* out = (float*)d_out;

    // --- in_proj (fp16 1-term) ---
    split_x_kernel<<<(M_ROWS * DMODEL / 4) / 256, 256>>>(x);
    splitT_kernel<0><<<dim3(DPROJ / 32, DMODEL / 32), 256>>>(W_in);
    splitT_kernel<1><<<dim3(DMODEL / 32, DINNER / 32), 256>>>(W_out);
    prep_wx_kernel<<<(128 * 2048) / 256, 256>>>(W_x);
    prep_wdt_kernel<<<(2048 * 64) / 256, 256>>>(W_dt);
    gemm_hmma<0><<<dim3(DPROJ / 128, M_ROWS / 128), 256>>>(nullptr);

    // --- mid pipeline ---
    conv_silu_kernel<<<(B_SZ * (T_LEN / 4) * (DINNER / 4)) / 256, 256>>>(conv_w, conv_b);
    xproj_hmma<<<M_ROWS / 128, 256>>>();
    dtproj_hmma<<<dim3(DINNER / 128, M_ROWS / 128), 256>>>(b_dt);
    scan_kernel<<<dim3(DINNER / 32, B_SZ), 128>>>(A_log, Dv);

    // --- out_proj (fp16 1-term) ---
    gemm_hmma<1><<<dim3(DMODEL / 128, M_ROWS / 128), 256>>>(out);
}

// round 16
// speedup vs baseline: 9.1222x; 1.0045x over previous
#include <cuda_runtime.h>
#include <cuda_bf16.h>
#include <cuda_fp16.h>
#include <math.h>
#include <stdint.h>

#define T_LEN   2048
#define B_SZ    4
#define DMODEL  1024
#define DINNER  2048
#define DSTATE  16
#define DTRANK  64
#define NXP     96
#define M_ROWS  (B_SZ*T_LEN)   // 8192
#define DPROJ   (2*DINNER)     // 4096

// ---------------- scratch (device globals; proven 323MB set) ----------
__device__ __align__(16) float g_P[(size_t)M_ROWS * DPROJ];     // in_proj out; u-half later A2 fp16
__device__ __align__(16) float g_uc[(size_t)M_ROWS * DINNER];   // W1H, then u fp16
__device__ __align__(16) float g_xdbl[(size_t)M_ROWS * NXP];
__device__ __align__(16) float g_delta[(size_t)M_ROWS * DINNER];
__device__ __align__(16) float g_y[(size_t)M_ROWS * DINNER];

// ---- fp16 operands ALIASED into scratch (lifetimes verified disjoint) ----
// A1 (x fp16):  g_delta until dtproj writes delta fp32
// W1 fp16:      g_uc until conv overwrites with u fp16 (gemm0 done by then)
// U16 (u fp16): g_uc, written by conv, read by xproj + scan
// A2 (y fp16):  g_P u-halves, written by scan
// g_y halves:   [0) W2H | [4.19M) WXT16 | [8.39M) WDT16 | [12.58M) XDT16 | [16.78M) GATE16
__device__ __forceinline__ __half* A1H()    { return (__half*)g_delta; }
__device__ __forceinline__ __half* W1H()    { return (__half*)g_uc; }
__device__ __forceinline__ __half* U16()    { return (__half*)g_uc; }
__device__ __forceinline__ __half* W2H()    { return (__half*)g_y; }
__device__ __forceinline__ __half* WXT16()  { return (__half*)g_y + 4194304; }   // [128][2048]
__device__ __forceinline__ __half* WDT16()  { return (__half*)g_y + 8388608; }   // [2048][64]
__device__ __forceinline__ __half* XDT16()  { return (__half*)g_y + 12582912; }  // [8192][64]
__device__ __forceinline__ __half* GATE16() { return (__half*)g_y + 16777216; }  // [8192][2048]

// ---------------- helpers ----------------
__device__ __forceinline__ uint32_t smem_u32(const void* p) {
    uint32_t a;
    asm("{ .reg .u64 t; cvta.to.shared.u64 t, %1; cvt.u32.u64 %0, t; }" : "=r"(a) : "l"(p));
    return a;
}
__device__ __forceinline__ void cp16(uint32_t d, const void* s) {
    asm volatile("cp.async.cg.shared.global [%0], [%1], 16;" :: "r"(d), "l"(s));
}
#define CP_COMMIT() asm volatile("cp.async.commit_group;" ::: "memory")
#define CP_WAIT0()  asm volatile("cp.async.wait_group 0;"  ::: "memory")
#define CP_WAIT1()  asm volatile("cp.async.wait_group 1;"  ::: "memory")
#define CP_WAIT5()  asm volatile("cp.async.wait_group 5;"  ::: "memory")

__device__ __forceinline__ void ldsm4(uint32_t* r, uint32_t a) {
    asm volatile("ldmatrix.sync.aligned.m8n8.x4.shared.b16 {%0,%1,%2,%3}, [%4];"
        : "=r"(r[0]), "=r"(r[1]), "=r"(r[2]), "=r"(r[3]) : "r"(a));
}
__device__ __forceinline__ void mma_fp16(float* c, const uint32_t* a, const uint32_t* b) {
    asm volatile("mma.sync.aligned.m16n8k16.row.col.f32.f16.f16.f32 "
        "{%0,%1,%2,%3}, {%4,%5,%6,%7}, {%8,%9}, {%0,%1,%2,%3};"
        : "+f"(c[0]), "+f"(c[1]), "+f"(c[2]), "+f"(c[3])
        : "r"(a[0]), "r"(a[1]), "r"(a[2]), "r"(a[3]), "r"(b[0]), "r"(b[1]));
}

__device__ __forceinline__ size_t map_tbc(int m, int col) {
    return (size_t)(m & (T_LEN - 1)) * (B_SZ * DMODEL) + (size_t)(m >> 11) * DMODEL + col;
}

// =================================================================================
// Conversion / prep kernels
// =================================================================================
__device__ __forceinline__ void cvt_store4h(float4 v, __half* hp) {
    __half h0 = __float2half_rn(v.x), h1 = __float2half_rn(v.y);
    __half h2 = __float2half_rn(v.z), h3 = __float2half_rn(v.w);
    *(ushort4*)hp = make_ushort4(__half_as_ushort(h0), __half_as_ushort(h1),
                                 __half_as_ushort(h2), __half_as_ushort(h3));
}

__global__ __launch_bounds__(256)
void split_x_kernel(const float* __restrict__ x)
{
    const int q = blockIdx.x * 256 + threadIdx.x;
    const int c = (q & 255) * 4;
    const int m = q >> 8;
    const int t = m & (T_LEN - 1), b = m >> 11;
    float4 v = *(const float4*)(x + (size_t)t * (B_SZ * DMODEL) + b * DMODEL + c);
    cvt_store4h(v, A1H() + (size_t)m * DMODEL + c);
}

template<int WHICH>
__global__ __launch_bounds__(256)
void splitT_kernel(const float* __restrict__ W)
{
    constexpr int K = WHICH ? DINNER : DMODEL;
    constexpr int N = WHICH ? DMODEL : DPROJ;
    __shared__ float tile[32][33];
    const int n0 = blockIdx.x * 32, k0 = blockIdx.y * 32;
    const int tid = threadIdx.x;
    #pragma unroll
    for (int p = 0; p < 4; p++) {
        const int idx = tid + p * 256;
        const int kr = idx >> 5, nc = idx & 31;
        tile[kr][nc] = W[(size_t)(k0 + kr) * N + n0 + nc];
    }
    __syncthreads();
    const int nr = tid >> 3;
    const int kq = (tid & 7) * 4;
    float4 v = make_float4(tile[kq + 0][nr], tile[kq + 1][nr], tile[kq + 2][nr], tile[kq + 3][nr]);
    __half* Th = WHICH ? W2H() : W1H();
    cvt_store4h(v, Th + (size_t)(n0 + nr) * K + (k0 + kq));
}

// merged: W_x [2048][96] -> WXT16 [128][2048]; W_dt [64][2048] -> WDT16 [2048][64]
__global__ __launch_bounds__(256)
void prep_w_kernel(const float* __restrict__ W_x, const float* __restrict__ W_dt)
{
    const int idx = blockIdx.x * 256 + threadIdx.x;   // 262144 + 131072 = 393216
    if (idx < 262144) {
        const int n = idx >> 11, k = idx & 2047;
        const float v = (n < NXP) ? W_x[(size_t)k * NXP + n] : 0.f;
        WXT16()[idx] = __float2half_rn(v);
    } else {
        const int j = idx - 262144;
        const int n = j >> 6, k = j & 63;
        WDT16()[j] = __float2half_rn(W_dt[(size_t)k * DINNER + n]);
    }
}

// =================================================================================
// fp16 1-term GEMM (proven R14/15). K-chunk 32, GROW=80, 2 mats, 2 stages.
// =================================================================================
#define GROW 80
#define MATB (128 * GROW)
#define STGB (2 * MATB)

template<int MODE>
__global__ __launch_bounds__(256)
void gemm_hmma(float* __restrict__ Cparam)
{
    constexpr int N  = MODE ? DMODEL : DPROJ;
    constexpr int K  = MODE ? DINNER : DMODEL;
    constexpr int CH = K / 32;

    __shared__ __align__(16) char smb[2 * STGB];

    const int tid  = threadIdx.x;
    const int lane = tid & 31, wid = tid >> 5;
    const int wm = wid & 1;
    const int wn = wid >> 1;
    const int bm = blockIdx.y * 128;
    const int bn = blockIdx.x * 128;

    const uint16_t* srcA;
    size_t strA;
    if (MODE == 0) {
        srcA = (const uint16_t*)A1H() + (size_t)bm * K;
        strA = K;
    } else {
        srcA = (const uint16_t*)g_P + (size_t)bm * (2 * DPROJ);
        strA = 2 * DPROJ;
    }
    const uint16_t* srcB = (const uint16_t*)(MODE ? W2H() : W1H()) + (size_t)bn * K;

    float* C = MODE ? Cparam : g_P;
    const uint32_t sb = smem_u32(smb);

    const int cmat = tid >> 7;
    const int cidx = tid & 127;
    const uint16_t* csrc = cmat ? srcB : srcA;
    const size_t cstr = cmat ? (size_t)K : strA;

    #define ISSUE(S, CHK) do {                                                   \
        const uint32_t dbase = sb + (uint32_t)(S) * STGB + cmat * MATB;          \
        _Pragma("unroll")                                                        \
        for (int jj = 0; jj < 4; jj++) {                                         \
            const int lin = jj * 128 + cidx;                                     \
            const int r = lin >> 2, cc = lin & 3;                                \
            cp16(dbase + r * GROW + cc * 16,                                     \
                 csrc + (size_t)r * cstr + (CHK) * 32 + cc * 8);                 \
        }                                                                        \
        CP_COMMIT();                                                             \
    } while (0)

    float acc[4][4][4];
    #pragma unroll
    for (int mi = 0; mi < 4; mi++)
        #pragma unroll
        for (int nj = 0; nj < 4; nj++)
            #pragma unroll
            for (int e = 0; e < 4; e++) acc[mi][nj][e] = 0.f;

    ISSUE(0, 0);
    if (CH > 1) ISSUE(1, 1);

    const int lrow = lane & 15;
    const int lsel = (lane >> 4) * 16;

    for (int i = 0; i < CH; i++) {
        const int s = i & 1;
        if (i + 1 < CH) { CP_WAIT1(); } else { CP_WAIT0(); }
        __syncthreads();

        const uint32_t Ab = sb + s * STGB;
        const uint32_t Bb = Ab + MATB;

        #pragma unroll
        for (int ks = 0; ks < 2; ks++) {
            const int kb = ks * 32 + lsel;
            uint32_t ar[4][4], br[4][2];
            #pragma unroll
            for (int mi = 0; mi < 4; mi++) {
                const uint32_t off = (uint32_t)(wm * 64 + mi * 16 + lrow) * GROW + kb;
                ldsm4(ar[mi], Ab + off);
            }
            #pragma unroll
            for (int p = 0; p < 2; p++) {
                const uint32_t off = (uint32_t)(wn * 32 + p * 16 + lrow) * GROW + kb;
                uint32_t r4[4];
                ldsm4(r4, Bb + off);
                br[2 * p][0] = r4[0]; br[2 * p + 1][0] = r4[1];
                br[2 * p][1] = r4[2]; br[2 * p + 1][1] = r4[3];
            }
            #pragma unroll
            for (int mi = 0; mi < 4; mi++)
                #pragma unroll
                for (int nj = 0; nj < 4; nj++)
                    mma_fp16(acc[mi][nj], ar[mi], br[nj]);
        }

        __syncthreads();
        if (i + 2 < CH) ISSUE(s, i + 2);
    }

    const int tg2 = (lane & 3) * 2;
    const int gq  = lane >> 2;
    #pragma unroll
    for (int mi = 0; mi < 4; mi++) {
        const int row0 = bm + wm * 64 + mi * 16 + gq;
        #pragma unroll
        for (int nj = 0; nj < 4; nj++) {
            const int col = bn + wn * 32 + nj * 8 + tg2;
            const size_t o0 = MODE ? map_tbc(row0, col)     : (size_t)row0 * N + col;
            const size_t o1 = MODE ? map_tbc(row0 + 8, col) : (size_t)(row0 + 8) * N + col;
            *(float2*)(C + o0) = make_float2(acc[mi][nj][0], acc[mi][nj][1]);
            *(float2*)(C + o1) = make_float2(acc[mi][nj][2], acc[mi][nj][3]);
        }
    }
}

// =================================================================================
// xproj via HMMA (proven R15): x_dbl = u16 @ WXT16^T, epilogue fp32 + fp16 dt copy.
// =================================================================================
__global__ __launch_bounds__(256)
void xproj_hmma()
{
    constexpr int K  = DINNER;
    constexpr int CH = K / 32;

    __shared__ __align__(16) char smb[2 * STGB];

    const int tid  = threadIdx.x;
    const int lane = tid & 31, wid = tid >> 5;
    const int wm = wid & 1;
    const int wn = wid >> 1;
    const int bm = blockIdx.x * 128;

    const uint16_t* srcA = (const uint16_t*)U16() + (size_t)bm * K;
    const uint16_t* srcB = (const uint16_t*)WXT16();

    const uint32_t sb = smem_u32(smb);
    const int cmat = tid >> 7;
    const int cidx = tid & 127;
    const uint16_t* csrc = cmat ? srcB : srcA;

    float acc[4][4][4];
    #pragma unroll
    for (int mi = 0; mi < 4; mi++)
        #pragma unroll
        for (int nj = 0; nj < 4; nj++)
            #pragma unroll
            for (int e = 0; e < 4; e++) acc[mi][nj][e] = 0.f;

    #define XISSUE(S, CHK) do {                                                  \
        const uint32_t dbase = sb + (uint32_t)(S) * STGB + cmat * MATB;          \
        _Pragma("unroll")                                                        \
        for (int jj = 0; jj < 4; jj++) {                                         \
            const int lin = jj * 128 + cidx;                                     \
            const int r = lin >> 2, cc = lin & 3;                                \
            cp16(dbase + r * GROW + cc * 16,                                     \
                 csrc + (size_t)r * K + (CHK) * 32 + cc * 8);                    \
        }                                                                        \
        CP_COMMIT();                                                             \
    } while (0)

    XISSUE(0, 0);
    XISSUE(1, 1);

    const int lrow = lane & 15;
    const int lsel = (lane >> 4) * 16;

    for (int i = 0; i < CH; i++) {
        const int s = i & 1;
        if (i + 1 < CH) { CP_WAIT1(); } else { CP_WAIT0(); }
        __syncthreads();

        const uint32_t Ab = sb + s * STGB;
        const uint32_t Bb = Ab + MATB;

        #pragma unroll
        for (int ks = 0; ks < 2; ks++) {
            const int kb = ks * 32 + lsel;
            uint32_t ar[4][4], br[4][2];
            #pragma unroll
            for (int mi = 0; mi < 4; mi++) {
                const uint32_t off = (uint32_t)(wm * 64 + mi * 16 + lrow) * GROW + kb;
                ldsm4(ar[mi], Ab + off);
            }
            #pragma unroll
            for (int p = 0; p < 2; p++) {
                const uint32_t off = (uint32_t)(wn * 32 + p * 16 + lrow) * GROW + kb;
                uint32_t r4[4];
                ldsm4(r4, Bb + off);
                br[2 * p][0] = r4[0]; br[2 * p + 1][0] = r4[1];
                br[2 * p][1] = r4[2]; br[2 * p + 1][1] = r4[3];
            }
            #pragma unroll
            for (int mi = 0; mi < 4; mi++)
                #pragma unroll
                for (int nj = 0; nj < 4; nj++)
                    mma_fp16(acc[mi][nj], ar[mi], br[nj]);
        }

        __syncthreads();
        if (i + 2 < CH) XISSUE(s, i + 2);
    }

    const int tg2 = (lane & 3) * 2;
    const int gq  = lane >> 2;
    #pragma unroll
    for (int mi = 0; mi < 4; mi++) {
        const int row0 = bm + wm * 64 + mi * 16 + gq;
        #pragma unroll
        for (int nj = 0; nj < 4; nj++) {
            const int col = wn * 32 + nj * 8 + tg2;
            if (col < NXP) {
                *(float2*)(g_xdbl + (size_t)row0 * NXP + col)
                    = make_float2(acc[mi][nj][0], acc[mi][nj][1]);
                *(float2*)(g_xdbl + (size_t)(row0 + 8) * NXP + col)
                    = make_float2(acc[mi][nj][2], acc[mi][nj][3]);
            }
            if (col < DTRANK) {
                *(__half2*)(XDT16() + (size_t)row0 * DTRANK + col)
                    = __floats2half2_rn(acc[mi][nj][0], acc[mi][nj][1]);
                *(__half2*)(XDT16() + (size_t)(row0 + 8) * DTRANK + col)
                    = __floats2half2_rn(acc[mi][nj][2], acc[mi][nj][3]);
            }
        }
    }
}

// =================================================================================
// dtproj via HMMA + softplus (proven R15).
// =================================================================================
__global__ __launch_bounds__(256)
void dtproj_hmma(const float* __restrict__ b_dt)
{
    constexpr int K = DTRANK;

    __shared__ __align__(16) char smb[2 * STGB];

    const int tid  = threadIdx.x;
    const int lane = tid & 31, wid = tid >> 5;
    const int wm = wid & 1;
    const int wn = wid >> 1;
    const int bn = blockIdx.x * 128;
    const int bm = blockIdx.y * 128;

    const uint16_t* srcA = (const uint16_t*)XDT16() + (size_t)bm * K;
    const uint16_t* srcB = (const uint16_t*)WDT16() + (size_t)bn * K;

    const uint32_t sb = smem_u32(smb);
    const int cmat = tid >> 7;
    const int cidx = tid & 127;
    const uint16_t* csrc = cmat ? srcB : srcA;

    #define DISSUE(S, CHK) do {                                                  \
        const uint32_t dbase = sb + (uint32_t)(S) * STGB + cmat * MATB;          \
        _Pragma("unroll")                                                        \
        for (int jj = 0; jj < 4; jj++) {                                         \
            const int lin = jj * 128 + cidx;                                     \
            const int r = lin >> 2, cc = lin & 3;                                \
            cp16(dbase + r * GROW + cc * 16,                                     \
                 csrc + (size_t)r * K + (CHK) * 32 + cc * 8);                    \
        }                                                                        \
        CP_COMMIT();                                                             \
    } while (0)

    float acc[4][4][4];
    #pragma unroll
    for (int mi = 0; mi < 4; mi++)
        #pragma unroll
        for (int nj = 0; nj < 4; nj++)
            #pragma unroll
            for (int e = 0; e < 4; e++) acc[mi][nj][e] = 0.f;

    DISSUE(0, 0);
    DISSUE(1, 1);

    const int lrow = lane & 15;
    const int lsel = (lane >> 4) * 16;

    #pragma unroll
    for (int i = 0; i < 2; i++) {
        const int s = i;
        if (i == 0) { CP_WAIT1(); } else { CP_WAIT0(); }
        __syncthreads();

        const uint32_t Ab = sb + s * STGB;
        const uint32_t Bb = Ab + MATB;

        #pragma unroll
        for (int ks = 0; ks < 2; ks++) {
            const int kb = ks * 32 + lsel;
            uint32_t ar[4][4], br[4][2];
            #pragma unroll
            for (int mi = 0; mi < 4; mi++) {
                const uint32_t off = (uint32_t)(wm * 64 + mi * 16 + lrow) * GROW + kb;
                ldsm4(ar[mi], Ab + off);
            }
            #pragma unroll
            for (int p = 0; p < 2; p++) {
                const uint32_t off = (uint32_t)(wn * 32 + p * 16 + lrow) * GROW + kb;
                uint32_t r4[4];
                ldsm4(r4, Bb + off);
                br[2 * p][0] = r4[0]; br[2 * p + 1][0] = r4[1];
                br[2 * p][1] = r4[2]; br[2 * p + 1][1] = r4[3];
            }
            #pragma unroll
            for (int mi = 0; mi < 4; mi++)
                #pragma unroll
                for (int nj = 0; nj < 4; nj++)
                    mma_fp16(acc[mi][nj], ar[mi], br[nj]);
        }
        __syncthreads();
    }

    const int tg2 = (lane & 3) * 2;
    const int gq  = lane >> 2;
    #pragma unroll
    for (int mi = 0; mi < 4; mi++) {
        const int row0 = bm + wm * 64 + mi * 16 + gq;
        #pragma unroll
        for (int nj = 0; nj < 4; nj++) {
            const int col = bn + wn * 32 + nj * 8 + tg2;
            const float b0 = b_dt[col], b1 = b_dt[col + 1];
            #pragma unroll
            for (int e = 0; e < 2; e++) {
                const int row = row0 + e * 8;
                float z0 = acc[mi][nj][e * 2 + 0] + b0;
                float z1 = acc[mi][nj][e * 2 + 1] + b1;
                z0 = (z0 > 15.f) ? z0 : log1pf(__expf(z0));
                z1 = (z1 > 15.f) ? z1 : log1pf(__expf(z1));
                *(float2*)(g_delta + (size_t)row * DINNER + col) = make_float2(z0, z1);
            }
        }
    }
}

// =================================================================================
// Depthwise causal conv (k=4) + bias + silu -> u fp16 only; gate = silu(res) fp16.
// =================================================================================
__global__ __launch_bounds__(256)
void conv_silu_kernel(const float* __restrict__ cw, const float* __restrict__ cb)
{
    const int q = blockIdx.x * 256 + threadIdx.x;
    const int d  = (q & 511) << 2;
    const int r  = q >> 9;
    const int t0 = (r & 511) << 2;
    const int b  = r >> 9;

    float4 w[4];
    #pragma unroll
    for (int i = 0; i < 4; i++) w[i] = *(const float4*)(cw + (d + i) * 4);
    const float4 cbv = *(const float4*)(cb + d);

    float4 in[7];
    #pragma unroll
    for (int j = 0; j < 7; j++) {
        const int t = t0 + j - 3;
        in[j] = (t >= 0)
            ? *(const float4*)(g_P + (size_t)(b * T_LEN + t) * DPROJ + d)
            : make_float4(0.f, 0.f, 0.f, 0.f);
    }

    #pragma unroll
    for (int j = 0; j < 4; j++) {
        float4 o;
        o.x = cbv.x + w[0].x*in[j].x + w[0].y*in[j+1].x + w[0].z*in[j+2].x + w[0].w*in[j+3].x;
        o.y = cbv.y + w[1].x*in[j].y + w[1].y*in[j+1].y + w[1].z*in[j+2].y + w[1].w*in[j+3].y;
        o.z = cbv.z + w[2].x*in[j].z + w[2].y*in[j+1].z + w[2].z*in[j+2].z + w[2].w*in[j+3].z;
        o.w = cbv.w + w[3].x*in[j].w + w[3].y*in[j+1].w + w[3].z*in[j+2].w + w[3].w*in[j+3].w;
        o.x = o.x * (1.f / (1.f + __expf(-o.x)));
        o.y = o.y * (1.f / (1.f + __expf(-o.y)));
        o.z = o.z * (1.f / (1.f + __expf(-o.z)));
        o.w = o.w * (1.f / (1.f + __expf(-o.w)));
        const size_t mrow = (size_t)(b * T_LEN + t0 + j);
        __half2 p0 = __floats2half2_rn(o.x, o.y);
        __half2 p1 = __floats2half2_rn(o.z, o.w);
        *(uint2*)(U16() + mrow * DINNER + d) = make_uint2(*(uint32_t*)&p0, *(uint32_t*)&p1);
    }

    // gate = silu(res) -> fp16 (separate region, no RMW on g_P)
    #pragma unroll
    for (int j = 0; j < 4; j++) {
        const size_t mrow = (size_t)(b * T_LEN + t0 + j);
        float4 rv = *(const float4*)(g_P + mrow * DPROJ + DINNER + d);
        rv.x = rv.x * (1.f / (1.f + __expf(-rv.x)));
        rv.y = rv.y * (1.f / (1.f + __expf(-rv.y)));
        rv.z = rv.z * (1.f / (1.f + __expf(-rv.z)));
        rv.w = rv.w * (1.f / (1.f + __expf(-rv.w)));
        __half2 p0 = __floats2half2_rn(rv.x, rv.y);
        __half2 p1 = __floats2half2_rn(rv.z, rv.w);
        *(uint2*)(GATE16() + mrow * DINNER + d) = make_uint2(*(uint32_t*)&p0, *(uint32_t*)&p1);
    }
}

// =================================================================================
// Selective scan: 6-stage cp.async; delta/BC fp32, u+gate fp16; fp16 y out.
// smem 36KB.
// =================================================================================
#define TB   16
#define NSTG 6

__global__ __launch_bounds__(128)
void scan_kernel(const float* __restrict__ A_log, const float* __restrict__ Dv)
{
    __shared__ __align__(16) float  sdl[NSTG][TB][32];
    __shared__ __align__(16) float  sbc[NSTG][TB][32];
    __shared__ __align__(16) __half sug[NSTG][TB][64];   // [0..31]=u, [32..63]=gate

    const int b = blockIdx.y;
    const int d0 = blockIdx.x * 32;
    const int tid = threadIdx.x;
    const int w = tid >> 5, lane = tid & 31;
    const int g = lane >> 2, q = lane & 3;
    const int dloc = w * 8 + g;
    const int d = d0 + dloc;
    const int nb = q * 4;

    const float A0 = -__expf(A_log[d * DSTATE + nb + 0]);
    const float A1 = -__expf(A_log[d * DSTATE + nb + 1]);
    const float A2 = -__expf(A_log[d * DSTATE + nb + 2]);
    const float A3 = -__expf(A_log[d * DSTATE + nb + 3]);
    const float Dd = Dv[d];

    const int t_ld = tid >> 3;        // 0..15
    const int seg  = tid & 7;         // 0..7

    const size_t mb = (size_t)b * T_LEN;

    const uint32_t a_dl = smem_u32(&sdl[0][t_ld][seg * 4]);
    const uint32_t a_bc = smem_u32(&sbc[0][t_ld][seg * 4]);
    const uint32_t a_ug = smem_u32(&sug[0][t_ld][seg * 8]);
    const uint32_t st_f  = TB * 32 * 4;   // fp32 stage stride
    const uint32_t st_h  = TB * 64 * 2;   // half stage stride

    // u/gate source for this thread's 16B slot
    const __half* ugsrc = (seg < 4) ? U16() : GATE16();
    const int ugoff = (seg & 3) * 8;

    #define SCAN_ISSUE(S, Cc) do {                                                     \
        const size_t _m = mb + (size_t)(Cc) * TB + t_ld;                               \
        cp16(a_dl + (S) * st_f, g_delta + _m * DINNER + d0 + seg * 4);                 \
        cp16(a_bc + (S) * st_f, g_xdbl  + _m * NXP + DTRANK + seg * 4);                \
        cp16(a_ug + (S) * st_h, ugsrc + _m * DINNER + d0 + ugoff);                     \
        CP_COMMIT();                                                                   \
    } while (0)

    #pragma unroll
    for (int p = 0; p < NSTG; p++) SCAN_ISSUE(p, p);

    float h0 = 0.f, h1 = 0.f, h2 = 0.f, h3 = 0.f;
    constexpr int NCH = T_LEN / TB;

    for (int c = 0; c < NCH; c++) {
        const int S = c % NSTG;
        CP_WAIT5();
        __syncthreads();

        #pragma unroll
        for (int tt = 0; tt < TB; tt++) {
            const float dl = sdl[S][tt][dloc];
            const float uu = __half2float(sug[S][tt][dloc]);
            const float4 Bv = *(const float4*)&sbc[S][tt][nb];
            const float4 Cv = *(const float4*)&sbc[S][tt][16 + nb];

            const float du = dl * uu;
            h0 = fmaf(__expf(dl * A0), h0, du * Bv.x);
            h1 = fmaf(__expf(dl * A1), h1, du * Bv.y);
            h2 = fmaf(__expf(dl * A2), h2, du * Bv.z);
            h3 = fmaf(__expf(dl * A3), h3, du * Bv.w);

            float p = fmaf(h0, Cv.x, fmaf(h1, Cv.y, fmaf(h2, Cv.z, h3 * Cv.w)));
            p += __shfl_xor_sync(0xffffffffu, p, 1);
            p += __shfl_xor_sync(0xffffffffu, p, 2);

            if (q == 0) {
                const float gate = __half2float(sug[S][tt][32 + dloc]);
                const float yv = fmaf(uu, Dd, p) * gate;
                __half* rowp = (__half*)g_P + (mb + (size_t)(c * TB + tt)) * (2 * DPROJ);
                rowp[d] = __float2half_rn(yv);
            }
        }
        __syncthreads();
        if (c + NSTG < NCH) { SCAN_ISSUE(S, c + NSTG); }
        else                { CP_COMMIT(); }
    }
}

// =================================================================================
// launch
// =================================================================================
extern "C" void kernel_launch(void* const* d_in, const int* in_sizes, int n_in,
                              void* d_out, int out_size)
{
    const float* x      = (const float*)d_in[0];
    const float* W_in   = (const float*)d_in[1];
    const float* conv_w = (const float*)d_in[2];
    const float* conv_b = (const float*)d_in[3];
    const float* W_x    = (const float*)d_in[4];
    const float* W_dt   = (const float*)d_in[5];
    const float* b_dt   = (const float*)d_in[6];
    const float* A_log  = (const float*)d_in[7];
    const float* Dv     = (const float*)d_in[8];
    const float* W_out  = (const float*)d_in[9];
    float* out = (float*)d_out;

    // --- preps + in_proj ---
    split_x_kernel<<<(M_ROWS * DMODEL / 4) / 256, 256>>>(x);
    splitT_kernel<0><<<dim3(DPROJ / 32, DMODEL / 32), 256>>>(W_in);
    splitT_kernel<1><<<dim3(DMODEL / 32, DINNER / 32), 256>>>(W_out);
    prep_w_kernel<<<(262144 + 131072) / 256, 256>>>(W_x, W_dt);
    gemm_hmma<0><<<dim3(DPROJ / 128, M_ROWS / 128), 256>>>(nullptr);

    // --- mid pipeline ---
    conv_silu_kernel<<<(B_SZ * (T_LEN / 4) * (DINNER / 4)) / 256, 256>>>(conv_w, conv_b);
    xproj_hmma<<<M_ROWS / 128, 256>>>();
    dtproj_hmma<<<dim3(DINNER / 128, M_ROWS / 128), 256>>>(b_dt);
    scan_kernel<<<dim3(DINNER / 32, B_SZ), 128>>>(A_log, Dv);

    // --- out_proj ---
    gemm_hmma<1><<<dim3(DMODEL / 128, M_ROWS / 128), 256>>>(out);
}